// round 1
// baseline (speedup 1.0000x reference)
#include <cuda_runtime.h>
#include <math.h>
#include <stdint.h>

// Problem-size caps (from reference): N=50000, DIM=256, VAL_DIM=300, ATT=1001,
// N_VAL=100000, E_ATTR=200000, E_EDGE unique <= 2*400000+50000=850000, N_SEED=10000.
#define DIM 256
#define NMAX 50000
#define EMAX 860000
#define NVALMAX 100000
#define NATTMAX 1001

// ---------------- scratch (static device globals; no allocation) ----------------
__device__ float g_valW[NVALMAX * DIM];       // val_feats @ W_enc[256:556]
__device__ float g_attW[NATTMAX * DIM];       // att_feats @ W_enc[0:256]
__device__ float g_attdot[NATTMAX];           // att_feats @ a_w[256:512]
__device__ float g_entdot[NMAX];              // ent_feats @ a_w[0:256]
__device__ int   g_cnt[NMAX];
__device__ int   g_ptr[NMAX + 1];
__device__ int   g_fill[NMAX];
__device__ int   g_idx[EMAX];                 // triple-index list, then col list (reused)
__device__ float g_F1[NMAX * DIM];
__device__ float g_F2[NMAX * DIM];
__device__ float g_X[NMAX * DIM];

// ---------------- helpers ----------------
__global__ void zero_int_k(int* p, int n) {
    int i = blockIdx.x * blockDim.x + threadIdx.x;
    if (i < n) p[i] = 0;
}

// attW + attdot: one block per attribute row
__global__ void att_k(const float* __restrict__ att_feats,
                      const float* __restrict__ W_enc,
                      const float* __restrict__ a_w, int natt) {
    int r = blockIdx.x;
    int d = threadIdx.x;
    __shared__ float sh[DIM];
    __shared__ float sred[8];
    sh[d] = att_feats[(size_t)r * DIM + d];
    __syncthreads();
    float acc = 0.f;
    #pragma unroll 8
    for (int k = 0; k < DIM; k++)
        acc += sh[k] * W_enc[(size_t)k * DIM + d];
    g_attW[(size_t)r * DIM + d] = acc;
    // attdot = dot(att_row, a_w[256:512])
    float v = sh[d] * a_w[DIM + d];
    for (int o = 16; o; o >>= 1) v += __shfl_xor_sync(0xffffffffu, v, o);
    if ((d & 31) == 0) sred[d >> 5] = v;
    __syncthreads();
    if (d == 0) {
        float s = 0.f;
        #pragma unroll
        for (int i = 0; i < 8; i++) s += sred[i];
        g_attdot[r] = s;
    }
}

// entdot: one warp per entity row
__global__ void entdot_k(const float* __restrict__ ent, int n) {
    int warp = (blockIdx.x * blockDim.x + threadIdx.x) >> 5;
    int lane = threadIdx.x & 31;
    if (warp >= n) return;
    // a_w low half cached via __ldg
    extern __shared__ float dummy[];
    float s = 0.f;
    const float* aw = (const float*)0;  // replaced below via param-less trick? no — pass via global
    (void)aw;
    // a_w is passed through g_F2? keep it simple: second param
    s = 0.f;
    // NOTE: real impl below uses the 2-arg version; this kernel is replaced.
    if (lane == 0) g_entdot[warp] = s;
}

// real entdot (with a_w pointer)
__global__ void entdot2_k(const float* __restrict__ ent, const float* __restrict__ a_w, int n) {
    int warp = (blockIdx.x * blockDim.x + threadIdx.x) >> 5;
    int lane = threadIdx.x & 31;
    if (warp >= n) return;
    const float* row = ent + (size_t)warp * DIM;
    float s = 0.f;
    #pragma unroll
    for (int d = lane; d < DIM; d += 32) s += row[d] * a_w[d];
    for (int o = 16; o; o >>= 1) s += __shfl_xor_sync(0xffffffffu, s, o);
    if (lane == 0) g_entdot[warp] = s;
}

// histogram of triple heads
__global__ void hist_triples_k(const int* __restrict__ triples, int ne) {
    int e = blockIdx.x * blockDim.x + threadIdx.x;
    if (e < ne) atomicAdd(&g_cnt[triples[3 * e]], 1);
}

// histogram of edge rows
__global__ void hist_rows_k(const int* __restrict__ rows, int ne) {
    int e = blockIdx.x * blockDim.x + threadIdx.x;
    if (e < ne) atomicAdd(&g_cnt[rows[e]], 1);
}

// single-block exclusive scan of g_cnt[0..n) -> g_ptr, g_fill; g_ptr[n]=total
__global__ void scan_k(int n) {
    __shared__ int sh[1024];
    __shared__ int s_off;
    if (threadIdx.x == 0) s_off = 0;
    __syncthreads();
    for (int base = 0; base < n; base += 1024) {
        int i = base + threadIdx.x;
        int v = (i < n) ? g_cnt[i] : 0;
        sh[threadIdx.x] = v;
        __syncthreads();
        for (int off = 1; off < 1024; off <<= 1) {
            int t = (threadIdx.x >= off) ? sh[threadIdx.x - off] : 0;
            __syncthreads();
            sh[threadIdx.x] += t;
            __syncthreads();
        }
        int incl = sh[threadIdx.x];
        int excl = incl - v;
        if (i < n) { g_ptr[i] = s_off + excl; g_fill[i] = s_off + excl; }
        __syncthreads();
        if (threadIdx.x == 1023) s_off += sh[1023];
        __syncthreads();
    }
    if (threadIdx.x == 0) g_ptr[n] = s_off;
}

__global__ void scatter_triples_k(const int* __restrict__ triples, int ne) {
    int e = blockIdx.x * blockDim.x + threadIdx.x;
    if (e < ne) {
        int pos = atomicAdd(&g_fill[triples[3 * e]], 1);
        g_idx[pos] = e;
    }
}

__global__ void scatter_cols_k(const int* __restrict__ rows, const int* __restrict__ cols, int ne) {
    int e = blockIdx.x * blockDim.x + threadIdx.x;
    if (e < ne) {
        int pos = atomicAdd(&g_fill[rows[e]], 1);
        g_idx[pos] = cols[e];
    }
}

// attributed encoder aggregation: one block (256 thr) per node
__global__ void attr_agg_k(const int* __restrict__ triples,
                           const float* __restrict__ ab_ptr,
                           const float* __restrict__ ent_feats) {
    int v = blockIdx.x;
    int d = threadIdx.x;
    int s = g_ptr[v], e = g_ptr[v + 1];
    __shared__ float sred[8];
    __shared__ float s_inv;
    __shared__ float sh_p[256];
    __shared__ int   sh_att[256];
    __shared__ int   sh_val[256];
    float ab = ab_ptr[0];
    float ed = g_entdot[v];

    // pass 1: row sum of exp(leaky(score))
    float part = 0.f;
    for (int i = s + d; i < e; i += 256) {
        int t = g_idx[i];
        float sc = ed + g_attdot[triples[3 * t + 2]] + ab;
        sc = sc > 0.f ? sc : 0.2f * sc;
        part += expf(sc);
    }
    float v2 = part;
    for (int o = 16; o; o >>= 1) v2 += __shfl_xor_sync(0xffffffffu, v2, o);
    if ((d & 31) == 0) sred[d >> 5] = v2;
    __syncthreads();
    if (d == 0) {
        float rs = 0.f;
        #pragma unroll
        for (int i = 0; i < 8; i++) rs += sred[i];
        s_inv = (rs > 0.f) ? 1.f / rs : 0.f;
    }
    __syncthreads();
    float inv_rs = s_inv;

    // pass 2: weighted aggregation; thread d owns dim d
    float acc = 0.f;
    for (int base = s; base < e; base += 256) {
        int cnt = min(256, e - base);
        if (d < cnt) {
            int t = g_idx[base + d];
            int att = triples[3 * t + 2];
            int val = triples[3 * t + 1];
            sh_att[d] = att;
            sh_val[d] = val;
            float sc = ed + g_attdot[att] + ab;
            sc = sc > 0.f ? sc : 0.2f * sc;
            sh_p[d] = expf(sc) * inv_rs;
        }
        __syncthreads();
        for (int j = 0; j < cnt; j++) {
            acc += sh_p[j] * (g_attW[(size_t)sh_att[j] * DIM + d] +
                              g_valW[(size_t)sh_val[j] * DIM + d]);
        }
        __syncthreads();
    }
    float x = acc + ent_feats[(size_t)v * DIM + d];
    g_F1[(size_t)v * DIM + d] = x > 0.f ? x : expm1f(x);
}

// GCN neighbor aggregation (mean): one block per node, CSR in g_ptr/g_idx
__global__ void gcn_agg_k(const float* __restrict__ feats, float* __restrict__ X) {
    int v = blockIdx.x;
    int d = threadIdx.x;
    int s = g_ptr[v], e = g_ptr[v + 1];
    __shared__ int sh_c[256];
    float acc = 0.f;
    for (int base = s; base < e; base += 256) {
        int cnt = min(256, e - base);
        if (d < cnt) sh_c[d] = g_idx[base + d];
        __syncthreads();
        for (int j = 0; j < cnt; j++)
            acc += feats[(size_t)sh_c[j] * DIM + d];
        __syncthreads();
    }
    float deg = (float)(e - s);
    X[(size_t)v * DIM + d] = (deg > 0.f) ? acc / deg : 0.f;
}

// ---------------- tiled fp32 GEMM: C[M,256] = A[M,K] * B[K,256] (+ epilogue) ----------------
// MODE 0: C = AB
// MODE 1: C = res + relu(AB + bias)
// MODE 2: C = res + (AB + bias)
#define GBM 64
#define GBN 64
#define GBK 16
template <int MODE>
__global__ void sgemm_k(const float* __restrict__ A, int lda,
                        const float* __restrict__ B,
                        const float* __restrict__ bias,
                        const float* __restrict__ res,
                        float* __restrict__ C,
                        int M, int K) {
    const int N = 256;
    __shared__ float As[GBK][GBM + 4];
    __shared__ float Bs[GBK][GBN];
    int tid = threadIdx.x;
    int row0 = blockIdx.y * GBM;
    int col0 = blockIdx.x * GBN;
    int ty = tid >> 4;       // 0..15
    int tx = tid & 15;       // 0..15
    float acc[4][4] = {};
    for (int k0 = 0; k0 < K; k0 += GBK) {
        // load A tile 64x16
        {
            int ar = tid >> 2;
            int ac = (tid & 3) * 4;
            int grow = row0 + ar;
            #pragma unroll
            for (int u = 0; u < 4; u++) {
                int gk = k0 + ac + u;
                float v = (grow < M && gk < K) ? A[(size_t)grow * lda + gk] : 0.f;
                As[ac + u][ar] = v;
            }
        }
        // load B tile 16x64
        {
            int br = tid >> 4;
            int bc = (tid & 15) * 4;
            int gk = k0 + br;
            #pragma unroll
            for (int u = 0; u < 4; u++) {
                float v = (gk < K) ? B[(size_t)gk * N + col0 + bc + u] : 0.f;
                Bs[br][bc + u] = v;
            }
        }
        __syncthreads();
        #pragma unroll
        for (int k = 0; k < GBK; k++) {
            float a[4], b[4];
            #pragma unroll
            for (int i = 0; i < 4; i++) a[i] = As[k][ty * 4 + i];
            #pragma unroll
            for (int j = 0; j < 4; j++) b[j] = Bs[k][tx * 4 + j];
            #pragma unroll
            for (int i = 0; i < 4; i++)
                #pragma unroll
                for (int j = 0; j < 4; j++)
                    acc[i][j] += a[i] * b[j];
        }
        __syncthreads();
    }
    #pragma unroll
    for (int i = 0; i < 4; i++) {
        int r = row0 + ty * 4 + i;
        if (r >= M) continue;
        #pragma unroll
        for (int j = 0; j < 4; j++) {
            int c = col0 + tx * 4 + j;
            float v = acc[i][j];
            if (MODE >= 1) {
                v += bias[c];
                if (MODE == 1) v = fmaxf(v, 0.f);
                v += res[(size_t)r * N + c];
            }
            C[(size_t)r * N + c] = v;
        }
    }
}

// row-wise L2 normalize
__global__ void l2norm_k(const float* __restrict__ in, float* __restrict__ out) {
    int v = blockIdx.x;
    int d = threadIdx.x;
    __shared__ float sred[8];
    __shared__ float s_inv;
    float x = in[(size_t)v * DIM + d];
    float sq = x * x;
    for (int o = 16; o; o >>= 1) sq += __shfl_xor_sync(0xffffffffu, sq, o);
    if ((d & 31) == 0) sred[d >> 5] = sq;
    __syncthreads();
    if (d == 0) {
        float s = 0.f;
        #pragma unroll
        for (int i = 0; i < 8; i++) s += sred[i];
        float nrm = sqrtf(s);
        s_inv = 1.f / fmaxf(nrm, 1e-12f);
    }
    __syncthreads();
    out[(size_t)v * DIM + d] = x * s_inv;
}

__global__ void gather_k(const int* __restrict__ seed, const float* __restrict__ src,
                         float* __restrict__ dst) {
    int i = blockIdx.x;
    int d = threadIdx.x;
    dst[(size_t)i * DIM + d] = src[(size_t)seed[i] * DIM + d];
}

// ---------------- host orchestration ----------------
static inline int ceildiv(int a, int b) { return (a + b - 1) / b; }

extern "C" void kernel_launch(void* const* d_in, const int* in_sizes, int n_in,
                              void* d_out, int out_size) {
    const int* seed_sr = (const int*)d_in[0];
    const int* seed_tg = (const int*)d_in[1];
    const int* tri_sr  = (const int*)d_in[2];
    const int* tri_tg  = (const int*)d_in[3];
    const int* rows_sr = (const int*)d_in[4];
    const int* cols_sr = (const int*)d_in[5];
    const int* rows_tg = (const int*)d_in[6];
    const int* cols_tg = (const int*)d_in[7];
    const float* att_feats = (const float*)d_in[8];
    const float* val_feats = (const float*)d_in[9];
    const float* ent_sr = (const float*)d_in[10];
    const float* ent_tg = (const float*)d_in[11];
    const float* a_w   = (const float*)d_in[12];
    const float* a_b   = (const float*)d_in[13];
    const float* W_enc = (const float*)d_in[14];
    const float* w1    = (const float*)d_in[15];
    const float* b1    = (const float*)d_in[16];
    const float* w2    = (const float*)d_in[17];
    const float* b2    = (const float*)d_in[18];
    (void)n_in; (void)out_size;

    const int nseed  = in_sizes[0];
    const int ne_tri = in_sizes[2] / 3;
    const int e_sr   = in_sizes[4];
    const int e_tg   = in_sizes[6];
    const int natt   = in_sizes[8] / DIM;
    const int nval   = in_sizes[9] / 300;
    const int n_sr   = in_sizes[10] / DIM;
    const int n_tg   = in_sizes[11] / DIM;

    float* valW;  cudaGetSymbolAddress((void**)&valW,  g_valW);
    float* F1;    cudaGetSymbolAddress((void**)&F1,    g_F1);
    float* F2;    cudaGetSymbolAddress((void**)&F2,    g_F2);
    float* Xb;    cudaGetSymbolAddress((void**)&Xb,    g_X);
    int*   cntp;  cudaGetSymbolAddress((void**)&cntp,  g_cnt);

    float* out = (float*)d_out;
    float* out_fs_seed = out;
    float* out_ft_seed = out + (size_t)nseed * DIM;
    float* out_fs      = out + (size_t)2 * nseed * DIM;
    float* out_ft      = out_fs + (size_t)n_sr * DIM;

    // ---- shared precompute ----
    att_k<<<natt, DIM>>>(att_feats, W_enc, a_w, natt);
    {
        dim3 grid(256 / GBN, ceildiv(nval, GBM));
        sgemm_k<0><<<grid, 256>>>(val_feats, 300, W_enc + (size_t)DIM * DIM,
                                  nullptr, nullptr, valW, nval, 300);
    }

    // ---- per side ----
    for (int side = 0; side < 2; side++) {
        const int n = side ? n_tg : n_sr;
        const int E = side ? e_tg : e_sr;
        const int* tri  = side ? tri_tg  : tri_sr;
        const int* rows = side ? rows_tg : rows_sr;
        const int* cols = side ? cols_tg : cols_sr;
        const float* ent = side ? ent_tg : ent_sr;
        const int* seed = side ? seed_tg : seed_sr;
        float* out_full = side ? out_ft : out_fs;
        float* out_seed = side ? out_ft_seed : out_fs_seed;

        // entdot
        entdot2_k<<<ceildiv(n * 32, 256), 256>>>(ent, a_w, n);

        // triple CSR
        zero_int_k<<<ceildiv(n, 256), 256>>>(cntp, n);
        hist_triples_k<<<ceildiv(ne_tri, 256), 256>>>(tri, ne_tri);
        scan_k<<<1, 1024>>>(n);
        scatter_triples_k<<<ceildiv(ne_tri, 256), 256>>>(tri, ne_tri);

        // attributed encoder -> F1
        attr_agg_k<<<n, DIM>>>(tri, a_b, ent);

        // edge CSR
        zero_int_k<<<ceildiv(n, 256), 256>>>(cntp, n);
        hist_rows_k<<<ceildiv(E, 256), 256>>>(rows, E);
        scan_k<<<1, 1024>>>(n);
        scatter_cols_k<<<ceildiv(E, 256), 256>>>(rows, cols, E);

        dim3 ggrid(256 / GBN, ceildiv(n, GBM));
        // GCN layer 1: F2 = F1 + relu((agg(F1)/deg) @ w1 + b1)
        gcn_agg_k<<<n, DIM>>>(F1, Xb);
        sgemm_k<1><<<ggrid, 256>>>(Xb, DIM, w1, b1, F1, F2, n, DIM);
        // GCN layer 2: F3 = F2 + ((agg(F2)/deg) @ w2 + b2)   (F3 reuses F1)
        gcn_agg_k<<<n, DIM>>>(F2, Xb);
        sgemm_k<2><<<ggrid, 256>>>(Xb, DIM, w2, b2, F2, F1, n, DIM);

        // l2norm -> output, gather seeds
        l2norm_k<<<n, DIM>>>(F1, out_full);
        gather_k<<<nseed, DIM>>>(seed, out_full, out_seed);
    }
}

// round 2
// speedup vs baseline: 1.8250x; 1.8250x over previous
#include <cuda_runtime.h>
#include <math.h>
#include <stdint.h>

#define DIM 256
#define NMAX 50000
#define EMAX 860000
#define NVALMAX 100000
#define NATTMAX 1001

// ---------------- scratch (static device globals; no allocation) ----------------
__device__ float g_valW[NVALMAX * DIM];
__device__ float g_attW[NATTMAX * DIM];
__device__ float g_attdot[NATTMAX];
__device__ float g_entdot[NMAX];
__device__ int   g_cnt[NMAX];
__device__ int   g_ptr[NMAX + 1];
__device__ int   g_fill[NMAX];
__device__ int   g_idx[EMAX];
__device__ float g_F1[NMAX * DIM];
__device__ float g_F2[NMAX * DIM];
__device__ float g_X[NMAX * DIM];

// ---------------- packed f32x2 helpers ----------------
__device__ __forceinline__ unsigned long long pack_dup(float a) {
    unsigned long long r;
    asm("mov.b64 %0, {%1, %1};" : "=l"(r) : "f"(a));
    return r;
}
__device__ __forceinline__ void fma2(unsigned long long& d, unsigned long long a,
                                     unsigned long long b) {
    asm("fma.rn.f32x2 %0, %1, %2, %0;" : "+l"(d) : "l"(a), "l"(b));
}
__device__ __forceinline__ float2 unpack2(unsigned long long v) {
    float2 f;
    asm("mov.b64 {%0, %1}, %2;" : "=f"(f.x), "=f"(f.y) : "l"(v));
    return f;
}

// ---------------- helpers ----------------
__global__ void zero_int_k(int* p, int n) {
    int i = blockIdx.x * blockDim.x + threadIdx.x;
    if (i < n) p[i] = 0;
}

// attW + attdot: one block per attribute row
__global__ void att_k(const float* __restrict__ att_feats,
                      const float* __restrict__ W_enc,
                      const float* __restrict__ a_w, int natt) {
    int r = blockIdx.x;
    int d = threadIdx.x;
    __shared__ float sh[DIM];
    __shared__ float sred[8];
    sh[d] = att_feats[(size_t)r * DIM + d];
    __syncthreads();
    float acc = 0.f;
    #pragma unroll 8
    for (int k = 0; k < DIM; k++)
        acc += sh[k] * W_enc[(size_t)k * DIM + d];
    g_attW[(size_t)r * DIM + d] = acc;
    float v = sh[d] * a_w[DIM + d];
    for (int o = 16; o; o >>= 1) v += __shfl_xor_sync(0xffffffffu, v, o);
    if ((d & 31) == 0) sred[d >> 5] = v;
    __syncthreads();
    if (d == 0) {
        float s = 0.f;
        #pragma unroll
        for (int i = 0; i < 8; i++) s += sred[i];
        g_attdot[r] = s;
    }
}

__global__ void entdot2_k(const float* __restrict__ ent, const float* __restrict__ a_w, int n) {
    int warp = (blockIdx.x * blockDim.x + threadIdx.x) >> 5;
    int lane = threadIdx.x & 31;
    if (warp >= n) return;
    const float* row = ent + (size_t)warp * DIM;
    float s = 0.f;
    #pragma unroll
    for (int d = lane; d < DIM; d += 32) s += row[d] * a_w[d];
    for (int o = 16; o; o >>= 1) s += __shfl_xor_sync(0xffffffffu, s, o);
    if (lane == 0) g_entdot[warp] = s;
}

__global__ void hist_triples_k(const int* __restrict__ triples, int ne) {
    int e = blockIdx.x * blockDim.x + threadIdx.x;
    if (e < ne) atomicAdd(&g_cnt[triples[3 * e]], 1);
}
__global__ void hist_rows_k(const int* __restrict__ rows, int ne) {
    int e = blockIdx.x * blockDim.x + threadIdx.x;
    if (e < ne) atomicAdd(&g_cnt[rows[e]], 1);
}

// single-block scan (warp-shuffle based, 2 barriers/tile)
__global__ void scan_k(int n) {
    __shared__ int wsum[32];
    __shared__ int s_off;
    int lane = threadIdx.x & 31;
    int wid = threadIdx.x >> 5;
    if (threadIdx.x == 0) s_off = 0;
    __syncthreads();
    for (int base = 0; base < n; base += 1024) {
        int i = base + threadIdx.x;
        int v = (i < n) ? g_cnt[i] : 0;
        int x = v;
        #pragma unroll
        for (int o = 1; o < 32; o <<= 1) {
            int y = __shfl_up_sync(0xffffffffu, x, o);
            if (lane >= o) x += y;
        }
        if (lane == 31) wsum[wid] = x;
        __syncthreads();
        if (wid == 0) {
            int w = wsum[lane];
            int xs = w;
            #pragma unroll
            for (int o = 1; o < 32; o <<= 1) {
                int y = __shfl_up_sync(0xffffffffu, xs, o);
                if (lane >= o) xs += y;
            }
            wsum[lane] = xs - w;  // exclusive warp offsets
        }
        __syncthreads();
        int excl = s_off + wsum[wid] + x - v;
        if (i < n) { g_ptr[i] = excl; g_fill[i] = excl; }
        __syncthreads();
        if (threadIdx.x == 1023) s_off += wsum[31] + x;
        __syncthreads();
    }
    if (threadIdx.x == 0) g_ptr[n] = s_off;
}

__global__ void scatter_triples_k(const int* __restrict__ triples, int ne) {
    int e = blockIdx.x * blockDim.x + threadIdx.x;
    if (e < ne) {
        int pos = atomicAdd(&g_fill[triples[3 * e]], 1);
        g_idx[pos] = e;
    }
}
__global__ void scatter_cols_k(const int* __restrict__ rows, const int* __restrict__ cols, int ne) {
    int e = blockIdx.x * blockDim.x + threadIdx.x;
    if (e < ne) {
        int pos = atomicAdd(&g_fill[rows[e]], 1);
        g_idx[pos] = cols[e];
    }
}

// attributed encoder aggregation: one block (64 thr) per node; thread t owns dims 4t..4t+3
__global__ void attr_agg_k(const int* __restrict__ triples,
                           const float* __restrict__ ab_ptr,
                           const float* __restrict__ ent_feats) {
    int v = blockIdx.x;
    int t = threadIdx.x;           // 0..63
    int s = g_ptr[v], e = g_ptr[v + 1];
    __shared__ float sred[2];
    __shared__ float s_inv;
    __shared__ float sh_p[64];
    __shared__ int sh_att[64];
    __shared__ int sh_val[64];
    float ab = ab_ptr[0];
    float ed = g_entdot[v];

    // pass 1: row sum of exp(leaky(score))
    float part = 0.f;
    for (int i = s + t; i < e; i += 64) {
        int tt = g_idx[i];
        float sc = ed + g_attdot[triples[3 * tt + 2]] + ab;
        sc = sc > 0.f ? sc : 0.2f * sc;
        part += expf(sc);
    }
    for (int o = 16; o; o >>= 1) part += __shfl_xor_sync(0xffffffffu, part, o);
    if ((t & 31) == 0) sred[t >> 5] = part;
    __syncthreads();
    if (t == 0) {
        float rs = sred[0] + sred[1];
        s_inv = (rs > 0.f) ? 1.f / rs : 0.f;
    }
    __syncthreads();
    float inv_rs = s_inv;

    // pass 2: weighted aggregation, float4 per thread
    float4 acc = make_float4(0.f, 0.f, 0.f, 0.f);
    for (int base = s; base < e; base += 64) {
        int cnt = min(64, e - base);
        if (t < cnt) {
            int tt = g_idx[base + t];
            int att = triples[3 * tt + 2];
            int val = triples[3 * tt + 1];
            sh_att[t] = att;
            sh_val[t] = val;
            float sc = ed + g_attdot[att] + ab;
            sc = sc > 0.f ? sc : 0.2f * sc;
            sh_p[t] = expf(sc) * inv_rs;
        }
        __syncthreads();
        for (int j = 0; j < cnt; j++) {
            float p = sh_p[j];
            const float4 aw = *(const float4*)&g_attW[(size_t)sh_att[j] * DIM + t * 4];
            const float4 vw = *(const float4*)&g_valW[(size_t)sh_val[j] * DIM + t * 4];
            acc.x += p * (aw.x + vw.x);
            acc.y += p * (aw.y + vw.y);
            acc.z += p * (aw.z + vw.z);
            acc.w += p * (aw.w + vw.w);
        }
        __syncthreads();
    }
    const float4 ef = *(const float4*)&ent_feats[(size_t)v * DIM + t * 4];
    float4 x = make_float4(acc.x + ef.x, acc.y + ef.y, acc.z + ef.z, acc.w + ef.w);
    x.x = x.x > 0.f ? x.x : expm1f(x.x);
    x.y = x.y > 0.f ? x.y : expm1f(x.y);
    x.z = x.z > 0.f ? x.z : expm1f(x.z);
    x.w = x.w > 0.f ? x.w : expm1f(x.w);
    *(float4*)&g_F1[(size_t)v * DIM + t * 4] = x;
}

// GCN neighbor aggregation (mean): one block (64 thr) per node
__global__ void gcn_agg_k(const float* __restrict__ feats, float* __restrict__ X) {
    int v = blockIdx.x;
    int t = threadIdx.x;
    int s = g_ptr[v], e = g_ptr[v + 1];
    __shared__ int sh_c[64];
    float4 acc = make_float4(0.f, 0.f, 0.f, 0.f);
    for (int base = s; base < e; base += 64) {
        int cnt = min(64, e - base);
        if (t < cnt) sh_c[t] = g_idx[base + t];
        __syncthreads();
        for (int j = 0; j < cnt; j++) {
            const float4 f = *(const float4*)&feats[(size_t)sh_c[j] * DIM + t * 4];
            acc.x += f.x; acc.y += f.y; acc.z += f.z; acc.w += f.w;
        }
        __syncthreads();
    }
    float inv = (e > s) ? 1.f / (float)(e - s) : 0.f;
    acc.x *= inv; acc.y *= inv; acc.z *= inv; acc.w *= inv;
    *(float4*)&X[(size_t)v * DIM + t * 4] = acc;
}

// ---------------- f32x2 GEMM: C[M,256] = A[M,K] * B[K,256] (+ epilogue) ----------------
// MODE 0: C = AB
// MODE 1: C = res + relu(AB + bias)
// MODE 2: C = res + (AB + bias)
#define BM 128
#define BN 128
#define BK 8
template <int MODE>
__global__ __launch_bounds__(256, 2)
void sgemm_k(const float* __restrict__ A, int lda,
             const float* __restrict__ B,
             const float* __restrict__ bias,
             const float* __restrict__ res,
             float* __restrict__ C,
             int M, int K) {
    const int N = 256;
    __shared__ float As[BK][BM];
    __shared__ float Bs[BK][BN];
    int tid = threadIdx.x;
    int row0 = blockIdx.y * BM;
    int col0 = blockIdx.x * BN;
    int ty = tid >> 4;       // 0..15
    int tx = tid & 15;       // 0..15

    // global load mapping
    int arow = tid >> 1;            // 0..127
    int acol = (tid & 1) * 4;       // 0 or 4
    int brow = tid >> 5;            // 0..7
    int bcol = (tid & 31) * 4;      // 0..124

    int grow = row0 + arow;
    bool rowok = grow < M;
    const float* Arow = A + (size_t)(rowok ? grow : 0) * lda;

    unsigned long long acc[8][4];
    #pragma unroll
    for (int i = 0; i < 8; i++)
        #pragma unroll
        for (int j = 0; j < 4; j++) acc[i][j] = 0ull;

    auto loadA = [&](int k0) -> float4 {
        int gk = k0 + acol;
        float4 av = make_float4(0.f, 0.f, 0.f, 0.f);
        if (rowok) {
            if (gk + 3 < K) av = *(const float4*)(Arow + gk);
            else {
                float tmp[4] = {0.f, 0.f, 0.f, 0.f};
                #pragma unroll
                for (int u = 0; u < 4; u++) if (gk + u < K) tmp[u] = Arow[gk + u];
                av = make_float4(tmp[0], tmp[1], tmp[2], tmp[3]);
            }
        }
        return av;
    };
    auto loadB = [&](int k0) -> float4 {
        int gk = k0 + brow;
        if (gk < K) return *(const float4*)(B + (size_t)gk * N + col0 + bcol);
        return make_float4(0.f, 0.f, 0.f, 0.f);
    };

    float4 aReg = loadA(0);
    float4 bReg = loadB(0);

    for (int k0 = 0; k0 < K; k0 += BK) {
        As[acol + 0][arow] = aReg.x;
        As[acol + 1][arow] = aReg.y;
        As[acol + 2][arow] = aReg.z;
        As[acol + 3][arow] = aReg.w;
        *(float4*)&Bs[brow][bcol] = bReg;
        __syncthreads();
        if (k0 + BK < K) {
            aReg = loadA(k0 + BK);
            bReg = loadB(k0 + BK);
        }
        #pragma unroll
        for (int k = 0; k < BK; k++) {
            const float4 a0 = *(const float4*)&As[k][ty * 4];
            const float4 a1 = *(const float4*)&As[k][64 + ty * 4];
            const ulonglong2 b01 = *(const ulonglong2*)&Bs[k][tx * 4];
            const ulonglong2 b23 = *(const ulonglong2*)&Bs[k][64 + tx * 4];
            unsigned long long bp[4] = {b01.x, b01.y, b23.x, b23.y};
            unsigned long long ap[8];
            ap[0] = pack_dup(a0.x); ap[1] = pack_dup(a0.y);
            ap[2] = pack_dup(a0.z); ap[3] = pack_dup(a0.w);
            ap[4] = pack_dup(a1.x); ap[5] = pack_dup(a1.y);
            ap[6] = pack_dup(a1.z); ap[7] = pack_dup(a1.w);
            #pragma unroll
            for (int i = 0; i < 8; i++)
                #pragma unroll
                for (int j = 0; j < 4; j++)
                    fma2(acc[i][j], ap[i], bp[j]);
        }
        __syncthreads();
    }

    // epilogue
    #pragma unroll
    for (int half = 0; half < 2; half++) {
        #pragma unroll
        for (int i2 = 0; i2 < 4; i2++) {
            int r = row0 + half * 64 + ty * 4 + i2;
            if (r >= M) continue;
            int i = half * 4 + i2;
            #pragma unroll
            for (int ch = 0; ch < 2; ch++) {
                int c = col0 + ch * 64 + tx * 4;
                float2 lo = unpack2(acc[i][ch * 2 + 0]);
                float2 hi = unpack2(acc[i][ch * 2 + 1]);
                float4 v = make_float4(lo.x, lo.y, hi.x, hi.y);
                if (MODE >= 1) {
                    const float4 bb = *(const float4*)&bias[c];
                    v.x += bb.x; v.y += bb.y; v.z += bb.z; v.w += bb.w;
                    if (MODE == 1) {
                        v.x = fmaxf(v.x, 0.f); v.y = fmaxf(v.y, 0.f);
                        v.z = fmaxf(v.z, 0.f); v.w = fmaxf(v.w, 0.f);
                    }
                    const float4 rr = *(const float4*)&res[(size_t)r * N + c];
                    v.x += rr.x; v.y += rr.y; v.z += rr.z; v.w += rr.w;
                }
                *(float4*)&C[(size_t)r * N + c] = v;
            }
        }
    }
}

// row-wise L2 normalize: 64 threads per node
__global__ void l2norm_k(const float* __restrict__ in, float* __restrict__ out) {
    int v = blockIdx.x;
    int t = threadIdx.x;
    __shared__ float sred[2];
    __shared__ float s_inv;
    const float4 x = *(const float4*)&in[(size_t)v * DIM + t * 4];
    float sq = x.x * x.x + x.y * x.y + x.z * x.z + x.w * x.w;
    for (int o = 16; o; o >>= 1) sq += __shfl_xor_sync(0xffffffffu, sq, o);
    if ((t & 31) == 0) sred[t >> 5] = sq;
    __syncthreads();
    if (t == 0) {
        float nrm = sqrtf(sred[0] + sred[1]);
        s_inv = 1.f / fmaxf(nrm, 1e-12f);
    }
    __syncthreads();
    float inv = s_inv;
    float4 y = make_float4(x.x * inv, x.y * inv, x.z * inv, x.w * inv);
    *(float4*)&out[(size_t)v * DIM + t * 4] = y;
}

__global__ void gather_k(const int* __restrict__ seed, const float* __restrict__ src,
                         float* __restrict__ dst) {
    int i = blockIdx.x;
    int t = threadIdx.x;
    *(float4*)&dst[(size_t)i * DIM + t * 4] =
        *(const float4*)&src[(size_t)seed[i] * DIM + t * 4];
}

// ---------------- host orchestration ----------------
static inline int ceildiv(int a, int b) { return (a + b - 1) / b; }

extern "C" void kernel_launch(void* const* d_in, const int* in_sizes, int n_in,
                              void* d_out, int out_size) {
    const int* seed_sr = (const int*)d_in[0];
    const int* seed_tg = (const int*)d_in[1];
    const int* tri_sr  = (const int*)d_in[2];
    const int* tri_tg  = (const int*)d_in[3];
    const int* rows_sr = (const int*)d_in[4];
    const int* cols_sr = (const int*)d_in[5];
    const int* rows_tg = (const int*)d_in[6];
    const int* cols_tg = (const int*)d_in[7];
    const float* att_feats = (const float*)d_in[8];
    const float* val_feats = (const float*)d_in[9];
    const float* ent_sr = (const float*)d_in[10];
    const float* ent_tg = (const float*)d_in[11];
    const float* a_w   = (const float*)d_in[12];
    const float* a_b   = (const float*)d_in[13];
    const float* W_enc = (const float*)d_in[14];
    const float* w1    = (const float*)d_in[15];
    const float* b1    = (const float*)d_in[16];
    const float* w2    = (const float*)d_in[17];
    const float* b2    = (const float*)d_in[18];
    (void)n_in; (void)out_size;

    const int nseed  = in_sizes[0];
    const int ne_tri = in_sizes[2] / 3;
    const int e_sr   = in_sizes[4];
    const int e_tg   = in_sizes[6];
    const int natt   = in_sizes[8] / DIM;
    const int nval   = in_sizes[9] / 300;
    const int n_sr   = in_sizes[10] / DIM;
    const int n_tg   = in_sizes[11] / DIM;

    float* valW;  cudaGetSymbolAddress((void**)&valW,  g_valW);
    float* F1;    cudaGetSymbolAddress((void**)&F1,    g_F1);
    float* F2;    cudaGetSymbolAddress((void**)&F2,    g_F2);
    float* Xb;    cudaGetSymbolAddress((void**)&Xb,    g_X);
    int*   cntp;  cudaGetSymbolAddress((void**)&cntp,  g_cnt);

    float* out = (float*)d_out;
    float* out_fs_seed = out;
    float* out_ft_seed = out + (size_t)nseed * DIM;
    float* out_fs      = out + (size_t)2 * nseed * DIM;
    float* out_ft      = out_fs + (size_t)n_sr * DIM;

    // ---- shared precompute + side-0 CSR front (ordered so launch #5 = big valW GEMM for ncu) ----
    att_k<<<natt, DIM>>>(att_feats, W_enc, a_w, natt);                       // 0
    entdot2_k<<<ceildiv(n_sr * 32, 256), 256>>>(ent_sr, a_w, n_sr);          // 1
    zero_int_k<<<ceildiv(n_sr, 256), 256>>>(cntp, n_sr);                     // 2
    hist_triples_k<<<ceildiv(ne_tri, 256), 256>>>(tri_sr, ne_tri);           // 3
    scan_k<<<1, 1024>>>(n_sr);                                               // 4
    {
        dim3 grid(256 / BN, ceildiv(nval, BM));                              // 5 (profiled)
        sgemm_k<0><<<grid, 256>>>(val_feats, 300, W_enc + (size_t)DIM * DIM,
                                  nullptr, nullptr, valW, nval, 300);
    }
    scatter_triples_k<<<ceildiv(ne_tri, 256), 256>>>(tri_sr, ne_tri);        // 6

    for (int side = 0; side < 2; side++) {
        const int n = side ? n_tg : n_sr;
        const int E = side ? e_tg : e_sr;
        const int* tri  = side ? tri_tg  : tri_sr;
        const int* rows = side ? rows_tg : rows_sr;
        const int* cols = side ? cols_tg : cols_sr;
        const float* ent = side ? ent_tg : ent_sr;
        const int* seed = side ? seed_tg : seed_sr;
        float* out_full = side ? out_ft : out_fs;
        float* out_seed = side ? out_ft_seed : out_fs_seed;

        if (side == 1) {
            entdot2_k<<<ceildiv(n * 32, 256), 256>>>(ent, a_w, n);
            zero_int_k<<<ceildiv(n, 256), 256>>>(cntp, n);
            hist_triples_k<<<ceildiv(ne_tri, 256), 256>>>(tri, ne_tri);
            scan_k<<<1, 1024>>>(n);
            scatter_triples_k<<<ceildiv(ne_tri, 256), 256>>>(tri, ne_tri);
        }

        // attributed encoder -> F1
        attr_agg_k<<<n, 64>>>(tri, a_b, ent);

        // edge CSR
        zero_int_k<<<ceildiv(n, 256), 256>>>(cntp, n);
        hist_rows_k<<<ceildiv(E, 256), 256>>>(rows, E);
        scan_k<<<1, 1024>>>(n);
        scatter_cols_k<<<ceildiv(E, 256), 256>>>(rows, cols, E);

        dim3 ggrid(256 / BN, ceildiv(n, BM));
        // GCN layer 1: F2 = F1 + relu((agg(F1)/deg) @ w1 + b1)
        gcn_agg_k<<<n, 64>>>(F1, Xb);
        sgemm_k<1><<<ggrid, 256>>>(Xb, DIM, w1, b1, F1, F2, n, DIM);
        // GCN layer 2: F3 = F2 + ((agg(F2)/deg) @ w2 + b2)  (F3 reuses F1)
        gcn_agg_k<<<n, 64>>>(F2, Xb);
        sgemm_k<2><<<ggrid, 256>>>(Xb, DIM, w2, b2, F2, F1, n, DIM);

        // l2norm -> output, gather seeds
        l2norm_k<<<n, 64>>>(F1, out_full);
        gather_k<<<nseed, 64>>>(seed, out_full, out_seed);
    }
}

// round 4
// speedup vs baseline: 2.1036x; 1.1526x over previous
#include <cuda_runtime.h>
#include <cuda_bf16.h>
#include <math.h>
#include <stdint.h>

#define DIM 256
#define NMAX 50000
#define EMAX 860000
#define NVALMAX 100000
#define NATTMAX 1001
#define KPAD_VAL 320
#define MT_S 40   // smem row stride in bf16 (80B): conflict-free fragment LDS

// ---------------- scratch (static device globals; no allocation) ----------------
__device__ float g_valW[NVALMAX * DIM];
__device__ float g_attW[NATTMAX * DIM];
__device__ float g_attdot[NATTMAX];
__device__ float g_entdot[NMAX];
__device__ int   g_cnt[NMAX];
__device__ int   g_ptr[NMAX + 1];
__device__ int   g_fill[NMAX];
__device__ int   g_idx[EMAX];
__device__ float g_F1[NMAX * DIM];
__device__ float g_F2[NMAX * DIM];
// bf16 hi/lo split operands
__device__ __nv_bfloat16 g_a_h[NVALMAX * KPAD_VAL];
__device__ __nv_bfloat16 g_a_l[NVALMAX * KPAD_VAL];
__device__ __nv_bfloat16 g_wet_h[DIM * KPAD_VAL];
__device__ __nv_bfloat16 g_wet_l[DIM * KPAD_VAL];
__device__ __nv_bfloat16 g_w1t_h[DIM * DIM];
__device__ __nv_bfloat16 g_w1t_l[DIM * DIM];
__device__ __nv_bfloat16 g_w2t_h[DIM * DIM];
__device__ __nv_bfloat16 g_w2t_l[DIM * DIM];

// ---------------- mma.sync wrapper (bf16, fp32 accum; compute_103-safe) ----------------
__device__ __forceinline__ void mma16816(float* c, const uint32_t* a, const uint32_t* b) {
    asm volatile(
        "mma.sync.aligned.m16n8k16.row.col.f32.bf16.bf16.f32 "
        "{%0,%1,%2,%3}, {%4,%5,%6,%7}, {%8,%9}, {%0,%1,%2,%3};"
        : "+f"(c[0]), "+f"(c[1]), "+f"(c[2]), "+f"(c[3])
        : "r"(a[0]), "r"(a[1]), "r"(a[2]), "r"(a[3]), "r"(b[0]), "r"(b[1]));
}

// ---------------- HMMA GEMM: C[M,256] = (Ah+Al)[M,Kpad] @ (Bh+Bl)t[256,Kpad]^T ----------
// MODE 0: C = AB ; MODE 1: C = res + relu(AB+bias) ; MODE 2: C = res + AB + bias
template <int MODE>
__global__ void __launch_bounds__(256)
mma_gemm_k(const __nv_bfloat16* __restrict__ Ah, const __nv_bfloat16* __restrict__ Al,
           const __nv_bfloat16* __restrict__ Bh, const __nv_bfloat16* __restrict__ Bl,
           int M, int Kpad,
           const float* __restrict__ bias, const float* __restrict__ res,
           float* __restrict__ C) {
    __shared__ __align__(16) __nv_bfloat16 sAh[128 * MT_S];
    __shared__ __align__(16) __nv_bfloat16 sAl[128 * MT_S];
    __shared__ __align__(16) __nv_bfloat16 sBh[128 * MT_S];
    __shared__ __align__(16) __nv_bfloat16 sBl[128 * MT_S];
    int tid = threadIdx.x;
    int wid = tid >> 5, lane = tid & 31;
    int wm = wid & 3;      // 4 warps over 128 rows
    int wn = wid >> 2;     // 2 warps over 128 cols
    int row0 = blockIdx.y * 128;
    int col0 = blockIdx.x * 128;

    float acc[2][8][4];
    #pragma unroll
    for (int mt = 0; mt < 2; mt++)
        #pragma unroll
        for (int nt = 0; nt < 8; nt++)
            #pragma unroll
            for (int q = 0; q < 4; q++) acc[mt][nt][q] = 0.f;

    int lr = tid >> 2;   // 0..63
    int seg = tid & 3;   // 0..3 (8 bf16 each)

    for (int k0 = 0; k0 < Kpad; k0 += 32) {
        #pragma unroll
        for (int h = 0; h < 2; h++) {
            int r = lr + h * 64;
            int gr = row0 + r;
            uint4 vh = make_uint4(0, 0, 0, 0), vl = make_uint4(0, 0, 0, 0);
            if (gr < M) {
                size_t g = (size_t)gr * Kpad + k0 + seg * 8;
                vh = *(const uint4*)(Ah + g);
                vl = *(const uint4*)(Al + g);
            }
            *(uint4*)&sAh[r * MT_S + seg * 8] = vh;
            *(uint4*)&sAl[r * MT_S + seg * 8] = vl;
            size_t gb = (size_t)(col0 + r) * Kpad + k0 + seg * 8;
            *(uint4*)&sBh[r * MT_S + seg * 8] = *(const uint4*)(Bh + gb);
            *(uint4*)&sBl[r * MT_S + seg * 8] = *(const uint4*)(Bl + gb);
        }
        __syncthreads();
        #pragma unroll
        for (int ks = 0; ks < 2; ks++) {
            int acol = ks * 16 + (lane & 3) * 2;
            uint32_t aH[2][4], aL[2][4];
            #pragma unroll
            for (int mt = 0; mt < 2; mt++) {
                int rb = (wm * 32 + mt * 16 + (lane >> 2)) * MT_S + acol;
                aH[mt][0] = *(const uint32_t*)&sAh[rb];
                aH[mt][1] = *(const uint32_t*)&sAh[rb + 8 * MT_S];
                aH[mt][2] = *(const uint32_t*)&sAh[rb + 8];
                aH[mt][3] = *(const uint32_t*)&sAh[rb + 8 * MT_S + 8];
                aL[mt][0] = *(const uint32_t*)&sAl[rb];
                aL[mt][1] = *(const uint32_t*)&sAl[rb + 8 * MT_S];
                aL[mt][2] = *(const uint32_t*)&sAl[rb + 8];
                aL[mt][3] = *(const uint32_t*)&sAl[rb + 8 * MT_S + 8];
            }
            #pragma unroll
            for (int nt = 0; nt < 8; nt++) {
                int nb = (wn * 64 + nt * 8 + (lane >> 2)) * MT_S + acol;
                uint32_t bH[2], bL[2];
                bH[0] = *(const uint32_t*)&sBh[nb];
                bH[1] = *(const uint32_t*)&sBh[nb + 8];
                bL[0] = *(const uint32_t*)&sBl[nb];
                bL[1] = *(const uint32_t*)&sBl[nb + 8];
                #pragma unroll
                for (int mt = 0; mt < 2; mt++) {
                    mma16816(acc[mt][nt], aH[mt], bH);
                    mma16816(acc[mt][nt], aL[mt], bH);
                    mma16816(acc[mt][nt], aH[mt], bL);
                }
            }
        }
        __syncthreads();
    }

    // epilogue: c0,c1 -> (row=lane/4, col+{0,1}); c2,c3 -> row+8
    #pragma unroll
    for (int mt = 0; mt < 2; mt++) {
        #pragma unroll
        for (int half = 0; half < 2; half++) {
            int r = row0 + wm * 32 + mt * 16 + (lane >> 2) + half * 8;
            if (r >= M) continue;
            #pragma unroll
            for (int nt = 0; nt < 8; nt++) {
                int c = col0 + wn * 64 + nt * 8 + (lane & 3) * 2;
                float2 v;
                v.x = acc[mt][nt][half * 2 + 0];
                v.y = acc[mt][nt][half * 2 + 1];
                if (MODE >= 1) {
                    const float2 bb = *(const float2*)&bias[c];
                    v.x += bb.x; v.y += bb.y;
                    if (MODE == 1) { v.x = fmaxf(v.x, 0.f); v.y = fmaxf(v.y, 0.f); }
                    const float2 rr = *(const float2*)&res[(size_t)r * 256 + c];
                    v.x += rr.x; v.y += rr.y;
                }
                *(float2*)&C[(size_t)r * 256 + c] = v;
            }
        }
    }
}

// ---------------- fp32 -> bf16 hi/lo splits ----------------
__global__ void split_pad_k(const float* __restrict__ src, int M, int K, int Kpad,
                            __nv_bfloat16* __restrict__ hi, __nv_bfloat16* __restrict__ lo) {
    long long idx = (long long)blockIdx.x * blockDim.x + threadIdx.x;
    long long tot = (long long)M * Kpad;
    if (idx >= tot) return;
    int k = (int)(idx % Kpad);
    long long r = idx / Kpad;
    float v = (k < K) ? src[r * K + k] : 0.f;
    __nv_bfloat16 h = __float2bfloat16(v);
    hi[idx] = h;
    lo[idx] = __float2bfloat16(v - __bfloat162float(h));
}
__global__ void tsplit_k(const float* __restrict__ src, int K, int Kpad,
                         __nv_bfloat16* __restrict__ hi, __nv_bfloat16* __restrict__ lo) {
    int idx = blockIdx.x * blockDim.x + threadIdx.x;
    if (idx >= 256 * Kpad) return;
    int k = idx % Kpad;
    int n = idx / Kpad;
    float v = (k < K) ? src[(size_t)k * 256 + n] : 0.f;
    __nv_bfloat16 h = __float2bfloat16(v);
    hi[idx] = h;
    lo[idx] = __float2bfloat16(v - __bfloat162float(h));
}

// ---------------- SIMT pipeline kernels (validated round 2) ----------------
__global__ void zero_int_k(int* p, int n) {
    int i = blockIdx.x * blockDim.x + threadIdx.x;
    if (i < n) p[i] = 0;
}
__global__ void att_k(const float* __restrict__ att_feats,
                      const float* __restrict__ W_enc,
                      const float* __restrict__ a_w, int natt) {
    int r = blockIdx.x;
    int d = threadIdx.x;
    __shared__ float sh[DIM];
    __shared__ float sred[8];
    sh[d] = att_feats[(size_t)r * DIM + d];
    __syncthreads();
    float acc = 0.f;
    #pragma unroll 8
    for (int k = 0; k < DIM; k++) acc += sh[k] * W_enc[(size_t)k * DIM + d];
    g_attW[(size_t)r * DIM + d] = acc;
    float v = sh[d] * a_w[DIM + d];
    for (int o = 16; o; o >>= 1) v += __shfl_xor_sync(0xffffffffu, v, o);
    if ((d & 31) == 0) sred[d >> 5] = v;
    __syncthreads();
    if (d == 0) {
        float s = 0.f;
        #pragma unroll
        for (int i = 0; i < 8; i++) s += sred[i];
        g_attdot[r] = s;
    }
}
__global__ void entdot2_k(const float* __restrict__ ent, const float* __restrict__ a_w, int n) {
    int warp = (blockIdx.x * blockDim.x + threadIdx.x) >> 5;
    int lane = threadIdx.x & 31;
    if (warp >= n) return;
    const float* row = ent + (size_t)warp * DIM;
    float s = 0.f;
    #pragma unroll
    for (int d = lane; d < DIM; d += 32) s += row[d] * a_w[d];
    for (int o = 16; o; o >>= 1) s += __shfl_xor_sync(0xffffffffu, s, o);
    if (lane == 0) g_entdot[warp] = s;
}
__global__ void hist_triples_k(const int* __restrict__ triples, int ne) {
    int e = blockIdx.x * blockDim.x + threadIdx.x;
    if (e < ne) atomicAdd(&g_cnt[triples[3 * e]], 1);
}
__global__ void hist_rows_k(const int* __restrict__ rows, int ne) {
    int e = blockIdx.x * blockDim.x + threadIdx.x;
    if (e < ne) atomicAdd(&g_cnt[rows[e]], 1);
}
__global__ void scan_k(int n) {
    __shared__ int wsum[32];
    __shared__ int s_off;
    int lane = threadIdx.x & 31;
    int wid = threadIdx.x >> 5;
    if (threadIdx.x == 0) s_off = 0;
    __syncthreads();
    for (int base = 0; base < n; base += 1024) {
        int i = base + threadIdx.x;
        int v = (i < n) ? g_cnt[i] : 0;
        int x = v;
        #pragma unroll
        for (int o = 1; o < 32; o <<= 1) {
            int y = __shfl_up_sync(0xffffffffu, x, o);
            if (lane >= o) x += y;
        }
        if (lane == 31) wsum[wid] = x;
        __syncthreads();
        if (wid == 0) {
            int w = wsum[lane];
            int xs = w;
            #pragma unroll
            for (int o = 1; o < 32; o <<= 1) {
                int y = __shfl_up_sync(0xffffffffu, xs, o);
                if (lane >= o) xs += y;
            }
            wsum[lane] = xs - w;
        }
        __syncthreads();
        int excl = s_off + wsum[wid] + x - v;
        if (i < n) { g_ptr[i] = excl; g_fill[i] = excl; }
        __syncthreads();
        if (threadIdx.x == 1023) s_off += wsum[31] + x;
        __syncthreads();
    }
    if (threadIdx.x == 0) g_ptr[n] = s_off;
}
__global__ void scatter_triples_k(const int* __restrict__ triples, int ne) {
    int e = blockIdx.x * blockDim.x + threadIdx.x;
    if (e < ne) {
        int pos = atomicAdd(&g_fill[triples[3 * e]], 1);
        g_idx[pos] = e;
    }
}
__global__ void scatter_cols_k(const int* __restrict__ rows, const int* __restrict__ cols, int ne) {
    int e = blockIdx.x * blockDim.x + threadIdx.x;
    if (e < ne) {
        int pos = atomicAdd(&g_fill[rows[e]], 1);
        g_idx[pos] = cols[e];
    }
}
__global__ void attr_agg_k(const int* __restrict__ triples,
                           const float* __restrict__ ab_ptr,
                           const float* __restrict__ ent_feats) {
    int v = blockIdx.x;
    int t = threadIdx.x;
    int s = g_ptr[v], e = g_ptr[v + 1];
    __shared__ float sred[2];
    __shared__ float s_inv;
    __shared__ float sh_p[64];
    __shared__ int sh_att[64];
    __shared__ int sh_val[64];
    float ab = ab_ptr[0];
    float ed = g_entdot[v];
    float part = 0.f;
    for (int i = s + t; i < e; i += 64) {
        int tt = g_idx[i];
        float sc = ed + g_attdot[triples[3 * tt + 2]] + ab;
        sc = sc > 0.f ? sc : 0.2f * sc;
        part += expf(sc);
    }
    for (int o = 16; o; o >>= 1) part += __shfl_xor_sync(0xffffffffu, part, o);
    if ((t & 31) == 0) sred[t >> 5] = part;
    __syncthreads();
    if (t == 0) {
        float rs = sred[0] + sred[1];
        s_inv = (rs > 0.f) ? 1.f / rs : 0.f;
    }
    __syncthreads();
    float inv_rs = s_inv;
    float4 acc = make_float4(0.f, 0.f, 0.f, 0.f);
    for (int base = s; base < e; base += 64) {
        int cnt = min(64, e - base);
        if (t < cnt) {
            int tt = g_idx[base + t];
            int att = triples[3 * tt + 2];
            int val = triples[3 * tt + 1];
            sh_att[t] = att;
            sh_val[t] = val;
            float sc = ed + g_attdot[att] + ab;
            sc = sc > 0.f ? sc : 0.2f * sc;
            sh_p[t] = expf(sc) * inv_rs;
        }
        __syncthreads();
        for (int j = 0; j < cnt; j++) {
            float p = sh_p[j];
            const float4 aw = *(const float4*)&g_attW[(size_t)sh_att[j] * DIM + t * 4];
            const float4 vw = *(const float4*)&g_valW[(size_t)sh_val[j] * DIM + t * 4];
            acc.x += p * (aw.x + vw.x);
            acc.y += p * (aw.y + vw.y);
            acc.z += p * (aw.z + vw.z);
            acc.w += p * (aw.w + vw.w);
        }
        __syncthreads();
    }
    const float4 ef = *(const float4*)&ent_feats[(size_t)v * DIM + t * 4];
    float4 x = make_float4(acc.x + ef.x, acc.y + ef.y, acc.z + ef.z, acc.w + ef.w);
    x.x = x.x > 0.f ? x.x : expm1f(x.x);
    x.y = x.y > 0.f ? x.y : expm1f(x.y);
    x.z = x.z > 0.f ? x.z : expm1f(x.z);
    x.w = x.w > 0.f ? x.w : expm1f(x.w);
    *(float4*)&g_F1[(size_t)v * DIM + t * 4] = x;
}
// GCN mean-aggregation, fused fp32->bf16 hi/lo split of the result
__global__ void gcn_agg_split_k(const float* __restrict__ feats,
                                __nv_bfloat16* __restrict__ hi,
                                __nv_bfloat16* __restrict__ lo) {
    int v = blockIdx.x;
    int t = threadIdx.x;
    int s = g_ptr[v], e = g_ptr[v + 1];
    __shared__ int sh_c[64];
    float4 acc = make_float4(0.f, 0.f, 0.f, 0.f);
    for (int base = s; base < e; base += 64) {
        int cnt = min(64, e - base);
        if (t < cnt) sh_c[t] = g_idx[base + t];
        __syncthreads();
        for (int j = 0; j < cnt; j++) {
            const float4 f = *(const float4*)&feats[(size_t)sh_c[j] * DIM + t * 4];
            acc.x += f.x; acc.y += f.y; acc.z += f.z; acc.w += f.w;
        }
        __syncthreads();
    }
    float inv = (e > s) ? 1.f / (float)(e - s) : 0.f;
    float vals[4] = {acc.x * inv, acc.y * inv, acc.z * inv, acc.w * inv};
    __nv_bfloat16 hv[4], lv[4];
    #pragma unroll
    for (int j = 0; j < 4; j++) {
        hv[j] = __float2bfloat16(vals[j]);
        lv[j] = __float2bfloat16(vals[j] - __bfloat162float(hv[j]));
    }
    *(uint2*)&hi[(size_t)v * DIM + t * 4] = *(uint2*)hv;
    *(uint2*)&lo[(size_t)v * DIM + t * 4] = *(uint2*)lv;
}
__global__ void l2norm_k(const float* __restrict__ in, float* __restrict__ out) {
    int v = blockIdx.x;
    int t = threadIdx.x;
    __shared__ float sred[2];
    __shared__ float s_inv;
    const float4 x = *(const float4*)&in[(size_t)v * DIM + t * 4];
    float sq = x.x * x.x + x.y * x.y + x.z * x.z + x.w * x.w;
    for (int o = 16; o; o >>= 1) sq += __shfl_xor_sync(0xffffffffu, sq, o);
    if ((t & 31) == 0) sred[t >> 5] = sq;
    __syncthreads();
    if (t == 0) {
        float nrm = sqrtf(sred[0] + sred[1]);
        s_inv = 1.f / fmaxf(nrm, 1e-12f);
    }
    __syncthreads();
    float inv = s_inv;
    float4 y = make_float4(x.x * inv, x.y * inv, x.z * inv, x.w * inv);
    *(float4*)&out[(size_t)v * DIM + t * 4] = y;
}
__global__ void gather_k(const int* __restrict__ seed, const float* __restrict__ src,
                         float* __restrict__ dst) {
    int i = blockIdx.x;
    int t = threadIdx.x;
    *(float4*)&dst[(size_t)i * DIM + t * 4] =
        *(const float4*)&src[(size_t)seed[i] * DIM + t * 4];
}

// ---------------- host orchestration ----------------
static inline int ceildiv(int a, int b) { return (a + b - 1) / b; }

extern "C" void kernel_launch(void* const* d_in, const int* in_sizes, int n_in,
                              void* d_out, int out_size) {
    const int* seed_sr = (const int*)d_in[0];
    const int* seed_tg = (const int*)d_in[1];
    const int* tri_sr  = (const int*)d_in[2];
    const int* tri_tg  = (const int*)d_in[3];
    const int* rows_sr = (const int*)d_in[4];
    const int* cols_sr = (const int*)d_in[5];
    const int* rows_tg = (const int*)d_in[6];
    const int* cols_tg = (const int*)d_in[7];
    const float* att_feats = (const float*)d_in[8];
    const float* val_feats = (const float*)d_in[9];
    const float* ent_sr = (const float*)d_in[10];
    const float* ent_tg = (const float*)d_in[11];
    const float* a_w   = (const float*)d_in[12];
    const float* a_b   = (const float*)d_in[13];
    const float* W_enc = (const float*)d_in[14];
    const float* w1    = (const float*)d_in[15];
    const float* b1    = (const float*)d_in[16];
    const float* w2    = (const float*)d_in[17];
    const float* b2    = (const float*)d_in[18];
    (void)n_in; (void)out_size;

    const int nseed  = in_sizes[0];
    const int ne_tri = in_sizes[2] / 3;
    const int e_sr   = in_sizes[4];
    const int e_tg   = in_sizes[6];
    const int natt   = in_sizes[8] / DIM;
    const int nval   = in_sizes[9] / 300;
    const int n_sr   = in_sizes[10] / DIM;
    const int n_tg   = in_sizes[11] / DIM;

    float* valW;  cudaGetSymbolAddress((void**)&valW,  g_valW);
    float* F1;    cudaGetSymbolAddress((void**)&F1,    g_F1);
    float* F2;    cudaGetSymbolAddress((void**)&F2,    g_F2);
    int*   cntp;  cudaGetSymbolAddress((void**)&cntp,  g_cnt);
    __nv_bfloat16 *aH, *aL, *wetH, *wetL, *w1tH, *w1tL, *w2tH, *w2tL;
    cudaGetSymbolAddress((void**)&aH, g_a_h);
    cudaGetSymbolAddress((void**)&aL, g_a_l);
    cudaGetSymbolAddress((void**)&wetH, g_wet_h);
    cudaGetSymbolAddress((void**)&wetL, g_wet_l);
    cudaGetSymbolAddress((void**)&w1tH, g_w1t_h);
    cudaGetSymbolAddress((void**)&w1tL, g_w1t_l);
    cudaGetSymbolAddress((void**)&w2tH, g_w2t_h);
    cudaGetSymbolAddress((void**)&w2tL, g_w2t_l);

    float* out = (float*)d_out;
    float* out_fs_seed = out;
    float* out_ft_seed = out + (size_t)nseed * DIM;
    float* out_fs      = out + (size_t)2 * nseed * DIM;
    float* out_ft      = out_fs + (size_t)n_sr * DIM;

    // ---- shared precompute (launch #5 = valW HMMA GEMM, profiled by ncu) ----
    att_k<<<natt, DIM>>>(att_feats, W_enc, a_w, natt);                                     // 0
    tsplit_k<<<ceildiv(256 * KPAD_VAL, 256), 256>>>(W_enc + (size_t)DIM * DIM, 300,
                                                    KPAD_VAL, wetH, wetL);                 // 1
    tsplit_k<<<ceildiv(256 * 256, 256), 256>>>(w1, 256, 256, w1tH, w1tL);                  // 2
    tsplit_k<<<ceildiv(256 * 256, 256), 256>>>(w2, 256, 256, w2tH, w2tL);                  // 3
    {
        long long tot = (long long)nval * KPAD_VAL;
        split_pad_k<<<(int)((tot + 255) / 256), 256>>>(val_feats, nval, 300, KPAD_VAL,
                                                       aH, aL);                            // 4
        dim3 grid(2, ceildiv(nval, 128));
        mma_gemm_k<0><<<grid, 256>>>(aH, aL, wetH, wetL, nval, KPAD_VAL,
                                     nullptr, nullptr, valW);                              // 5
    }

    for (int side = 0; side < 2; side++) {
        const int n = side ? n_tg : n_sr;
        const int E = side ? e_tg : e_sr;
        const int* tri  = side ? tri_tg  : tri_sr;
        const int* rows = side ? rows_tg : rows_sr;
        const int* cols = side ? cols_tg : cols_sr;
        const float* ent = side ? ent_tg : ent_sr;
        const int* seed = side ? seed_tg : seed_sr;
        float* out_full = side ? out_ft : out_fs;
        float* out_seed = side ? out_ft_seed : out_fs_seed;

        entdot2_k<<<ceildiv(n * 32, 256), 256>>>(ent, a_w, n);
        zero_int_k<<<ceildiv(n, 256), 256>>>(cntp, n);
        hist_triples_k<<<ceildiv(ne_tri, 256), 256>>>(tri, ne_tri);
        scan_k<<<1, 1024>>>(n);
        scatter_triples_k<<<ceildiv(ne_tri, 256), 256>>>(tri, ne_tri);
        attr_agg_k<<<n, 64>>>(tri, a_b, ent);

        zero_int_k<<<ceildiv(n, 256), 256>>>(cntp, n);
        hist_rows_k<<<ceildiv(E, 256), 256>>>(rows, E);
        scan_k<<<1, 1024>>>(n);
        scatter_cols_k<<<ceildiv(E, 256), 256>>>(rows, cols, E);

        dim3 ggrid(2, ceildiv(n, 128));
        // GCN layer 1: F2 = F1 + relu((agg(F1)/deg) @ w1 + b1)
        gcn_agg_split_k<<<n, 64>>>(F1, aH, aL);
        mma_gemm_k<1><<<ggrid, 256>>>(aH, aL, w1tH, w1tL, n, 256, b1, F1, F2);
        // GCN layer 2: F1 = F2 + ((agg(F2)/deg) @ w2 + b2)
        gcn_agg_split_k<<<n, 64>>>(F2, aH, aL);
        mma_gemm_k<2><<<ggrid, 256>>>(aH, aL, w2tH, w2tL, n, 256, b2, F2, F1);

        l2norm_k<<<n, 64>>>(F1, out_full);
        gather_k<<<nseed, 64>>>(seed, out_full, out_seed);
    }
}

// round 5
// speedup vs baseline: 2.4636x; 1.1711x over previous
#include <cuda_runtime.h>
#include <cuda_bf16.h>
#include <math.h>
#include <stdint.h>

#define DIM 256
#define NMAX 50000
#define EMAX 860000
#define NVALMAX 100000
#define NATTMAX 1001
#define KPAD_VAL 320
#define MT_S 40   // smem row stride in bf16 (80B): conflict-free fragment LDS

// ---------------- scratch (static device globals; no allocation) ----------------
__device__ float g_valW[NVALMAX * DIM];
__device__ float g_attW[NATTMAX * DIM];
__device__ float g_attdot[NATTMAX];
__device__ float g_entdot[NMAX];
__device__ int   g_cnt[NMAX];
__device__ int   g_ptr[NMAX + 1];
__device__ int   g_fill[NMAX];
__device__ int   g_idx[EMAX];
__device__ int   g_bsum[128];
__device__ int   g_boff[128];
__device__ float g_F1[NMAX * DIM];
__device__ float g_F2[NMAX * DIM];
__device__ float g_X[NMAX * DIM];
// bf16 hi/lo split weights (B operands)
__device__ __nv_bfloat16 g_wet_h[DIM * KPAD_VAL];
__device__ __nv_bfloat16 g_wet_l[DIM * KPAD_VAL];
__device__ __nv_bfloat16 g_w1t_h[DIM * DIM];
__device__ __nv_bfloat16 g_w1t_l[DIM * DIM];
__device__ __nv_bfloat16 g_w2t_h[DIM * DIM];
__device__ __nv_bfloat16 g_w2t_l[DIM * DIM];

// ---------------- mma.sync wrapper (bf16, fp32 accum; compute_103-safe) ----------------
__device__ __forceinline__ void mma16816(float* c, const uint32_t* a, const uint32_t* b) {
    asm volatile(
        "mma.sync.aligned.m16n8k16.row.col.f32.bf16.bf16.f32 "
        "{%0,%1,%2,%3}, {%4,%5,%6,%7}, {%8,%9}, {%0,%1,%2,%3};"
        : "+f"(c[0]), "+f"(c[1]), "+f"(c[2]), "+f"(c[3])
        : "r"(a[0]), "r"(a[1]), "r"(a[2]), "r"(a[3]), "r"(b[0]), "r"(b[1]));
}

// ---------------- HMMA GEMM v2: C[M,256] = A_f32[M,K] @ (Bh+Bl)[256,Kpad]^T ----------
// A is fp32, converted to bf16 hi/lo in-register (split GEMM: AhBh + AlBh + AhBl).
// MODE 0: C = AB ; MODE 1: C = res + relu(AB+bias) ; MODE 2: C = res + AB + bias
template <int MODE>
__global__ void __launch_bounds__(256, 2)
mma_gemm_k(const float* __restrict__ A, int K, int Kpad,
           const __nv_bfloat16* __restrict__ Bh, const __nv_bfloat16* __restrict__ Bl,
           int M,
           const float* __restrict__ bias, const float* __restrict__ res,
           float* __restrict__ C) {
    __shared__ __align__(16) __nv_bfloat16 sAh[128 * MT_S];
    __shared__ __align__(16) __nv_bfloat16 sAl[128 * MT_S];
    __shared__ __align__(16) __nv_bfloat16 sBh[128 * MT_S];
    __shared__ __align__(16) __nv_bfloat16 sBl[128 * MT_S];
    int tid = threadIdx.x;
    int wid = tid >> 5, lane = tid & 31;
    int wm = wid & 3;      // 4 warps over 128 rows
    int wn = wid >> 2;     // 2 warps over 128 cols
    int row0 = blockIdx.y * 128;
    int col0 = blockIdx.x * 128;

    float acc[2][8][4];
    #pragma unroll
    for (int mt = 0; mt < 2; mt++)
        #pragma unroll
        for (int nt = 0; nt < 8; nt++)
            #pragma unroll
            for (int q = 0; q < 4; q++) acc[mt][nt][q] = 0.f;

    int lr = tid >> 1;            // 0..127
    int seg = (tid & 1) * 16;     // k offset 0 or 16
    int gr = row0 + lr;
    bool arow_ok = gr < M;
    const float* Arow = A + (size_t)(arow_ok ? gr : 0) * K;
    const __nv_bfloat16* BhRow = Bh + (size_t)(col0 + lr) * Kpad;
    const __nv_bfloat16* BlRow = Bl + (size_t)(col0 + lr) * Kpad;

    float aF[16];
    uint4 bh[2], bl[2];

    auto loadChunk = [&](int k0) {
        #pragma unroll
        for (int j = 0; j < 4; j++) {
            int gk = k0 + seg + j * 4;
            float4 v = make_float4(0.f, 0.f, 0.f, 0.f);
            if (arow_ok && gk < K) v = *(const float4*)(Arow + gk);
            aF[j * 4 + 0] = v.x; aF[j * 4 + 1] = v.y;
            aF[j * 4 + 2] = v.z; aF[j * 4 + 3] = v.w;
        }
        bh[0] = *(const uint4*)(BhRow + k0 + seg);
        bh[1] = *(const uint4*)(BhRow + k0 + seg + 8);
        bl[0] = *(const uint4*)(BlRow + k0 + seg);
        bl[1] = *(const uint4*)(BlRow + k0 + seg + 8);
    };
    auto storeChunk = [&]() {
        __nv_bfloat16 h[16], l[16];
        #pragma unroll
        for (int j = 0; j < 16; j++) {
            h[j] = __float2bfloat16(aF[j]);
            l[j] = __float2bfloat16(aF[j] - __bfloat162float(h[j]));
        }
        *(uint4*)&sAh[lr * MT_S + seg]     = ((const uint4*)h)[0];
        *(uint4*)&sAh[lr * MT_S + seg + 8] = ((const uint4*)h)[1];
        *(uint4*)&sAl[lr * MT_S + seg]     = ((const uint4*)l)[0];
        *(uint4*)&sAl[lr * MT_S + seg + 8] = ((const uint4*)l)[1];
        *(uint4*)&sBh[lr * MT_S + seg]     = bh[0];
        *(uint4*)&sBh[lr * MT_S + seg + 8] = bh[1];
        *(uint4*)&sBl[lr * MT_S + seg]     = bl[0];
        *(uint4*)&sBl[lr * MT_S + seg + 8] = bl[1];
    };

    int nch = Kpad / 32;
    loadChunk(0);
    for (int ci = 0; ci < nch; ci++) {
        storeChunk();
        __syncthreads();
        if (ci + 1 < nch) loadChunk((ci + 1) * 32);   // prefetch overlaps MMA below
        #pragma unroll
        for (int ks = 0; ks < 2; ks++) {
            int acol = ks * 16 + (lane & 3) * 2;
            uint32_t aH[2][4], aL[2][4];
            #pragma unroll
            for (int mt = 0; mt < 2; mt++) {
                int rb = (wm * 32 + mt * 16 + (lane >> 2)) * MT_S + acol;
                aH[mt][0] = *(const uint32_t*)&sAh[rb];
                aH[mt][1] = *(const uint32_t*)&sAh[rb + 8 * MT_S];
                aH[mt][2] = *(const uint32_t*)&sAh[rb + 8];
                aH[mt][3] = *(const uint32_t*)&sAh[rb + 8 * MT_S + 8];
                aL[mt][0] = *(const uint32_t*)&sAl[rb];
                aL[mt][1] = *(const uint32_t*)&sAl[rb + 8 * MT_S];
                aL[mt][2] = *(const uint32_t*)&sAl[rb + 8];
                aL[mt][3] = *(const uint32_t*)&sAl[rb + 8 * MT_S + 8];
            }
            #pragma unroll
            for (int nt = 0; nt < 8; nt++) {
                int nb = (wn * 64 + nt * 8 + (lane >> 2)) * MT_S + acol;
                uint32_t bH[2], bL[2];
                bH[0] = *(const uint32_t*)&sBh[nb];
                bH[1] = *(const uint32_t*)&sBh[nb + 8];
                bL[0] = *(const uint32_t*)&sBl[nb];
                bL[1] = *(const uint32_t*)&sBl[nb + 8];
                #pragma unroll
                for (int mt = 0; mt < 2; mt++) {
                    mma16816(acc[mt][nt], aH[mt], bH);
                    mma16816(acc[mt][nt], aL[mt], bH);
                    mma16816(acc[mt][nt], aH[mt], bL);
                }
            }
        }
        __syncthreads();
    }

    #pragma unroll
    for (int mt = 0; mt < 2; mt++) {
        #pragma unroll
        for (int half = 0; half < 2; half++) {
            int r = row0 + wm * 32 + mt * 16 + (lane >> 2) + half * 8;
            if (r >= M) continue;
            #pragma unroll
            for (int nt = 0; nt < 8; nt++) {
                int c = col0 + wn * 64 + nt * 8 + (lane & 3) * 2;
                float2 v;
                v.x = acc[mt][nt][half * 2 + 0];
                v.y = acc[mt][nt][half * 2 + 1];
                if (MODE >= 1) {
                    const float2 bb = *(const float2*)&bias[c];
                    v.x += bb.x; v.y += bb.y;
                    if (MODE == 1) { v.x = fmaxf(v.x, 0.f); v.y = fmaxf(v.y, 0.f); }
                    const float2 rr = *(const float2*)&res[(size_t)r * 256 + c];
                    v.x += rr.x; v.y += rr.y;
                }
                *(float2*)&C[(size_t)r * 256 + c] = v;
            }
        }
    }
}

// ---------------- weight transpose + hi/lo split ----------------
__global__ void tsplit_k(const float* __restrict__ src, int K, int Kpad,
                         __nv_bfloat16* __restrict__ hi, __nv_bfloat16* __restrict__ lo) {
    int idx = blockIdx.x * blockDim.x + threadIdx.x;
    if (idx >= 256 * Kpad) return;
    int k = idx % Kpad;
    int n = idx / Kpad;
    float v = (k < K) ? src[(size_t)k * 256 + n] : 0.f;
    __nv_bfloat16 h = __float2bfloat16(v);
    hi[idx] = h;
    lo[idx] = __float2bfloat16(v - __bfloat162float(h));
}

// ---------------- SIMT pipeline kernels ----------------
__global__ void zero_int_k(int* p, int n) {
    int i = blockIdx.x * blockDim.x + threadIdx.x;
    if (i < n) p[i] = 0;
}
__global__ void att_k(const float* __restrict__ att_feats,
                      const float* __restrict__ W_enc,
                      const float* __restrict__ a_w, int natt) {
    int r = blockIdx.x;
    int d = threadIdx.x;
    __shared__ float sh[DIM];
    __shared__ float sred[8];
    sh[d] = att_feats[(size_t)r * DIM + d];
    __syncthreads();
    float acc = 0.f;
    #pragma unroll 8
    for (int k = 0; k < DIM; k++) acc += sh[k] * W_enc[(size_t)k * DIM + d];
    g_attW[(size_t)r * DIM + d] = acc;
    float v = sh[d] * a_w[DIM + d];
    for (int o = 16; o; o >>= 1) v += __shfl_xor_sync(0xffffffffu, v, o);
    if ((d & 31) == 0) sred[d >> 5] = v;
    __syncthreads();
    if (d == 0) {
        float s = 0.f;
        #pragma unroll
        for (int i = 0; i < 8; i++) s += sred[i];
        g_attdot[r] = s;
    }
}
__global__ void entdot2_k(const float* __restrict__ ent, const float* __restrict__ a_w, int n) {
    int warp = (blockIdx.x * blockDim.x + threadIdx.x) >> 5;
    int lane = threadIdx.x & 31;
    if (warp >= n) return;
    const float* row = ent + (size_t)warp * DIM;
    float s = 0.f;
    #pragma unroll
    for (int d = lane; d < DIM; d += 32) s += row[d] * a_w[d];
    for (int o = 16; o; o >>= 1) s += __shfl_xor_sync(0xffffffffu, s, o);
    if (lane == 0) g_entdot[warp] = s;
}
__global__ void hist_triples_k(const int* __restrict__ triples, int ne) {
    int e = blockIdx.x * blockDim.x + threadIdx.x;
    if (e < ne) atomicAdd(&g_cnt[triples[3 * e]], 1);
}
__global__ void hist_rows_k(const int* __restrict__ rows, int ne) {
    int e = blockIdx.x * blockDim.x + threadIdx.x;
    if (e < ne) atomicAdd(&g_cnt[rows[e]], 1);
}
// ---- multi-block scan: blk-local excl scan -> mid-scan of block sums -> add offsets ----
__global__ void scan_blk_k(int n) {
    __shared__ int wsum[32];
    int b = blockIdx.x;
    int i = b * 1024 + threadIdx.x;
    int lane = threadIdx.x & 31, wid = threadIdx.x >> 5;
    int v = (i < n) ? g_cnt[i] : 0;
    int x = v;
    #pragma unroll
    for (int o = 1; o < 32; o <<= 1) {
        int y = __shfl_up_sync(0xffffffffu, x, o);
        if (lane >= o) x += y;
    }
    if (lane == 31) wsum[wid] = x;
    __syncthreads();
    if (wid == 0) {
        int w = wsum[lane];
        int xs = w;
        #pragma unroll
        for (int o = 1; o < 32; o <<= 1) {
            int y = __shfl_up_sync(0xffffffffu, xs, o);
            if (lane >= o) xs += y;
        }
        wsum[lane] = xs - w;
    }
    __syncthreads();
    int excl = wsum[wid] + x - v;
    if (i < n) g_ptr[i] = excl;
    if (threadIdx.x == 1023) g_bsum[b] = excl + v;
}
__global__ void scan_mid_k(int nb, int n) {
    int lane = threadIdx.x;  // 32 threads
    int carry = 0;
    for (int base = 0; base < nb; base += 32) {
        int i = base + lane;
        int v = (i < nb) ? g_bsum[i] : 0;
        int x = v;
        #pragma unroll
        for (int o = 1; o < 32; o <<= 1) {
            int y = __shfl_up_sync(0xffffffffu, x, o);
            if (lane >= o) x += y;
        }
        if (i < nb) g_boff[i] = carry + x - v;
        carry += __shfl_sync(0xffffffffu, x, 31);
    }
    if (lane == 0) g_ptr[n] = carry;
}
__global__ void scan_add_k(int n) {
    int i = blockIdx.x * blockDim.x + threadIdx.x;
    if (i < n) {
        int p = g_ptr[i] + g_boff[i >> 10];
        g_ptr[i] = p;
        g_fill[i] = p;
    }
}
__global__ void scatter_triples_k(const int* __restrict__ triples, int ne) {
    int e = blockIdx.x * blockDim.x + threadIdx.x;
    if (e < ne) {
        int pos = atomicAdd(&g_fill[triples[3 * e]], 1);
        g_idx[pos] = e;
    }
}
__global__ void scatter_cols_k(const int* __restrict__ rows, const int* __restrict__ cols, int ne) {
    int e = blockIdx.x * blockDim.x + threadIdx.x;
    if (e < ne) {
        int pos = atomicAdd(&g_fill[rows[e]], 1);
        g_idx[pos] = cols[e];
    }
}
__global__ void attr_agg_k(const int* __restrict__ triples,
                           const float* __restrict__ ab_ptr,
                           const float* __restrict__ ent_feats) {
    int v = blockIdx.x;
    int t = threadIdx.x;
    int s = g_ptr[v], e = g_ptr[v + 1];
    __shared__ float sred[2];
    __shared__ float s_inv;
    __shared__ float sh_p[64];
    __shared__ int sh_att[64];
    __shared__ int sh_val[64];
    float ab = ab_ptr[0];
    float ed = g_entdot[v];
    float part = 0.f;
    for (int i = s + t; i < e; i += 64) {
        int tt = g_idx[i];
        float sc = ed + g_attdot[triples[3 * tt + 2]] + ab;
        sc = sc > 0.f ? sc : 0.2f * sc;
        part += expf(sc);
    }
    for (int o = 16; o; o >>= 1) part += __shfl_xor_sync(0xffffffffu, part, o);
    if ((t & 31) == 0) sred[t >> 5] = part;
    __syncthreads();
    if (t == 0) {
        float rs = sred[0] + sred[1];
        s_inv = (rs > 0.f) ? 1.f / rs : 0.f;
    }
    __syncthreads();
    float inv_rs = s_inv;
    float4 acc = make_float4(0.f, 0.f, 0.f, 0.f);
    for (int base = s; base < e; base += 64) {
        int cnt = min(64, e - base);
        if (t < cnt) {
            int tt = g_idx[base + t];
            int att = triples[3 * tt + 2];
            int val = triples[3 * tt + 1];
            sh_att[t] = att;
            sh_val[t] = val;
            float sc = ed + g_attdot[att] + ab;
            sc = sc > 0.f ? sc : 0.2f * sc;
            sh_p[t] = expf(sc) * inv_rs;
        }
        __syncthreads();
        for (int j = 0; j < cnt; j++) {
            float p = sh_p[j];
            const float4 aw = *(const float4*)&g_attW[(size_t)sh_att[j] * DIM + t * 4];
            const float4 vw = *(const float4*)&g_valW[(size_t)sh_val[j] * DIM + t * 4];
            acc.x += p * (aw.x + vw.x);
            acc.y += p * (aw.y + vw.y);
            acc.z += p * (aw.z + vw.z);
            acc.w += p * (aw.w + vw.w);
        }
        __syncthreads();
    }
    const float4 ef = *(const float4*)&ent_feats[(size_t)v * DIM + t * 4];
    float4 x = make_float4(acc.x + ef.x, acc.y + ef.y, acc.z + ef.z, acc.w + ef.w);
    x.x = x.x > 0.f ? x.x : expm1f(x.x);
    x.y = x.y > 0.f ? x.y : expm1f(x.y);
    x.z = x.z > 0.f ? x.z : expm1f(x.z);
    x.w = x.w > 0.f ? x.w : expm1f(x.w);
    *(float4*)&g_F1[(size_t)v * DIM + t * 4] = x;
}
__global__ void gcn_agg_k(const float* __restrict__ feats, float* __restrict__ X) {
    int v = blockIdx.x;
    int t = threadIdx.x;
    int s = g_ptr[v], e = g_ptr[v + 1];
    __shared__ int sh_c[64];
    float4 acc = make_float4(0.f, 0.f, 0.f, 0.f);
    for (int base = s; base < e; base += 64) {
        int cnt = min(64, e - base);
        if (t < cnt) sh_c[t] = g_idx[base + t];
        __syncthreads();
        for (int j = 0; j < cnt; j++) {
            const float4 f = *(const float4*)&feats[(size_t)sh_c[j] * DIM + t * 4];
            acc.x += f.x; acc.y += f.y; acc.z += f.z; acc.w += f.w;
        }
        __syncthreads();
    }
    float inv = (e > s) ? 1.f / (float)(e - s) : 0.f;
    acc.x *= inv; acc.y *= inv; acc.z *= inv; acc.w *= inv;
    *(float4*)&X[(size_t)v * DIM + t * 4] = acc;
}
__global__ void l2norm_k(const float* __restrict__ in, float* __restrict__ out) {
    int v = blockIdx.x;
    int t = threadIdx.x;
    __shared__ float sred[2];
    __shared__ float s_inv;
    const float4 x = *(const float4*)&in[(size_t)v * DIM + t * 4];
    float sq = x.x * x.x + x.y * x.y + x.z * x.z + x.w * x.w;
    for (int o = 16; o; o >>= 1) sq += __shfl_xor_sync(0xffffffffu, sq, o);
    if ((t & 31) == 0) sred[t >> 5] = sq;
    __syncthreads();
    if (t == 0) {
        float nrm = sqrtf(sred[0] + sred[1]);
        s_inv = 1.f / fmaxf(nrm, 1e-12f);
    }
    __syncthreads();
    float inv = s_inv;
    float4 y = make_float4(x.x * inv, x.y * inv, x.z * inv, x.w * inv);
    *(float4*)&out[(size_t)v * DIM + t * 4] = y;
}
__global__ void gather_k(const int* __restrict__ seed, const float* __restrict__ src,
                         float* __restrict__ dst) {
    int i = blockIdx.x;
    int t = threadIdx.x;
    *(float4*)&dst[(size_t)i * DIM + t * 4] =
        *(const float4*)&src[(size_t)seed[i] * DIM + t * 4];
}

// ---------------- host orchestration ----------------
static inline int ceildiv(int a, int b) { return (a + b - 1) / b; }

extern "C" void kernel_launch(void* const* d_in, const int* in_sizes, int n_in,
                              void* d_out, int out_size) {
    const int* seed_sr = (const int*)d_in[0];
    const int* seed_tg = (const int*)d_in[1];
    const int* tri_sr  = (const int*)d_in[2];
    const int* tri_tg  = (const int*)d_in[3];
    const int* rows_sr = (const int*)d_in[4];
    const int* cols_sr = (const int*)d_in[5];
    const int* rows_tg = (const int*)d_in[6];
    const int* cols_tg = (const int*)d_in[7];
    const float* att_feats = (const float*)d_in[8];
    const float* val_feats = (const float*)d_in[9];
    const float* ent_sr = (const float*)d_in[10];
    const float* ent_tg = (const float*)d_in[11];
    const float* a_w   = (const float*)d_in[12];
    const float* a_b   = (const float*)d_in[13];
    const float* W_enc = (const float*)d_in[14];
    const float* w1    = (const float*)d_in[15];
    const float* b1    = (const float*)d_in[16];
    const float* w2    = (const float*)d_in[17];
    const float* b2    = (const float*)d_in[18];
    (void)n_in; (void)out_size;

    const int nseed  = in_sizes[0];
    const int ne_tri = in_sizes[2] / 3;
    const int e_sr   = in_sizes[4];
    const int e_tg   = in_sizes[6];
    const int natt   = in_sizes[8] / DIM;
    const int nval   = in_sizes[9] / 300;
    const int n_sr   = in_sizes[10] / DIM;
    const int n_tg   = in_sizes[11] / DIM;

    float* valW;  cudaGetSymbolAddress((void**)&valW,  g_valW);
    float* F1;    cudaGetSymbolAddress((void**)&F1,    g_F1);
    float* F2;    cudaGetSymbolAddress((void**)&F2,    g_F2);
    float* Xb;    cudaGetSymbolAddress((void**)&Xb,    g_X);
    int*   cntp;  cudaGetSymbolAddress((void**)&cntp,  g_cnt);
    __nv_bfloat16 *wetH, *wetL, *w1tH, *w1tL, *w2tH, *w2tL;
    cudaGetSymbolAddress((void**)&wetH, g_wet_h);
    cudaGetSymbolAddress((void**)&wetL, g_wet_l);
    cudaGetSymbolAddress((void**)&w1tH, g_w1t_h);
    cudaGetSymbolAddress((void**)&w1tL, g_w1t_l);
    cudaGetSymbolAddress((void**)&w2tH, g_w2t_h);
    cudaGetSymbolAddress((void**)&w2tL, g_w2t_l);

    float* out = (float*)d_out;
    float* out_fs_seed = out;
    float* out_ft_seed = out + (size_t)nseed * DIM;
    float* out_fs      = out + (size_t)2 * nseed * DIM;
    float* out_ft      = out_fs + (size_t)n_sr * DIM;

    // ---- shared precompute (launch #5 = valW HMMA GEMM, profiled by ncu) ----
    att_k<<<natt, DIM>>>(att_feats, W_enc, a_w, natt);                                   // 0
    tsplit_k<<<ceildiv(256 * KPAD_VAL, 256), 256>>>(W_enc + (size_t)DIM * DIM, 300,
                                                    KPAD_VAL, wetH, wetL);               // 1
    tsplit_k<<<ceildiv(256 * 256, 256), 256>>>(w1, 256, 256, w1tH, w1tL);                // 2
    tsplit_k<<<ceildiv(256 * 256, 256), 256>>>(w2, 256, 256, w2tH, w2tL);                // 3
    entdot2_k<<<ceildiv(n_sr * 32, 256), 256>>>(ent_sr, a_w, n_sr);                      // 4
    {
        dim3 grid(2, ceildiv(nval, 128));
        mma_gemm_k<0><<<grid, 256>>>(val_feats, 300, KPAD_VAL, wetH, wetL, nval,
                                     nullptr, nullptr, valW);                            // 5
    }

    for (int side = 0; side < 2; side++) {
        const int n = side ? n_tg : n_sr;
        const int E = side ? e_tg : e_sr;
        const int* tri  = side ? tri_tg  : tri_sr;
        const int* rows = side ? rows_tg : rows_sr;
        const int* cols = side ? cols_tg : cols_sr;
        const float* ent = side ? ent_tg : ent_sr;
        const int* seed = side ? seed_tg : seed_sr;
        float* out_full = side ? out_ft : out_fs;
        float* out_seed = side ? out_ft_seed : out_fs_seed;
        int nb = ceildiv(n, 1024);

        if (side == 1) entdot2_k<<<ceildiv(n * 32, 256), 256>>>(ent, a_w, n);

        // triple CSR
        zero_int_k<<<ceildiv(n, 256), 256>>>(cntp, n);
        hist_triples_k<<<ceildiv(ne_tri, 256), 256>>>(tri, ne_tri);
        scan_blk_k<<<nb, 1024>>>(n);
        scan_mid_k<<<1, 32>>>(nb, n);
        scan_add_k<<<ceildiv(n, 256), 256>>>(n);
        scatter_triples_k<<<ceildiv(ne_tri, 256), 256>>>(tri, ne_tri);
        attr_agg_k<<<n, 64>>>(tri, a_b, ent);

        // edge CSR
        zero_int_k<<<ceildiv(n, 256), 256>>>(cntp, n);
        hist_rows_k<<<ceildiv(E, 256), 256>>>(rows, E);
        scan_blk_k<<<nb, 1024>>>(n);
        scan_mid_k<<<1, 32>>>(nb, n);
        scan_add_k<<<ceildiv(n, 256), 256>>>(n);
        scatter_cols_k<<<ceildiv(E, 256), 256>>>(rows, cols, E);

        dim3 ggrid(2, ceildiv(n, 128));
        // GCN layer 1: F2 = F1 + relu((agg(F1)/deg) @ w1 + b1)
        gcn_agg_k<<<n, 64>>>(F1, Xb);
        mma_gemm_k<1><<<ggrid, 256>>>(Xb, 256, 256, w1tH, w1tL, n, b1, F1, F2);
        // GCN layer 2: F1 = F2 + ((agg(F2)/deg) @ w2 + b2)
        gcn_agg_k<<<n, 64>>>(F2, Xb);
        mma_gemm_k<2><<<ggrid, 256>>>(Xb, 256, 256, w2tH, w2tL, n, b2, F2, F1);

        l2norm_k<<<n, 64>>>(F1, out_full);
        gather_k<<<nseed, 64>>>(seed, out_full, out_seed);
    }
}

// round 6
// speedup vs baseline: 2.5466x; 1.0337x over previous
#include <cuda_runtime.h>
#include <cuda_bf16.h>
#include <math.h>
#include <stdint.h>

#define DIM 256
#define NMAX 50000
#define EMAX 860000
#define NVALMAX 100000
#define NATTMAX 1001
#define KPAD_VAL 320
#define MT_S 40   // smem row stride in bf16 (80B): conflict-free fragment LDS

// ---------------- scratch (static device globals; no allocation) ----------------
__device__ float g_valW[NVALMAX * DIM];
__device__ float g_attW[NATTMAX * DIM];
__device__ float g_attdot[NATTMAX];
__device__ float g_entdot[NMAX];
__device__ int   g_cnt[NMAX];
__device__ int   g_ptr[NMAX + 1];
__device__ int   g_fill[NMAX];
__device__ int   g_idx[EMAX];
__device__ int   g_bsum[128];
__device__ int   g_boff[128];
__device__ float g_F1[NMAX * DIM];
__device__ float g_F2[NMAX * DIM];
// pre-split bf16 hi/lo A operand (GCN agg output)
__device__ __nv_bfloat16 g_xa_h[NMAX * DIM];
__device__ __nv_bfloat16 g_xa_l[NMAX * DIM];
// bf16 hi/lo split weights (B operands)
__device__ __nv_bfloat16 g_wet_h[DIM * KPAD_VAL];
__device__ __nv_bfloat16 g_wet_l[DIM * KPAD_VAL];
__device__ __nv_bfloat16 g_w1t_h[DIM * DIM];
__device__ __nv_bfloat16 g_w1t_l[DIM * DIM];
__device__ __nv_bfloat16 g_w2t_h[DIM * DIM];
__device__ __nv_bfloat16 g_w2t_l[DIM * DIM];

// ---------------- mma.sync wrapper (bf16, fp32 accum; compute_103-safe) ----------------
__device__ __forceinline__ void mma16816(float* c, const uint32_t* a, const uint32_t* b) {
    asm volatile(
        "mma.sync.aligned.m16n8k16.row.col.f32.bf16.bf16.f32 "
        "{%0,%1,%2,%3}, {%4,%5,%6,%7}, {%8,%9}, {%0,%1,%2,%3};"
        : "+f"(c[0]), "+f"(c[1]), "+f"(c[2]), "+f"(c[3])
        : "r"(a[0]), "r"(a[1]), "r"(a[2]), "r"(a[3]), "r"(b[0]), "r"(b[1]));
}

// ---------------- HMMA GEMM: C[M,256] = A[M,K] @ (Bh+Bl)[256,Kpad]^T ----------
// PRE=0: A fp32 (converted in-register to hi/lo)  PRE=1: A pre-split bf16 hi/lo.
// Split GEMM: AhBh + AlBh + AhBl, fp32 accum.
// MODE 0: C = AB ; MODE 1: C = res + relu(AB+bias) ; MODE 2: C = res + AB + bias
template <int MODE, int PRE>
__global__ void __launch_bounds__(256, 2)
mma_gemm_k(const void* __restrict__ Ap, const void* __restrict__ Ap2, int K, int Kpad,
           const __nv_bfloat16* __restrict__ Bh, const __nv_bfloat16* __restrict__ Bl,
           int M,
           const float* __restrict__ bias, const float* __restrict__ res,
           float* __restrict__ C) {
    __shared__ __align__(16) __nv_bfloat16 sAh[128 * MT_S];
    __shared__ __align__(16) __nv_bfloat16 sAl[128 * MT_S];
    __shared__ __align__(16) __nv_bfloat16 sBh[128 * MT_S];
    __shared__ __align__(16) __nv_bfloat16 sBl[128 * MT_S];
    int tid = threadIdx.x;
    int wid = tid >> 5, lane = tid & 31;
    int wm = wid & 3;
    int wn = wid >> 2;
    int row0 = blockIdx.y * 128;
    int col0 = blockIdx.x * 128;

    float acc[2][8][4];
    #pragma unroll
    for (int mt = 0; mt < 2; mt++)
        #pragma unroll
        for (int nt = 0; nt < 8; nt++)
            #pragma unroll
            for (int q = 0; q < 4; q++) acc[mt][nt][q] = 0.f;

    int lr = tid >> 1;            // 0..127
    int seg = (tid & 1) * 16;     // k offset 0 or 16
    int gr = row0 + lr;
    bool arow_ok = gr < M;
    const float* Arow = (const float*)Ap + (size_t)(arow_ok ? gr : 0) * K;
    const __nv_bfloat16* AhRow = (const __nv_bfloat16*)Ap + (size_t)(arow_ok ? gr : 0) * Kpad;
    const __nv_bfloat16* AlRow = (const __nv_bfloat16*)Ap2 + (size_t)(arow_ok ? gr : 0) * Kpad;
    const __nv_bfloat16* BhRow = Bh + (size_t)(col0 + lr) * Kpad;
    const __nv_bfloat16* BlRow = Bl + (size_t)(col0 + lr) * Kpad;

    float aF[16];
    uint4 ah[2], al[2];
    uint4 bh[2], bl[2];

    auto loadChunk = [&](int k0) {
        if (PRE) {
            ah[0] = *(const uint4*)(AhRow + k0 + seg);
            ah[1] = *(const uint4*)(AhRow + k0 + seg + 8);
            al[0] = *(const uint4*)(AlRow + k0 + seg);
            al[1] = *(const uint4*)(AlRow + k0 + seg + 8);
        } else {
            #pragma unroll
            for (int j = 0; j < 4; j++) {
                int gk = k0 + seg + j * 4;
                float4 v = make_float4(0.f, 0.f, 0.f, 0.f);
                if (arow_ok && gk < K) v = *(const float4*)(Arow + gk);
                aF[j * 4 + 0] = v.x; aF[j * 4 + 1] = v.y;
                aF[j * 4 + 2] = v.z; aF[j * 4 + 3] = v.w;
            }
        }
        bh[0] = *(const uint4*)(BhRow + k0 + seg);
        bh[1] = *(const uint4*)(BhRow + k0 + seg + 8);
        bl[0] = *(const uint4*)(BlRow + k0 + seg);
        bl[1] = *(const uint4*)(BlRow + k0 + seg + 8);
    };
    auto storeChunk = [&]() {
        if (PRE) {
            *(uint4*)&sAh[lr * MT_S + seg]     = ah[0];
            *(uint4*)&sAh[lr * MT_S + seg + 8] = ah[1];
            *(uint4*)&sAl[lr * MT_S + seg]     = al[0];
            *(uint4*)&sAl[lr * MT_S + seg + 8] = al[1];
        } else {
            __nv_bfloat16 h[16], l[16];
            #pragma unroll
            for (int j = 0; j < 16; j++) {
                h[j] = __float2bfloat16(aF[j]);
                l[j] = __float2bfloat16(aF[j] - __bfloat162float(h[j]));
            }
            *(uint4*)&sAh[lr * MT_S + seg]     = ((const uint4*)h)[0];
            *(uint4*)&sAh[lr * MT_S + seg + 8] = ((const uint4*)h)[1];
            *(uint4*)&sAl[lr * MT_S + seg]     = ((const uint4*)l)[0];
            *(uint4*)&sAl[lr * MT_S + seg + 8] = ((const uint4*)l)[1];
        }
        *(uint4*)&sBh[lr * MT_S + seg]     = bh[0];
        *(uint4*)&sBh[lr * MT_S + seg + 8] = bh[1];
        *(uint4*)&sBl[lr * MT_S + seg]     = bl[0];
        *(uint4*)&sBl[lr * MT_S + seg + 8] = bl[1];
    };

    int nch = Kpad / 32;
    loadChunk(0);
    for (int ci = 0; ci < nch; ci++) {
        storeChunk();
        __syncthreads();
        if (ci + 1 < nch) loadChunk((ci + 1) * 32);
        #pragma unroll
        for (int ks = 0; ks < 2; ks++) {
            int acol = ks * 16 + (lane & 3) * 2;
            uint32_t aH[2][4], aL[2][4];
            #pragma unroll
            for (int mt = 0; mt < 2; mt++) {
                int rb = (wm * 32 + mt * 16 + (lane >> 2)) * MT_S + acol;
                aH[mt][0] = *(const uint32_t*)&sAh[rb];
                aH[mt][1] = *(const uint32_t*)&sAh[rb + 8 * MT_S];
                aH[mt][2] = *(const uint32_t*)&sAh[rb + 8];
                aH[mt][3] = *(const uint32_t*)&sAh[rb + 8 * MT_S + 8];
                aL[mt][0] = *(const uint32_t*)&sAl[rb];
                aL[mt][1] = *(const uint32_t*)&sAl[rb + 8 * MT_S];
                aL[mt][2] = *(const uint32_t*)&sAl[rb + 8];
                aL[mt][3] = *(const uint32_t*)&sAl[rb + 8 * MT_S + 8];
            }
            #pragma unroll
            for (int nt = 0; nt < 8; nt++) {
                int nb = (wn * 64 + nt * 8 + (lane >> 2)) * MT_S + acol;
                uint32_t bH[2], bL[2];
                bH[0] = *(const uint32_t*)&sBh[nb];
                bH[1] = *(const uint32_t*)&sBh[nb + 8];
                bL[0] = *(const uint32_t*)&sBl[nb];
                bL[1] = *(const uint32_t*)&sBl[nb + 8];
                #pragma unroll
                for (int mt = 0; mt < 2; mt++) {
                    mma16816(acc[mt][nt], aH[mt], bH);
                    mma16816(acc[mt][nt], aL[mt], bH);
                    mma16816(acc[mt][nt], aH[mt], bL);
                }
            }
        }
        __syncthreads();
    }

    #pragma unroll
    for (int mt = 0; mt < 2; mt++) {
        #pragma unroll
        for (int half = 0; half < 2; half++) {
            int r = row0 + wm * 32 + mt * 16 + (lane >> 2) + half * 8;
            if (r >= M) continue;
            #pragma unroll
            for (int nt = 0; nt < 8; nt++) {
                int c = col0 + wn * 64 + nt * 8 + (lane & 3) * 2;
                float2 v;
                v.x = acc[mt][nt][half * 2 + 0];
                v.y = acc[mt][nt][half * 2 + 1];
                if (MODE >= 1) {
                    const float2 bb = *(const float2*)&bias[c];
                    v.x += bb.x; v.y += bb.y;
                    if (MODE == 1) { v.x = fmaxf(v.x, 0.f); v.y = fmaxf(v.y, 0.f); }
                    const float2 rr = *(const float2*)&res[(size_t)r * 256 + c];
                    v.x += rr.x; v.y += rr.y;
                }
                *(float2*)&C[(size_t)r * 256 + c] = v;
            }
        }
    }
}

// ---------------- weight transpose + hi/lo split ----------------
__global__ void tsplit_k(const float* __restrict__ src, int K, int Kpad,
                         __nv_bfloat16* __restrict__ hi, __nv_bfloat16* __restrict__ lo) {
    int idx = blockIdx.x * blockDim.x + threadIdx.x;
    if (idx >= 256 * Kpad) return;
    int k = idx % Kpad;
    int n = idx / Kpad;
    float v = (k < K) ? src[(size_t)k * 256 + n] : 0.f;
    __nv_bfloat16 h = __float2bfloat16(v);
    hi[idx] = h;
    lo[idx] = __float2bfloat16(v - __bfloat162float(h));
}

// ---------------- SIMT pipeline kernels ----------------
__global__ void zero_int_k(int* p, int n) {
    int i = blockIdx.x * blockDim.x + threadIdx.x;
    if (i < n) p[i] = 0;
}
__global__ void att_k(const float* __restrict__ att_feats,
                      const float* __restrict__ W_enc,
                      const float* __restrict__ a_w, int natt) {
    int r = blockIdx.x;
    int d = threadIdx.x;
    __shared__ float sh[DIM];
    __shared__ float sred[8];
    sh[d] = att_feats[(size_t)r * DIM + d];
    __syncthreads();
    float acc = 0.f;
    #pragma unroll 8
    for (int k = 0; k < DIM; k++) acc += sh[k] * W_enc[(size_t)k * DIM + d];
    g_attW[(size_t)r * DIM + d] = acc;
    float v = sh[d] * a_w[DIM + d];
    for (int o = 16; o; o >>= 1) v += __shfl_xor_sync(0xffffffffu, v, o);
    if ((d & 31) == 0) sred[d >> 5] = v;
    __syncthreads();
    if (d == 0) {
        float s = 0.f;
        #pragma unroll
        for (int i = 0; i < 8; i++) s += sred[i];
        g_attdot[r] = s;
    }
}
__global__ void entdot2_k(const float* __restrict__ ent, const float* __restrict__ a_w, int n) {
    int warp = (blockIdx.x * blockDim.x + threadIdx.x) >> 5;
    int lane = threadIdx.x & 31;
    if (warp >= n) return;
    const float* row = ent + (size_t)warp * DIM;
    float s = 0.f;
    #pragma unroll
    for (int d = lane; d < DIM; d += 32) s += row[d] * a_w[d];
    for (int o = 16; o; o >>= 1) s += __shfl_xor_sync(0xffffffffu, s, o);
    if (lane == 0) g_entdot[warp] = s;
}
__global__ void hist_triples_k(const int* __restrict__ triples, int ne) {
    int e = blockIdx.x * blockDim.x + threadIdx.x;
    if (e < ne) atomicAdd(&g_cnt[triples[3 * e]], 1);
}
// ---- multi-block scan ----
__global__ void scan_blk_k(int n) {
    __shared__ int wsum[32];
    int b = blockIdx.x;
    int i = b * 1024 + threadIdx.x;
    int lane = threadIdx.x & 31, wid = threadIdx.x >> 5;
    int v = (i < n) ? g_cnt[i] : 0;
    int x = v;
    #pragma unroll
    for (int o = 1; o < 32; o <<= 1) {
        int y = __shfl_up_sync(0xffffffffu, x, o);
        if (lane >= o) x += y;
    }
    if (lane == 31) wsum[wid] = x;
    __syncthreads();
    if (wid == 0) {
        int w = wsum[lane];
        int xs = w;
        #pragma unroll
        for (int o = 1; o < 32; o <<= 1) {
            int y = __shfl_up_sync(0xffffffffu, xs, o);
            if (lane >= o) xs += y;
        }
        wsum[lane] = xs - w;
    }
    __syncthreads();
    int excl = wsum[wid] + x - v;
    if (i < n) g_ptr[i] = excl;
    if (threadIdx.x == 1023) g_bsum[b] = excl + v;
}
__global__ void scan_mid_k(int nb, int n) {
    int lane = threadIdx.x;
    int carry = 0;
    for (int base = 0; base < nb; base += 32) {
        int i = base + lane;
        int v = (i < nb) ? g_bsum[i] : 0;
        int x = v;
        #pragma unroll
        for (int o = 1; o < 32; o <<= 1) {
            int y = __shfl_up_sync(0xffffffffu, x, o);
            if (lane >= o) x += y;
        }
        if (i < nb) g_boff[i] = carry + x - v;
        carry += __shfl_sync(0xffffffffu, x, 31);
    }
    if (lane == 0) g_ptr[n] = carry;
}
__global__ void scan_add_k(int n) {
    int i = blockIdx.x * blockDim.x + threadIdx.x;
    if (i < n) {
        int p = g_ptr[i] + g_boff[i >> 10];
        g_ptr[i] = p;
        g_fill[i] = p;
    }
}
__global__ void scatter_triples_k(const int* __restrict__ triples, int ne) {
    int e = blockIdx.x * blockDim.x + threadIdx.x;
    if (e < ne) {
        int pos = atomicAdd(&g_fill[triples[3 * e]], 1);
        g_idx[pos] = e;
    }
}
// ---- edge CSR from SORTED rows (np.unique axis=0 sorts; self-loops => all rows present) ----
__global__ void edge_ptr_k(const int* __restrict__ rows, int E, int n) {
    int e = blockIdx.x * blockDim.x + threadIdx.x;
    if (e >= E) return;
    int r = rows[e];
    if (e == 0) {
        for (int v = 0; v <= r; v++) g_ptr[v] = 0;
    } else {
        int rp = rows[e - 1];
        for (int v = rp + 1; v <= r; v++) g_ptr[v] = e;
    }
    if (e == E - 1) {
        for (int v = r + 1; v <= n; v++) g_ptr[v] = E;
    }
}
__global__ void attr_agg_k(const int* __restrict__ triples,
                           const float* __restrict__ ab_ptr,
                           const float* __restrict__ ent_feats) {
    int v = blockIdx.x;
    int t = threadIdx.x;
    int s = g_ptr[v], e = g_ptr[v + 1];
    __shared__ float sred[2];
    __shared__ float s_inv;
    __shared__ float sh_p[64];
    __shared__ int sh_att[64];
    __shared__ int sh_val[64];
    float ab = ab_ptr[0];
    float ed = g_entdot[v];
    float part = 0.f;
    for (int i = s + t; i < e; i += 64) {
        int tt = g_idx[i];
        float sc = ed + g_attdot[triples[3 * tt + 2]] + ab;
        sc = sc > 0.f ? sc : 0.2f * sc;
        part += expf(sc);
    }
    for (int o = 16; o; o >>= 1) part += __shfl_xor_sync(0xffffffffu, part, o);
    if ((t & 31) == 0) sred[t >> 5] = part;
    __syncthreads();
    if (t == 0) {
        float rs = sred[0] + sred[1];
        s_inv = (rs > 0.f) ? 1.f / rs : 0.f;
    }
    __syncthreads();
    float inv_rs = s_inv;
    float4 acc = make_float4(0.f, 0.f, 0.f, 0.f);
    for (int base = s; base < e; base += 64) {
        int cnt = min(64, e - base);
        if (t < cnt) {
            int tt = g_idx[base + t];
            int att = triples[3 * tt + 2];
            int val = triples[3 * tt + 1];
            sh_att[t] = att;
            sh_val[t] = val;
            float sc = ed + g_attdot[att] + ab;
            sc = sc > 0.f ? sc : 0.2f * sc;
            sh_p[t] = expf(sc) * inv_rs;
        }
        __syncthreads();
        for (int j = 0; j < cnt; j++) {
            float p = sh_p[j];
            const float4 aw = *(const float4*)&g_attW[(size_t)sh_att[j] * DIM + t * 4];
            const float4 vw = *(const float4*)&g_valW[(size_t)sh_val[j] * DIM + t * 4];
            acc.x += p * (aw.x + vw.x);
            acc.y += p * (aw.y + vw.y);
            acc.z += p * (aw.z + vw.z);
            acc.w += p * (aw.w + vw.w);
        }
        __syncthreads();
    }
    const float4 ef = *(const float4*)&ent_feats[(size_t)v * DIM + t * 4];
    float4 x = make_float4(acc.x + ef.x, acc.y + ef.y, acc.z + ef.z, acc.w + ef.w);
    x.x = x.x > 0.f ? x.x : expm1f(x.x);
    x.y = x.y > 0.f ? x.y : expm1f(x.y);
    x.z = x.z > 0.f ? x.z : expm1f(x.z);
    x.w = x.w > 0.f ? x.w : expm1f(x.w);
    *(float4*)&g_F1[(size_t)v * DIM + t * 4] = x;
}
// GCN mean-agg straight from sorted cols; writes bf16 hi/lo split for the GEMM
__global__ void gcn_agg_split_k(const float* __restrict__ feats,
                                const int* __restrict__ cols,
                                __nv_bfloat16* __restrict__ hi,
                                __nv_bfloat16* __restrict__ lo) {
    int v = blockIdx.x;
    int t = threadIdx.x;
    int s = g_ptr[v], e = g_ptr[v + 1];
    __shared__ int sh_c[64];
    float4 acc = make_float4(0.f, 0.f, 0.f, 0.f);
    for (int base = s; base < e; base += 64) {
        int cnt = min(64, e - base);
        if (t < cnt) sh_c[t] = cols[base + t];
        __syncthreads();
        for (int j = 0; j < cnt; j++) {
            const float4 f = *(const float4*)&feats[(size_t)sh_c[j] * DIM + t * 4];
            acc.x += f.x; acc.y += f.y; acc.z += f.z; acc.w += f.w;
        }
        __syncthreads();
    }
    float inv = (e > s) ? 1.f / (float)(e - s) : 0.f;
    float vals[4] = {acc.x * inv, acc.y * inv, acc.z * inv, acc.w * inv};
    __nv_bfloat16 hv[4], lv[4];
    #pragma unroll
    for (int j = 0; j < 4; j++) {
        hv[j] = __float2bfloat16(vals[j]);
        lv[j] = __float2bfloat16(vals[j] - __bfloat162float(hv[j]));
    }
    *(uint2*)&hi[(size_t)v * DIM + t * 4] = *(uint2*)hv;
    *(uint2*)&lo[(size_t)v * DIM + t * 4] = *(uint2*)lv;
}
__global__ void l2norm_k(const float* __restrict__ in, float* __restrict__ out) {
    int v = blockIdx.x;
    int t = threadIdx.x;
    __shared__ float sred[2];
    __shared__ float s_inv;
    const float4 x = *(const float4*)&in[(size_t)v * DIM + t * 4];
    float sq = x.x * x.x + x.y * x.y + x.z * x.z + x.w * x.w;
    for (int o = 16; o; o >>= 1) sq += __shfl_xor_sync(0xffffffffu, sq, o);
    if ((t & 31) == 0) sred[t >> 5] = sq;
    __syncthreads();
    if (t == 0) {
        float nrm = sqrtf(sred[0] + sred[1]);
        s_inv = 1.f / fmaxf(nrm, 1e-12f);
    }
    __syncthreads();
    float inv = s_inv;
    float4 y = make_float4(x.x * inv, x.y * inv, x.z * inv, x.w * inv);
    *(float4*)&out[(size_t)v * DIM + t * 4] = y;
}
__global__ void gather_k(const int* __restrict__ seed, const float* __restrict__ src,
                         float* __restrict__ dst) {
    int i = blockIdx.x;
    int t = threadIdx.x;
    *(float4*)&dst[(size_t)i * DIM + t * 4] =
        *(const float4*)&src[(size_t)seed[i] * DIM + t * 4];
}

// ---------------- host orchestration ----------------
static inline int ceildiv(int a, int b) { return (a + b - 1) / b; }

extern "C" void kernel_launch(void* const* d_in, const int* in_sizes, int n_in,
                              void* d_out, int out_size) {
    const int* seed_sr = (const int*)d_in[0];
    const int* seed_tg = (const int*)d_in[1];
    const int* tri_sr  = (const int*)d_in[2];
    const int* tri_tg  = (const int*)d_in[3];
    const int* rows_sr = (const int*)d_in[4];
    const int* cols_sr = (const int*)d_in[5];
    const int* rows_tg = (const int*)d_in[6];
    const int* cols_tg = (const int*)d_in[7];
    const float* att_feats = (const float*)d_in[8];
    const float* val_feats = (const float*)d_in[9];
    const float* ent_sr = (const float*)d_in[10];
    const float* ent_tg = (const float*)d_in[11];
    const float* a_w   = (const float*)d_in[12];
    const float* a_b   = (const float*)d_in[13];
    const float* W_enc = (const float*)d_in[14];
    const float* w1    = (const float*)d_in[15];
    const float* b1    = (const float*)d_in[16];
    const float* w2    = (const float*)d_in[17];
    const float* b2    = (const float*)d_in[18];
    (void)n_in; (void)out_size;

    const int nseed  = in_sizes[0];
    const int ne_tri = in_sizes[2] / 3;
    const int e_sr   = in_sizes[4];
    const int e_tg   = in_sizes[6];
    const int natt   = in_sizes[8] / DIM;
    const int nval   = in_sizes[9] / 300;
    const int n_sr   = in_sizes[10] / DIM;
    const int n_tg   = in_sizes[11] / DIM;

    float* valW;  cudaGetSymbolAddress((void**)&valW,  g_valW);
    float* F1;    cudaGetSymbolAddress((void**)&F1,    g_F1);
    float* F2;    cudaGetSymbolAddress((void**)&F2,    g_F2);
    int*   cntp;  cudaGetSymbolAddress((void**)&cntp,  g_cnt);
    __nv_bfloat16 *xaH, *xaL, *wetH, *wetL, *w1tH, *w1tL, *w2tH, *w2tL;
    cudaGetSymbolAddress((void**)&xaH, g_xa_h);
    cudaGetSymbolAddress((void**)&xaL, g_xa_l);
    cudaGetSymbolAddress((void**)&wetH, g_wet_h);
    cudaGetSymbolAddress((void**)&wetL, g_wet_l);
    cudaGetSymbolAddress((void**)&w1tH, g_w1t_h);
    cudaGetSymbolAddress((void**)&w1tL, g_w1t_l);
    cudaGetSymbolAddress((void**)&w2tH, g_w2t_h);
    cudaGetSymbolAddress((void**)&w2tL, g_w2t_l);

    float* out = (float*)d_out;
    float* out_fs_seed = out;
    float* out_ft_seed = out + (size_t)nseed * DIM;
    float* out_fs      = out + (size_t)2 * nseed * DIM;
    float* out_ft      = out_fs + (size_t)n_sr * DIM;

    // ---- shared precompute ----
    att_k<<<natt, DIM>>>(att_feats, W_enc, a_w, natt);
    tsplit_k<<<ceildiv(256 * KPAD_VAL, 256), 256>>>(W_enc + (size_t)DIM * DIM, 300,
                                                    KPAD_VAL, wetH, wetL);
    tsplit_k<<<ceildiv(256 * 256, 256), 256>>>(w1, 256, 256, w1tH, w1tL);
    tsplit_k<<<ceildiv(256 * 256, 256), 256>>>(w2, 256, 256, w2tH, w2tL);
    entdot2_k<<<ceildiv(n_sr * 32, 256), 256>>>(ent_sr, a_w, n_sr);
    {
        dim3 grid(2, ceildiv(nval, 128));
        mma_gemm_k<0, 0><<<grid, 256>>>(val_feats, nullptr, 300, KPAD_VAL, wetH, wetL,
                                        nval, nullptr, nullptr, valW);
    }

    for (int side = 0; side < 2; side++) {
        const int n = side ? n_tg : n_sr;
        const int E = side ? e_tg : e_sr;
        const int* tri  = side ? tri_tg  : tri_sr;
        const int* rows = side ? rows_tg : rows_sr;
        const int* cols = side ? cols_tg : cols_sr;
        const float* ent = side ? ent_tg : ent_sr;
        const int* seed = side ? seed_tg : seed_sr;
        float* out_full = side ? out_ft : out_fs;
        float* out_seed = side ? out_ft_seed : out_fs_seed;
        int nb = ceildiv(n, 1024);

        if (side == 1) entdot2_k<<<ceildiv(n * 32, 256), 256>>>(ent, a_w, n);

        // triple CSR (unsorted heads -> histogram+scan+scatter)
        zero_int_k<<<ceildiv(n, 256), 256>>>(cntp, n);
        hist_triples_k<<<ceildiv(ne_tri, 256), 256>>>(tri, ne_tri);
        scan_blk_k<<<nb, 1024>>>(n);
        scan_mid_k<<<1, 32>>>(nb, n);
        scan_add_k<<<ceildiv(n, 256), 256>>>(n);
        scatter_triples_k<<<ceildiv(ne_tri, 256), 256>>>(tri, ne_tri);
        attr_agg_k<<<n, 64>>>(tri, a_b, ent);

        // edge CSR: rows are sorted (np.unique) -> just mark boundaries
        edge_ptr_k<<<ceildiv(E, 256), 256>>>(rows, E, n);

        dim3 ggrid(2, ceildiv(n, 128));
        // GCN layer 1: F2 = F1 + relu((agg(F1)/deg) @ w1 + b1)
        gcn_agg_split_k<<<n, 64>>>(F1, cols, xaH, xaL);
        mma_gemm_k<1, 1><<<ggrid, 256>>>(xaH, xaL, 256, 256, w1tH, w1tL, n, b1, F1, F2);
        // GCN layer 2: F1 = F2 + ((agg(F2)/deg) @ w2 + b2)
        gcn_agg_split_k<<<n, 64>>>(F2, cols, xaH, xaL);
        mma_gemm_k<2, 1><<<ggrid, 256>>>(xaH, xaL, 256, 256, w2tH, w2tL, n, b2, F2, F1);

        l2norm_k<<<n, 64>>>(F1, out_full);
        gather_k<<<nseed, 64>>>(seed, out_full, out_seed);
    }
}

// round 7
// speedup vs baseline: 2.6390x; 1.0363x over previous
#include <cuda_runtime.h>
#include <cuda_bf16.h>
#include <math.h>
#include <stdint.h>

#define DIM 256
#define NMAX 50000
#define NTOT 100000
#define ETRI 400000
#define NVALMAX 100000
#define NATTMAX 1001
#define KPAD_VAL 320
#define MT_S 40   // smem row stride in bf16 (80B): conflict-free fragment LDS

// ---------------- scratch (static device globals; no allocation) ----------------
__device__ float g_valW[NVALMAX * DIM];
__device__ float g_attW[NATTMAX * DIM];
__device__ float g_attdot[NATTMAX];
__device__ float g_entdot[NTOT];
__device__ int   g_cnt[NTOT];
__device__ int   g_ptr[NTOT + 1];    // triple CSR (stacked)
__device__ int   g_eptr[NTOT + 1];   // edge CSR (stacked)
__device__ int   g_fill[NTOT];
__device__ int   g_idx[ETRI];
__device__ int   g_bsum[128];
__device__ int   g_boff[128];
__device__ float g_F1[NTOT * DIM];
__device__ float g_F2[NTOT * DIM];
__device__ __nv_bfloat16 g_xa_h[NTOT * DIM];
__device__ __nv_bfloat16 g_xa_l[NTOT * DIM];
__device__ __nv_bfloat16 g_wet_h[DIM * KPAD_VAL];
__device__ __nv_bfloat16 g_wet_l[DIM * KPAD_VAL];
__device__ __nv_bfloat16 g_w1t_h[DIM * DIM];
__device__ __nv_bfloat16 g_w1t_l[DIM * DIM];
__device__ __nv_bfloat16 g_w2t_h[DIM * DIM];
__device__ __nv_bfloat16 g_w2t_l[DIM * DIM];

// ---------------- mma.sync wrapper ----------------
__device__ __forceinline__ void mma16816(float* c, const uint32_t* a, const uint32_t* b) {
    asm volatile(
        "mma.sync.aligned.m16n8k16.row.col.f32.bf16.bf16.f32 "
        "{%0,%1,%2,%3}, {%4,%5,%6,%7}, {%8,%9}, {%0,%1,%2,%3};"
        : "+f"(c[0]), "+f"(c[1]), "+f"(c[2]), "+f"(c[3])
        : "r"(a[0]), "r"(a[1]), "r"(a[2]), "r"(a[3]), "r"(b[0]), "r"(b[1]));
}

// ---------------- HMMA split GEMM (AhBh + AlBh + AhBl, fp32 accum) ----------------
// PRE=0: A fp32 converted in-register; PRE=1: A pre-split bf16 hi/lo.
// MODE 0: C = AB ; MODE 1: C = res + relu(AB+bias) ; MODE 2: C = res + AB + bias
template <int MODE, int PRE>
__global__ void __launch_bounds__(256, 2)
mma_gemm_k(const void* __restrict__ Ap, const void* __restrict__ Ap2, int K, int Kpad,
           const __nv_bfloat16* __restrict__ Bh, const __nv_bfloat16* __restrict__ Bl,
           int M,
           const float* __restrict__ bias, const float* __restrict__ res,
           float* __restrict__ C) {
    __shared__ __align__(16) __nv_bfloat16 sAh[128 * MT_S];
    __shared__ __align__(16) __nv_bfloat16 sAl[128 * MT_S];
    __shared__ __align__(16) __nv_bfloat16 sBh[128 * MT_S];
    __shared__ __align__(16) __nv_bfloat16 sBl[128 * MT_S];
    int tid = threadIdx.x;
    int wid = tid >> 5, lane = tid & 31;
    int wm = wid & 3;
    int wn = wid >> 2;
    int row0 = blockIdx.y * 128;
    int col0 = blockIdx.x * 128;

    float acc[2][8][4];
    #pragma unroll
    for (int mt = 0; mt < 2; mt++)
        #pragma unroll
        for (int nt = 0; nt < 8; nt++)
            #pragma unroll
            for (int q = 0; q < 4; q++) acc[mt][nt][q] = 0.f;

    int lr = tid >> 1;
    int seg = (tid & 1) * 16;
    int gr = row0 + lr;
    bool arow_ok = gr < M;
    const float* Arow = (const float*)Ap + (size_t)(arow_ok ? gr : 0) * K;
    const __nv_bfloat16* AhRow = (const __nv_bfloat16*)Ap + (size_t)(arow_ok ? gr : 0) * Kpad;
    const __nv_bfloat16* AlRow = (const __nv_bfloat16*)Ap2 + (size_t)(arow_ok ? gr : 0) * Kpad;
    const __nv_bfloat16* BhRow = Bh + (size_t)(col0 + lr) * Kpad;
    const __nv_bfloat16* BlRow = Bl + (size_t)(col0 + lr) * Kpad;

    float aF[16];
    uint4 ah[2], al[2];
    uint4 bh[2], bl[2];

    auto loadChunk = [&](int k0) {
        if (PRE) {
            ah[0] = *(const uint4*)(AhRow + k0 + seg);
            ah[1] = *(const uint4*)(AhRow + k0 + seg + 8);
            al[0] = *(const uint4*)(AlRow + k0 + seg);
            al[1] = *(const uint4*)(AlRow + k0 + seg + 8);
        } else {
            #pragma unroll
            for (int j = 0; j < 4; j++) {
                int gk = k0 + seg + j * 4;
                float4 v = make_float4(0.f, 0.f, 0.f, 0.f);
                if (arow_ok && gk < K) v = *(const float4*)(Arow + gk);
                aF[j * 4 + 0] = v.x; aF[j * 4 + 1] = v.y;
                aF[j * 4 + 2] = v.z; aF[j * 4 + 3] = v.w;
            }
        }
        bh[0] = *(const uint4*)(BhRow + k0 + seg);
        bh[1] = *(const uint4*)(BhRow + k0 + seg + 8);
        bl[0] = *(const uint4*)(BlRow + k0 + seg);
        bl[1] = *(const uint4*)(BlRow + k0 + seg + 8);
    };
    auto storeChunk = [&]() {
        if (PRE) {
            *(uint4*)&sAh[lr * MT_S + seg]     = ah[0];
            *(uint4*)&sAh[lr * MT_S + seg + 8] = ah[1];
            *(uint4*)&sAl[lr * MT_S + seg]     = al[0];
            *(uint4*)&sAl[lr * MT_S + seg + 8] = al[1];
        } else {
            __nv_bfloat16 h[16], l[16];
            #pragma unroll
            for (int j = 0; j < 16; j++) {
                h[j] = __float2bfloat16(aF[j]);
                l[j] = __float2bfloat16(aF[j] - __bfloat162float(h[j]));
            }
            *(uint4*)&sAh[lr * MT_S + seg]     = ((const uint4*)h)[0];
            *(uint4*)&sAh[lr * MT_S + seg + 8] = ((const uint4*)h)[1];
            *(uint4*)&sAl[lr * MT_S + seg]     = ((const uint4*)l)[0];
            *(uint4*)&sAl[lr * MT_S + seg + 8] = ((const uint4*)l)[1];
        }
        *(uint4*)&sBh[lr * MT_S + seg]     = bh[0];
        *(uint4*)&sBh[lr * MT_S + seg + 8] = bh[1];
        *(uint4*)&sBl[lr * MT_S + seg]     = bl[0];
        *(uint4*)&sBl[lr * MT_S + seg + 8] = bl[1];
    };

    int nch = Kpad / 32;
    loadChunk(0);
    for (int ci = 0; ci < nch; ci++) {
        storeChunk();
        __syncthreads();
        if (ci + 1 < nch) loadChunk((ci + 1) * 32);
        #pragma unroll
        for (int ks = 0; ks < 2; ks++) {
            int acol = ks * 16 + (lane & 3) * 2;
            uint32_t aH[2][4], aL[2][4];
            #pragma unroll
            for (int mt = 0; mt < 2; mt++) {
                int rb = (wm * 32 + mt * 16 + (lane >> 2)) * MT_S + acol;
                aH[mt][0] = *(const uint32_t*)&sAh[rb];
                aH[mt][1] = *(const uint32_t*)&sAh[rb + 8 * MT_S];
                aH[mt][2] = *(const uint32_t*)&sAh[rb + 8];
                aH[mt][3] = *(const uint32_t*)&sAh[rb + 8 * MT_S + 8];
                aL[mt][0] = *(const uint32_t*)&sAl[rb];
                aL[mt][1] = *(const uint32_t*)&sAl[rb + 8 * MT_S];
                aL[mt][2] = *(const uint32_t*)&sAl[rb + 8];
                aL[mt][3] = *(const uint32_t*)&sAl[rb + 8 * MT_S + 8];
            }
            #pragma unroll
            for (int nt = 0; nt < 8; nt++) {
                int nb = (wn * 64 + nt * 8 + (lane >> 2)) * MT_S + acol;
                uint32_t bH[2], bL[2];
                bH[0] = *(const uint32_t*)&sBh[nb];
                bH[1] = *(const uint32_t*)&sBh[nb + 8];
                bL[0] = *(const uint32_t*)&sBl[nb];
                bL[1] = *(const uint32_t*)&sBl[nb + 8];
                #pragma unroll
                for (int mt = 0; mt < 2; mt++) {
                    mma16816(acc[mt][nt], aH[mt], bH);
                    mma16816(acc[mt][nt], aL[mt], bH);
                    mma16816(acc[mt][nt], aH[mt], bL);
                }
            }
        }
        __syncthreads();
    }

    #pragma unroll
    for (int mt = 0; mt < 2; mt++) {
        #pragma unroll
        for (int half = 0; half < 2; half++) {
            int r = row0 + wm * 32 + mt * 16 + (lane >> 2) + half * 8;
            if (r >= M) continue;
            #pragma unroll
            for (int nt = 0; nt < 8; nt++) {
                int c = col0 + wn * 64 + nt * 8 + (lane & 3) * 2;
                float2 v;
                v.x = acc[mt][nt][half * 2 + 0];
                v.y = acc[mt][nt][half * 2 + 1];
                if (MODE >= 1) {
                    const float2 bb = *(const float2*)&bias[c];
                    v.x += bb.x; v.y += bb.y;
                    if (MODE == 1) { v.x = fmaxf(v.x, 0.f); v.y = fmaxf(v.y, 0.f); }
                    const float2 rr = *(const float2*)&res[(size_t)r * 256 + c];
                    v.x += rr.x; v.y += rr.y;
                }
                *(float2*)&C[(size_t)r * 256 + c] = v;
            }
        }
    }
}

// ---------------- weight transpose + hi/lo split ----------------
__global__ void tsplit_k(const float* __restrict__ src, int K, int Kpad,
                         __nv_bfloat16* __restrict__ hi, __nv_bfloat16* __restrict__ lo) {
    int idx = blockIdx.x * blockDim.x + threadIdx.x;
    if (idx >= 256 * Kpad) return;
    int k = idx % Kpad;
    int n = idx / Kpad;
    float v = (k < K) ? src[(size_t)k * 256 + n] : 0.f;
    __nv_bfloat16 h = __float2bfloat16(v);
    hi[idx] = h;
    lo[idx] = __float2bfloat16(v - __bfloat162float(h));
}

// ---------------- stacked SIMT pipeline kernels ----------------
__global__ void zero_int_k(int* p, int n) {
    int i = blockIdx.x * blockDim.x + threadIdx.x;
    if (i < n) p[i] = 0;
}
__global__ void att_k(const float* __restrict__ att_feats,
                      const float* __restrict__ W_enc,
                      const float* __restrict__ a_w, int natt) {
    int r = blockIdx.x;
    int d = threadIdx.x;
    __shared__ float sh[DIM];
    __shared__ float sred[8];
    sh[d] = att_feats[(size_t)r * DIM + d];
    __syncthreads();
    float acc = 0.f;
    #pragma unroll 8
    for (int k = 0; k < DIM; k++) acc += sh[k] * W_enc[(size_t)k * DIM + d];
    g_attW[(size_t)r * DIM + d] = acc;
    float v = sh[d] * a_w[DIM + d];
    for (int o = 16; o; o >>= 1) v += __shfl_xor_sync(0xffffffffu, v, o);
    if ((d & 31) == 0) sred[d >> 5] = v;
    __syncthreads();
    if (d == 0) {
        float s = 0.f;
        #pragma unroll
        for (int i = 0; i < 8; i++) s += sred[i];
        g_attdot[r] = s;
    }
}
// one warp per stacked node
__global__ void entdot_all_k(const float* __restrict__ ent0, const float* __restrict__ ent1,
                             const float* __restrict__ a_w, int n0, int ntot) {
    int node = (blockIdx.x * blockDim.x + threadIdx.x) >> 5;
    int lane = threadIdx.x & 31;
    if (node >= ntot) return;
    const float* row = (node < n0) ? ent0 + (size_t)node * DIM
                                   : ent1 + (size_t)(node - n0) * DIM;
    float s = 0.f;
    #pragma unroll
    for (int d = lane; d < DIM; d += 32) s += row[d] * a_w[d];
    for (int o = 16; o; o >>= 1) s += __shfl_xor_sync(0xffffffffu, s, o);
    if (lane == 0) g_entdot[node] = s;
}
__global__ void hist_tri_all_k(const int* __restrict__ t0, const int* __restrict__ t1,
                               int ne0, int netot, int n0) {
    int e = blockIdx.x * blockDim.x + threadIdx.x;
    if (e >= netot) return;
    int head = (e < ne0) ? t0[3 * e] : n0 + t1[3 * (e - ne0)];
    atomicAdd(&g_cnt[head], 1);
}
__global__ void scan_blk_k(int n) {
    __shared__ int wsum[32];
    int b = blockIdx.x;
    int i = b * 1024 + threadIdx.x;
    int lane = threadIdx.x & 31, wid = threadIdx.x >> 5;
    int v = (i < n) ? g_cnt[i] : 0;
    int x = v;
    #pragma unroll
    for (int o = 1; o < 32; o <<= 1) {
        int y = __shfl_up_sync(0xffffffffu, x, o);
        if (lane >= o) x += y;
    }
    if (lane == 31) wsum[wid] = x;
    __syncthreads();
    if (wid == 0) {
        int w = wsum[lane];
        int xs = w;
        #pragma unroll
        for (int o = 1; o < 32; o <<= 1) {
            int y = __shfl_up_sync(0xffffffffu, xs, o);
            if (lane >= o) xs += y;
        }
        wsum[lane] = xs - w;
    }
    __syncthreads();
    int excl = wsum[wid] + x - v;
    if (i < n) g_ptr[i] = excl;
    if (threadIdx.x == 1023) g_bsum[b] = excl + v;
}
__global__ void scan_mid_k(int nb, int n) {
    int lane = threadIdx.x;
    int carry = 0;
    for (int base = 0; base < nb; base += 32) {
        int i = base + lane;
        int v = (i < nb) ? g_bsum[i] : 0;
        int x = v;
        #pragma unroll
        for (int o = 1; o < 32; o <<= 1) {
            int y = __shfl_up_sync(0xffffffffu, x, o);
            if (lane >= o) x += y;
        }
        if (i < nb) g_boff[i] = carry + x - v;
        carry += __shfl_sync(0xffffffffu, x, 31);
    }
    if (lane == 0) g_ptr[n] = carry;
}
__global__ void scan_add_k(int n) {
    int i = blockIdx.x * blockDim.x + threadIdx.x;
    if (i < n) {
        int p = g_ptr[i] + g_boff[i >> 10];
        g_ptr[i] = p;
        g_fill[i] = p;
    }
}
__global__ void scatter_tri_all_k(const int* __restrict__ t0, const int* __restrict__ t1,
                                  int ne0, int netot, int n0) {
    int e = blockIdx.x * blockDim.x + threadIdx.x;
    if (e >= netot) return;
    int head = (e < ne0) ? t0[3 * e] : n0 + t1[3 * (e - ne0)];
    int pos = atomicAdd(&g_fill[head], 1);
    g_idx[pos] = e;
}
// edge CSR from concatenated sorted rows (np.unique sorts; self-loops cover all nodes)
__global__ void edge_ptr_all_k(const int* __restrict__ r0, const int* __restrict__ r1,
                               int E0, int Etot, int n0, int ntot) {
    int e = blockIdx.x * blockDim.x + threadIdx.x;
    if (e >= Etot) return;
    int r = (e < E0) ? r0[e] : n0 + r1[e - E0];
    if (e == 0) {
        for (int v = 0; v <= r; v++) g_eptr[v] = 0;
    } else {
        int rp = (e - 1 < E0) ? r0[e - 1] : n0 + r1[e - 1 - E0];
        for (int v = rp + 1; v <= r; v++) g_eptr[v] = e;
    }
    if (e == Etot - 1) {
        for (int v = r + 1; v <= ntot; v++) g_eptr[v] = Etot;
    }
}
__global__ void attr_agg_all_k(const int* __restrict__ t0, const int* __restrict__ t1,
                               int ne0,
                               const float* __restrict__ ab_ptr,
                               const float* __restrict__ ent0, const float* __restrict__ ent1,
                               int n0) {
    int v = blockIdx.x;
    int t = threadIdx.x;
    int s = g_ptr[v], e = g_ptr[v + 1];
    int side = v >= n0;
    const int* tri = side ? t1 : t0;
    int tbase = side ? ne0 : 0;
    __shared__ float sred[2];
    __shared__ float s_inv;
    __shared__ float sh_p[64];
    __shared__ int sh_att[64];
    __shared__ int sh_val[64];
    float ab = ab_ptr[0];
    float ed = g_entdot[v];
    float part = 0.f;
    for (int i = s + t; i < e; i += 64) {
        int tt = g_idx[i] - tbase;
        float sc = ed + g_attdot[tri[3 * tt + 2]] + ab;
        sc = sc > 0.f ? sc : 0.2f * sc;
        part += expf(sc);
    }
    for (int o = 16; o; o >>= 1) part += __shfl_xor_sync(0xffffffffu, part, o);
    if ((t & 31) == 0) sred[t >> 5] = part;
    __syncthreads();
    if (t == 0) {
        float rs = sred[0] + sred[1];
        s_inv = (rs > 0.f) ? 1.f / rs : 0.f;
    }
    __syncthreads();
    float inv_rs = s_inv;
    float4 acc = make_float4(0.f, 0.f, 0.f, 0.f);
    for (int base = s; base < e; base += 64) {
        int cnt = min(64, e - base);
        if (t < cnt) {
            int tt = g_idx[base + t] - tbase;
            int att = tri[3 * tt + 2];
            int val = tri[3 * tt + 1];
            sh_att[t] = att;
            sh_val[t] = val;
            float sc = ed + g_attdot[att] + ab;
            sc = sc > 0.f ? sc : 0.2f * sc;
            sh_p[t] = expf(sc) * inv_rs;
        }
        __syncthreads();
        for (int j = 0; j < cnt; j++) {
            float p = sh_p[j];
            const float4 aw = *(const float4*)&g_attW[(size_t)sh_att[j] * DIM + t * 4];
            const float4 vw = *(const float4*)&g_valW[(size_t)sh_val[j] * DIM + t * 4];
            acc.x += p * (aw.x + vw.x);
            acc.y += p * (aw.y + vw.y);
            acc.z += p * (aw.z + vw.z);
            acc.w += p * (aw.w + vw.w);
        }
        __syncthreads();
    }
    const float* ef_row = side ? ent1 + (size_t)(v - n0) * DIM : ent0 + (size_t)v * DIM;
    const float4 ef = *(const float4*)&ef_row[t * 4];
    float4 x = make_float4(acc.x + ef.x, acc.y + ef.y, acc.z + ef.z, acc.w + ef.w);
    x.x = x.x > 0.f ? x.x : expm1f(x.x);
    x.y = x.y > 0.f ? x.y : expm1f(x.y);
    x.z = x.z > 0.f ? x.z : expm1f(x.z);
    x.w = x.w > 0.f ? x.w : expm1f(x.w);
    *(float4*)&g_F1[(size_t)v * DIM + t * 4] = x;
}
// GCN mean-agg over stacked graph; writes bf16 hi/lo split
__global__ void gcn_agg_split_all_k(const float* __restrict__ feats,
                                    const int* __restrict__ c0, const int* __restrict__ c1,
                                    int E0, int n0,
                                    __nv_bfloat16* __restrict__ hi,
                                    __nv_bfloat16* __restrict__ lo) {
    int v = blockIdx.x;
    int t = threadIdx.x;
    int s = g_eptr[v], e = g_eptr[v + 1];
    __shared__ int sh_c[64];
    float4 acc = make_float4(0.f, 0.f, 0.f, 0.f);
    for (int base = s; base < e; base += 64) {
        int cnt = min(64, e - base);
        if (t < cnt) {
            int i = base + t;
            sh_c[t] = (i < E0) ? c0[i] : n0 + c1[i - E0];
        }
        __syncthreads();
        for (int j = 0; j < cnt; j++) {
            const float4 f = *(const float4*)&feats[(size_t)sh_c[j] * DIM + t * 4];
            acc.x += f.x; acc.y += f.y; acc.z += f.z; acc.w += f.w;
        }
        __syncthreads();
    }
    float inv = (e > s) ? 1.f / (float)(e - s) : 0.f;
    float vals[4] = {acc.x * inv, acc.y * inv, acc.z * inv, acc.w * inv};
    __nv_bfloat16 hv[4], lv[4];
    #pragma unroll
    for (int j = 0; j < 4; j++) {
        hv[j] = __float2bfloat16(vals[j]);
        lv[j] = __float2bfloat16(vals[j] - __bfloat162float(hv[j]));
    }
    *(uint2*)&hi[(size_t)v * DIM + t * 4] = *(uint2*)hv;
    *(uint2*)&lo[(size_t)v * DIM + t * 4] = *(uint2*)lv;
}
__global__ void l2norm_all_k(const float* __restrict__ in, float* __restrict__ out) {
    int v = blockIdx.x;
    int t = threadIdx.x;
    __shared__ float sred[2];
    __shared__ float s_inv;
    const float4 x = *(const float4*)&in[(size_t)v * DIM + t * 4];
    float sq = x.x * x.x + x.y * x.y + x.z * x.z + x.w * x.w;
    for (int o = 16; o; o >>= 1) sq += __shfl_xor_sync(0xffffffffu, sq, o);
    if ((t & 31) == 0) sred[t >> 5] = sq;
    __syncthreads();
    if (t == 0) {
        float nrm = sqrtf(sred[0] + sred[1]);
        s_inv = 1.f / fmaxf(nrm, 1e-12f);
    }
    __syncthreads();
    float inv = s_inv;
    float4 y = make_float4(x.x * inv, x.y * inv, x.z * inv, x.w * inv);
    *(float4*)&out[(size_t)v * DIM + t * 4] = y;
}
__global__ void gather_all_k(const int* __restrict__ s0, const int* __restrict__ s1,
                             int nseed, int n0,
                             const float* __restrict__ src, float* __restrict__ dst) {
    int i = blockIdx.x;
    int t = threadIdx.x;
    int node = (i < nseed) ? s0[i] : n0 + s1[i - nseed];
    *(float4*)&dst[(size_t)i * DIM + t * 4] =
        *(const float4*)&src[(size_t)node * DIM + t * 4];
}

// ---------------- host orchestration ----------------
static inline int ceildiv(int a, int b) { return (a + b - 1) / b; }

extern "C" void kernel_launch(void* const* d_in, const int* in_sizes, int n_in,
                              void* d_out, int out_size) {
    const int* seed_sr = (const int*)d_in[0];
    const int* seed_tg = (const int*)d_in[1];
    const int* tri_sr  = (const int*)d_in[2];
    const int* tri_tg  = (const int*)d_in[3];
    const int* rows_sr = (const int*)d_in[4];
    const int* cols_sr = (const int*)d_in[5];
    const int* rows_tg = (const int*)d_in[6];
    const int* cols_tg = (const int*)d_in[7];
    const float* att_feats = (const float*)d_in[8];
    const float* val_feats = (const float*)d_in[9];
    const float* ent_sr = (const float*)d_in[10];
    const float* ent_tg = (const float*)d_in[11];
    const float* a_w   = (const float*)d_in[12];
    const float* a_b   = (const float*)d_in[13];
    const float* W_enc = (const float*)d_in[14];
    const float* w1    = (const float*)d_in[15];
    const float* b1    = (const float*)d_in[16];
    const float* w2    = (const float*)d_in[17];
    const float* b2    = (const float*)d_in[18];
    (void)n_in; (void)out_size;

    const int nseed  = in_sizes[0];
    const int ne0    = in_sizes[2] / 3;
    const int ne1    = in_sizes[3] / 3;
    const int E0     = in_sizes[4];
    const int E1     = in_sizes[6];
    const int natt   = in_sizes[8] / DIM;
    const int nval   = in_sizes[9] / 300;
    const int n0     = in_sizes[10] / DIM;
    const int n1     = in_sizes[11] / DIM;
    const int ntot   = n0 + n1;
    const int netot  = ne0 + ne1;
    const int Etot   = E0 + E1;

    // one-time host resources (created on the uncaptured correctness call)
    static cudaStream_t s_aux = nullptr;
    static cudaEvent_t ev_fork = nullptr, ev_join = nullptr;
    if (!s_aux) {
        cudaStreamCreateWithFlags(&s_aux, cudaStreamNonBlocking);
        cudaEventCreateWithFlags(&ev_fork, cudaEventDisableTiming);
        cudaEventCreateWithFlags(&ev_join, cudaEventDisableTiming);
    }

    float* valW;  cudaGetSymbolAddress((void**)&valW,  g_valW);
    float* F1;    cudaGetSymbolAddress((void**)&F1,    g_F1);
    float* F2;    cudaGetSymbolAddress((void**)&F2,    g_F2);
    int*   cntp;  cudaGetSymbolAddress((void**)&cntp,  g_cnt);
    __nv_bfloat16 *xaH, *xaL, *wetH, *wetL, *w1tH, *w1tL, *w2tH, *w2tL;
    cudaGetSymbolAddress((void**)&xaH, g_xa_h);
    cudaGetSymbolAddress((void**)&xaL, g_xa_l);
    cudaGetSymbolAddress((void**)&wetH, g_wet_h);
    cudaGetSymbolAddress((void**)&wetL, g_wet_l);
    cudaGetSymbolAddress((void**)&w1tH, g_w1t_h);
    cudaGetSymbolAddress((void**)&w1tL, g_w1t_l);
    cudaGetSymbolAddress((void**)&w2tH, g_w2t_h);
    cudaGetSymbolAddress((void**)&w2tL, g_w2t_l);

    float* out = (float*)d_out;
    float* out_seed = out;                                   // [2*nseed, 256]
    float* out_full = out + (size_t)2 * nseed * DIM;         // [ntot, 256] (fs then ft)

    // ---- fork: valW pipeline on aux stream ----
    cudaEventRecord(ev_fork, 0);
    cudaStreamWaitEvent(s_aux, ev_fork, 0);
    tsplit_k<<<ceildiv(256 * KPAD_VAL, 256), 256, 0, s_aux>>>(
        W_enc + (size_t)DIM * DIM, 300, KPAD_VAL, wetH, wetL);
    {
        dim3 grid(2, ceildiv(nval, 128));
        mma_gemm_k<0, 0><<<grid, 256, 0, s_aux>>>(val_feats, nullptr, 300, KPAD_VAL,
                                                  wetH, wetL, nval, nullptr, nullptr, valW);
    }
    cudaEventRecord(ev_join, s_aux);

    // ---- main stream: precompute + stacked CSR builds ----
    att_k<<<natt, DIM>>>(att_feats, W_enc, a_w, natt);
    tsplit_k<<<ceildiv(256 * 256, 256), 256>>>(w1, 256, 256, w1tH, w1tL);
    tsplit_k<<<ceildiv(256 * 256, 256), 256>>>(w2, 256, 256, w2tH, w2tL);
    entdot_all_k<<<ceildiv(ntot * 32, 256), 256>>>(ent_sr, ent_tg, a_w, n0, ntot);
    zero_int_k<<<ceildiv(ntot, 256), 256>>>(cntp, ntot);
    hist_tri_all_k<<<ceildiv(netot, 256), 256>>>(tri_sr, tri_tg, ne0, netot, n0);
    int nb = ceildiv(ntot, 1024);
    scan_blk_k<<<nb, 1024>>>(ntot);
    scan_mid_k<<<1, 32>>>(nb, ntot);
    scan_add_k<<<ceildiv(ntot, 256), 256>>>(ntot);
    scatter_tri_all_k<<<ceildiv(netot, 256), 256>>>(tri_sr, tri_tg, ne0, netot, n0);
    edge_ptr_all_k<<<ceildiv(Etot, 256), 256>>>(rows_sr, rows_tg, E0, Etot, n0, ntot);

    // ---- join: attr encoder needs valW ----
    cudaStreamWaitEvent(0, ev_join, 0);
    attr_agg_all_k<<<ntot, 64>>>(tri_sr, tri_tg, ne0, a_b, ent_sr, ent_tg, n0);

    // ---- stacked GCN layers ----
    dim3 ggrid(2, ceildiv(ntot, 128));
    gcn_agg_split_all_k<<<ntot, 64>>>(F1, cols_sr, cols_tg, E0, n0, xaH, xaL);
    mma_gemm_k<1, 1><<<ggrid, 256>>>(xaH, xaL, 256, 256, w1tH, w1tL, ntot, b1, F1, F2);
    gcn_agg_split_all_k<<<ntot, 64>>>(F2, cols_sr, cols_tg, E0, n0, xaH, xaL);
    mma_gemm_k<2, 1><<<ggrid, 256>>>(xaH, xaL, 256, 256, w2tH, w2tL, ntot, b2, F2, F1);

    // ---- output ----
    l2norm_all_k<<<ntot, 64>>>(F1, out_full);
    gather_all_k<<<2 * nseed, 64>>>(seed_sr, seed_tg, nseed, n0, out_full, out_seed);
}

// round 8
// speedup vs baseline: 2.7003x; 1.0232x over previous
#include <cuda_runtime.h>
#include <cuda_bf16.h>
#include <math.h>
#include <stdint.h>

#define DIM 256
#define NTOT 100000
#define ETRI 400000
#define NVALMAX 100000
#define NATTMAX 1001
#define KPAD_VAL 320
#define MT_S 40   // smem row stride in bf16 (80B): conflict-free for ldmatrix 8-row phases

// ---------------- scratch ----------------
__device__ float g_valW[NVALMAX * DIM];
__device__ float g_attW[NATTMAX * DIM];
__device__ float g_attdot[NATTMAX];
__device__ float g_entdot[NTOT];
__device__ int   g_cnt[NTOT];
__device__ int   g_ptr[NTOT + 1];
__device__ int   g_eptr[NTOT + 1];
__device__ int   g_fill[NTOT];
__device__ int   g_idx[ETRI];
__device__ int   g_bsum[128];
__device__ int   g_boff[128];
__device__ float g_F1[NTOT * DIM];
__device__ float g_F2[NTOT * DIM];
__device__ __nv_bfloat16 g_xa_h[NTOT * DIM];
__device__ __nv_bfloat16 g_xa_l[NTOT * DIM];
__device__ __nv_bfloat16 g_wet_h[DIM * KPAD_VAL];
__device__ __nv_bfloat16 g_wet_l[DIM * KPAD_VAL];
__device__ __nv_bfloat16 g_w1t_h[DIM * DIM];
__device__ __nv_bfloat16 g_w1t_l[DIM * DIM];
__device__ __nv_bfloat16 g_w2t_h[DIM * DIM];
__device__ __nv_bfloat16 g_w2t_l[DIM * DIM];

// ---------------- mma.sync + ldmatrix wrappers ----------------
__device__ __forceinline__ void mma16816(float* c, const uint32_t* a, const uint32_t* b) {
    asm volatile(
        "mma.sync.aligned.m16n8k16.row.col.f32.bf16.bf16.f32 "
        "{%0,%1,%2,%3}, {%4,%5,%6,%7}, {%8,%9}, {%0,%1,%2,%3};"
        : "+f"(c[0]), "+f"(c[1]), "+f"(c[2]), "+f"(c[3])
        : "r"(a[0]), "r"(a[1]), "r"(a[2]), "r"(a[3]), "r"(b[0]), "r"(b[1]));
}
#define LDMX4(r0, r1, r2, r3, addr) \
    asm volatile("ldmatrix.sync.aligned.m8n8.x4.shared.b16 {%0,%1,%2,%3}, [%4];" \
        : "=r"(r0), "=r"(r1), "=r"(r2), "=r"(r3) : "r"(addr))

// ---------------- HMMA split GEMM (AhBh + AlBh + AhBl, fp32 accum) ----------------
template <int MODE, int PRE>
__global__ void __launch_bounds__(256, 2)
mma_gemm_k(const void* __restrict__ Ap, const void* __restrict__ Ap2, int K, int Kpad,
           const __nv_bfloat16* __restrict__ Bh, const __nv_bfloat16* __restrict__ Bl,
           int M,
           const float* __restrict__ bias, const float* __restrict__ res,
           float* __restrict__ C) {
    __shared__ __align__(16) __nv_bfloat16 sAh[128 * MT_S];
    __shared__ __align__(16) __nv_bfloat16 sAl[128 * MT_S];
    __shared__ __align__(16) __nv_bfloat16 sBh[128 * MT_S];
    __shared__ __align__(16) __nv_bfloat16 sBl[128 * MT_S];
    int tid = threadIdx.x;
    int wid = tid >> 5, lane = tid & 31;
    int wm = wid & 3;
    int wn = wid >> 2;
    int row0 = blockIdx.y * 128;
    int col0 = blockIdx.x * 128;

    uint32_t sAh_b = (uint32_t)__cvta_generic_to_shared(sAh);
    uint32_t sAl_b = (uint32_t)__cvta_generic_to_shared(sAl);
    uint32_t sBh_b = (uint32_t)__cvta_generic_to_shared(sBh);
    uint32_t sBl_b = (uint32_t)__cvta_generic_to_shared(sBl);

    float acc[2][8][4];
    #pragma unroll
    for (int mt = 0; mt < 2; mt++)
        #pragma unroll
        for (int nt = 0; nt < 8; nt++)
            #pragma unroll
            for (int q = 0; q < 4; q++) acc[mt][nt][q] = 0.f;

    int lr = tid >> 1;
    int seg = (tid & 1) * 16;
    int gr = row0 + lr;
    bool arow_ok = gr < M;
    const float* Arow = (const float*)Ap + (size_t)(arow_ok ? gr : 0) * K;
    const __nv_bfloat16* AhRow = (const __nv_bfloat16*)Ap + (size_t)(arow_ok ? gr : 0) * Kpad;
    const __nv_bfloat16* AlRow = (const __nv_bfloat16*)Ap2 + (size_t)(arow_ok ? gr : 0) * Kpad;
    const __nv_bfloat16* BhRow = Bh + (size_t)(col0 + lr) * Kpad;
    const __nv_bfloat16* BlRow = Bl + (size_t)(col0 + lr) * Kpad;

    float aF[16];
    uint4 ah[2], al[2];
    uint4 bh[2], bl[2];

    auto loadChunk = [&](int k0) {
        if (PRE) {
            ah[0] = *(const uint4*)(AhRow + k0 + seg);
            ah[1] = *(const uint4*)(AhRow + k0 + seg + 8);
            al[0] = *(const uint4*)(AlRow + k0 + seg);
            al[1] = *(const uint4*)(AlRow + k0 + seg + 8);
        } else {
            #pragma unroll
            for (int j = 0; j < 4; j++) {
                int gk = k0 + seg + j * 4;
                float4 v = make_float4(0.f, 0.f, 0.f, 0.f);
                if (arow_ok && gk < K) v = *(const float4*)(Arow + gk);
                aF[j * 4 + 0] = v.x; aF[j * 4 + 1] = v.y;
                aF[j * 4 + 2] = v.z; aF[j * 4 + 3] = v.w;
            }
        }
        bh[0] = *(const uint4*)(BhRow + k0 + seg);
        bh[1] = *(const uint4*)(BhRow + k0 + seg + 8);
        bl[0] = *(const uint4*)(BlRow + k0 + seg);
        bl[1] = *(const uint4*)(BlRow + k0 + seg + 8);
    };
    auto storeChunk = [&]() {
        if (PRE) {
            *(uint4*)&sAh[lr * MT_S + seg]     = ah[0];
            *(uint4*)&sAh[lr * MT_S + seg + 8] = ah[1];
            *(uint4*)&sAl[lr * MT_S + seg]     = al[0];
            *(uint4*)&sAl[lr * MT_S + seg + 8] = al[1];
        } else {
            __nv_bfloat16 h[16], l[16];
            #pragma unroll
            for (int j = 0; j < 16; j++) {
                h[j] = __float2bfloat16(aF[j]);
                l[j] = __float2bfloat16(aF[j] - __bfloat162float(h[j]));
            }
            *(uint4*)&sAh[lr * MT_S + seg]     = ((const uint4*)h)[0];
            *(uint4*)&sAh[lr * MT_S + seg + 8] = ((const uint4*)h)[1];
            *(uint4*)&sAl[lr * MT_S + seg]     = ((const uint4*)l)[0];
            *(uint4*)&sAl[lr * MT_S + seg + 8] = ((const uint4*)l)[1];
        }
        *(uint4*)&sBh[lr * MT_S + seg]     = bh[0];
        *(uint4*)&sBh[lr * MT_S + seg + 8] = bh[1];
        *(uint4*)&sBl[lr * MT_S + seg]     = bl[0];
        *(uint4*)&sBl[lr * MT_S + seg + 8] = bl[1];
    };

    // ldmatrix lane-address components (byte offsets computed per ks/tile below)
    int a_row = wm * 32 + (lane & 15);            // + mt*16
    int a_colsel = (lane >> 4) * 8;               // 0 or 8 (k-half)
    int b_row = wn * 64 + ((lane >> 4) ? 8 : 0) + (lane & 7);   // + p*16
    int b_colsel = ((lane >> 3) & 1) * 8;         // 0 or 8 (k-half)

    int nch = Kpad / 32;
    loadChunk(0);
    for (int ci = 0; ci < nch; ci++) {
        storeChunk();
        __syncthreads();
        if (ci + 1 < nch) loadChunk((ci + 1) * 32);
        #pragma unroll
        for (int ks = 0; ks < 2; ks++) {
            uint32_t aH[2][4], aL[2][4];
            #pragma unroll
            for (int mt = 0; mt < 2; mt++) {
                uint32_t off = (uint32_t)(((a_row + mt * 16) * MT_S + ks * 16 + a_colsel) * 2);
                LDMX4(aH[mt][0], aH[mt][1], aH[mt][2], aH[mt][3], sAh_b + off);
                LDMX4(aL[mt][0], aL[mt][1], aL[mt][2], aL[mt][3], sAl_b + off);
            }
            #pragma unroll
            for (int p = 0; p < 4; p++) {
                uint32_t off = (uint32_t)(((b_row + p * 16) * MT_S + ks * 16 + b_colsel) * 2);
                uint32_t h0, h1, h2, h3, l0, l1, l2, l3;
                LDMX4(h0, h1, h2, h3, sBh_b + off);
                LDMX4(l0, l1, l2, l3, sBl_b + off);
                uint32_t bH0[2] = {h0, h1}, bH1[2] = {h2, h3};
                uint32_t bL0[2] = {l0, l1}, bL1[2] = {l2, l3};
                #pragma unroll
                for (int mt = 0; mt < 2; mt++) {
                    mma16816(acc[mt][2 * p],     aH[mt], bH0);
                    mma16816(acc[mt][2 * p],     aL[mt], bH0);
                    mma16816(acc[mt][2 * p],     aH[mt], bL0);
                    mma16816(acc[mt][2 * p + 1], aH[mt], bH1);
                    mma16816(acc[mt][2 * p + 1], aL[mt], bH1);
                    mma16816(acc[mt][2 * p + 1], aH[mt], bL1);
                }
            }
        }
        __syncthreads();
    }

    #pragma unroll
    for (int mt = 0; mt < 2; mt++) {
        #pragma unroll
        for (int half = 0; half < 2; half++) {
            int r = row0 + wm * 32 + mt * 16 + (lane >> 2) + half * 8;
            if (r >= M) continue;
            #pragma unroll
            for (int nt = 0; nt < 8; nt++) {
                int c = col0 + wn * 64 + nt * 8 + (lane & 3) * 2;
                float2 v;
                v.x = acc[mt][nt][half * 2 + 0];
                v.y = acc[mt][nt][half * 2 + 1];
                if (MODE >= 1) {
                    const float2 bb = *(const float2*)&bias[c];
                    v.x += bb.x; v.y += bb.y;
                    if (MODE == 1) { v.x = fmaxf(v.x, 0.f); v.y = fmaxf(v.y, 0.f); }
                    const float2 rr = *(const float2*)&res[(size_t)r * 256 + c];
                    v.x += rr.x; v.y += rr.y;
                }
                *(float2*)&C[(size_t)r * 256 + c] = v;
            }
        }
    }
}

// ---------------- weight transpose + hi/lo split ----------------
__global__ void tsplit_k(const float* __restrict__ src, int K, int Kpad,
                         __nv_bfloat16* __restrict__ hi, __nv_bfloat16* __restrict__ lo) {
    int idx = blockIdx.x * blockDim.x + threadIdx.x;
    if (idx >= 256 * Kpad) return;
    int k = idx % Kpad;
    int n = idx / Kpad;
    float v = (k < K) ? src[(size_t)k * 256 + n] : 0.f;
    __nv_bfloat16 h = __float2bfloat16(v);
    hi[idx] = h;
    lo[idx] = __float2bfloat16(v - __bfloat162float(h));
}

// ---------------- stacked SIMT pipeline kernels ----------------
__global__ void zero_int_k(int* p, int n) {
    int i = blockIdx.x * blockDim.x + threadIdx.x;
    if (i < n) p[i] = 0;
}
__global__ void att_k(const float* __restrict__ att_feats,
                      const float* __restrict__ W_enc,
                      const float* __restrict__ a_w, int natt) {
    int r = blockIdx.x;
    int d = threadIdx.x;
    __shared__ float sh[DIM];
    __shared__ float sred[8];
    sh[d] = att_feats[(size_t)r * DIM + d];
    __syncthreads();
    float acc = 0.f;
    #pragma unroll 8
    for (int k = 0; k < DIM; k++) acc += sh[k] * W_enc[(size_t)k * DIM + d];
    g_attW[(size_t)r * DIM + d] = acc;
    float v = sh[d] * a_w[DIM + d];
    for (int o = 16; o; o >>= 1) v += __shfl_xor_sync(0xffffffffu, v, o);
    if ((d & 31) == 0) sred[d >> 5] = v;
    __syncthreads();
    if (d == 0) {
        float s = 0.f;
        #pragma unroll
        for (int i = 0; i < 8; i++) s += sred[i];
        g_attdot[r] = s;
    }
}
__global__ void entdot_all_k(const float* __restrict__ ent0, const float* __restrict__ ent1,
                             const float* __restrict__ a_w, int n0, int ntot) {
    int node = (blockIdx.x * blockDim.x + threadIdx.x) >> 5;
    int lane = threadIdx.x & 31;
    if (node >= ntot) return;
    const float* row = (node < n0) ? ent0 + (size_t)node * DIM
                                   : ent1 + (size_t)(node - n0) * DIM;
    float s = 0.f;
    #pragma unroll
    for (int d = lane; d < DIM; d += 32) s += row[d] * a_w[d];
    for (int o = 16; o; o >>= 1) s += __shfl_xor_sync(0xffffffffu, s, o);
    if (lane == 0) g_entdot[node] = s;
}
__global__ void hist_tri_all_k(const int* __restrict__ t0, const int* __restrict__ t1,
                               int ne0, int netot, int n0) {
    int e = blockIdx.x * blockDim.x + threadIdx.x;
    if (e >= netot) return;
    int head = (e < ne0) ? t0[3 * e] : n0 + t1[3 * (e - ne0)];
    atomicAdd(&g_cnt[head], 1);
}
__global__ void scan_blk_k(int n) {
    __shared__ int wsum[32];
    int b = blockIdx.x;
    int i = b * 1024 + threadIdx.x;
    int lane = threadIdx.x & 31, wid = threadIdx.x >> 5;
    int v = (i < n) ? g_cnt[i] : 0;
    int x = v;
    #pragma unroll
    for (int o = 1; o < 32; o <<= 1) {
        int y = __shfl_up_sync(0xffffffffu, x, o);
        if (lane >= o) x += y;
    }
    if (lane == 31) wsum[wid] = x;
    __syncthreads();
    if (wid == 0) {
        int w = wsum[lane];
        int xs = w;
        #pragma unroll
        for (int o = 1; o < 32; o <<= 1) {
            int y = __shfl_up_sync(0xffffffffu, xs, o);
            if (lane >= o) xs += y;
        }
        wsum[lane] = xs - w;
    }
    __syncthreads();
    int excl = wsum[wid] + x - v;
    if (i < n) g_ptr[i] = excl;
    if (threadIdx.x == 1023) g_bsum[b] = excl + v;
}
__global__ void scan_mid_k(int nb, int n) {
    int lane = threadIdx.x;
    int carry = 0;
    for (int base = 0; base < nb; base += 32) {
        int i = base + lane;
        int v = (i < nb) ? g_bsum[i] : 0;
        int x = v;
        #pragma unroll
        for (int o = 1; o < 32; o <<= 1) {
            int y = __shfl_up_sync(0xffffffffu, x, o);
            if (lane >= o) x += y;
        }
        if (i < nb) g_boff[i] = carry + x - v;
        carry += __shfl_sync(0xffffffffu, x, 31);
    }
    if (lane == 0) g_ptr[n] = carry;
}
__global__ void scan_add_k(int n) {
    int i = blockIdx.x * blockDim.x + threadIdx.x;
    if (i < n) {
        int p = g_ptr[i] + g_boff[i >> 10];
        g_ptr[i] = p;
        g_fill[i] = p;
    }
}
__global__ void scatter_tri_all_k(const int* __restrict__ t0, const int* __restrict__ t1,
                                  int ne0, int netot, int n0) {
    int e = blockIdx.x * blockDim.x + threadIdx.x;
    if (e >= netot) return;
    int head = (e < ne0) ? t0[3 * e] : n0 + t1[3 * (e - ne0)];
    int pos = atomicAdd(&g_fill[head], 1);
    g_idx[pos] = e;
}
__global__ void edge_ptr_all_k(const int* __restrict__ r0, const int* __restrict__ r1,
                               int E0, int Etot, int n0, int ntot) {
    int e = blockIdx.x * blockDim.x + threadIdx.x;
    if (e >= Etot) return;
    int r = (e < E0) ? r0[e] : n0 + r1[e - E0];
    if (e == 0) {
        for (int v = 0; v <= r; v++) g_eptr[v] = 0;
    } else {
        int rp = (e - 1 < E0) ? r0[e - 1] : n0 + r1[e - 1 - E0];
        for (int v = rp + 1; v <= r; v++) g_eptr[v] = e;
    }
    if (e == Etot - 1) {
        for (int v = r + 1; v <= ntot; v++) g_eptr[v] = Etot;
    }
}
__global__ void attr_agg_all_k(const int* __restrict__ t0, const int* __restrict__ t1,
                               int ne0,
                               const float* __restrict__ ab_ptr,
                               const float* __restrict__ ent0, const float* __restrict__ ent1,
                               int n0) {
    int v = blockIdx.x;
    int t = threadIdx.x;
    int s = g_ptr[v], e = g_ptr[v + 1];
    int side = v >= n0;
    const int* tri = side ? t1 : t0;
    int tbase = side ? ne0 : 0;
    __shared__ float sred[2];
    __shared__ float s_inv;
    __shared__ float sh_p[64];
    __shared__ int sh_att[64];
    __shared__ int sh_val[64];
    float ab = ab_ptr[0];
    float ed = g_entdot[v];
    float part = 0.f;
    for (int i = s + t; i < e; i += 64) {
        int tt = g_idx[i] - tbase;
        float sc = ed + g_attdot[tri[3 * tt + 2]] + ab;
        sc = sc > 0.f ? sc : 0.2f * sc;
        part += expf(sc);
    }
    for (int o = 16; o; o >>= 1) part += __shfl_xor_sync(0xffffffffu, part, o);
    if ((t & 31) == 0) sred[t >> 5] = part;
    __syncthreads();
    if (t == 0) {
        float rs = sred[0] + sred[1];
        s_inv = (rs > 0.f) ? 1.f / rs : 0.f;
    }
    __syncthreads();
    float inv_rs = s_inv;
    float4 acc = make_float4(0.f, 0.f, 0.f, 0.f);
    for (int base = s; base < e; base += 64) {
        int cnt = min(64, e - base);
        if (t < cnt) {
            int tt = g_idx[base + t] - tbase;
            int att = tri[3 * tt + 2];
            int val = tri[3 * tt + 1];
            sh_att[t] = att;
            sh_val[t] = val;
            float sc = ed + g_attdot[att] + ab;
            sc = sc > 0.f ? sc : 0.2f * sc;
            sh_p[t] = expf(sc) * inv_rs;
        }
        __syncthreads();
        for (int j = 0; j < cnt; j++) {
            float p = sh_p[j];
            const float4 aw = *(const float4*)&g_attW[(size_t)sh_att[j] * DIM + t * 4];
            const float4 vw = *(const float4*)&g_valW[(size_t)sh_val[j] * DIM + t * 4];
            acc.x += p * (aw.x + vw.x);
            acc.y += p * (aw.y + vw.y);
            acc.z += p * (aw.z + vw.z);
            acc.w += p * (aw.w + vw.w);
        }
        __syncthreads();
    }
    const float* ef_row = side ? ent1 + (size_t)(v - n0) * DIM : ent0 + (size_t)v * DIM;
    const float4 ef = *(const float4*)&ef_row[t * 4];
    float4 x = make_float4(acc.x + ef.x, acc.y + ef.y, acc.z + ef.z, acc.w + ef.w);
    x.x = x.x > 0.f ? x.x : expm1f(x.x);
    x.y = x.y > 0.f ? x.y : expm1f(x.y);
    x.z = x.z > 0.f ? x.z : expm1f(x.z);
    x.w = x.w > 0.f ? x.w : expm1f(x.w);
    *(float4*)&g_F1[(size_t)v * DIM + t * 4] = x;
}
__global__ void gcn_agg_split_all_k(const float* __restrict__ feats,
                                    const int* __restrict__ c0, const int* __restrict__ c1,
                                    int E0, int n0,
                                    __nv_bfloat16* __restrict__ hi,
                                    __nv_bfloat16* __restrict__ lo) {
    int v = blockIdx.x;
    int t = threadIdx.x;
    int s = g_eptr[v], e = g_eptr[v + 1];
    __shared__ int sh_c[64];
    float4 acc = make_float4(0.f, 0.f, 0.f, 0.f);
    for (int base = s; base < e; base += 64) {
        int cnt = min(64, e - base);
        if (t < cnt) {
            int i = base + t;
            sh_c[t] = (i < E0) ? c0[i] : n0 + c1[i - E0];
        }
        __syncthreads();
        for (int j = 0; j < cnt; j++) {
            const float4 f = *(const float4*)&feats[(size_t)sh_c[j] * DIM + t * 4];
            acc.x += f.x; acc.y += f.y; acc.z += f.z; acc.w += f.w;
        }
        __syncthreads();
    }
    float inv = (e > s) ? 1.f / (float)(e - s) : 0.f;
    float vals[4] = {acc.x * inv, acc.y * inv, acc.z * inv, acc.w * inv};
    __nv_bfloat16 hv[4], lv[4];
    #pragma unroll
    for (int j = 0; j < 4; j++) {
        hv[j] = __float2bfloat16(vals[j]);
        lv[j] = __float2bfloat16(vals[j] - __bfloat162float(hv[j]));
    }
    *(uint2*)&hi[(size_t)v * DIM + t * 4] = *(uint2*)hv;
    *(uint2*)&lo[(size_t)v * DIM + t * 4] = *(uint2*)lv;
}
__global__ void l2norm_all_k(const float* __restrict__ in, float* __restrict__ out) {
    int v = blockIdx.x;
    int t = threadIdx.x;
    __shared__ float sred[2];
    __shared__ float s_inv;
    const float4 x = *(const float4*)&in[(size_t)v * DIM + t * 4];
    float sq = x.x * x.x + x.y * x.y + x.z * x.z + x.w * x.w;
    for (int o = 16; o; o >>= 1) sq += __shfl_xor_sync(0xffffffffu, sq, o);
    if ((t & 31) == 0) sred[t >> 5] = sq;
    __syncthreads();
    if (t == 0) {
        float nrm = sqrtf(sred[0] + sred[1]);
        s_inv = 1.f / fmaxf(nrm, 1e-12f);
    }
    __syncthreads();
    float inv = s_inv;
    float4 y = make_float4(x.x * inv, x.y * inv, x.z * inv, x.w * inv);
    *(float4*)&out[(size_t)v * DIM + t * 4] = y;
}
__global__ void gather_all_k(const int* __restrict__ s0, const int* __restrict__ s1,
                             int nseed, int n0,
                             const float* __restrict__ src, float* __restrict__ dst) {
    int i = blockIdx.x;
    int t = threadIdx.x;
    int node = (i < nseed) ? s0[i] : n0 + s1[i - nseed];
    *(float4*)&dst[(size_t)i * DIM + t * 4] =
        *(const float4*)&src[(size_t)node * DIM + t * 4];
}

// ---------------- host orchestration ----------------
static inline int ceildiv(int a, int b) { return (a + b - 1) / b; }

extern "C" void kernel_launch(void* const* d_in, const int* in_sizes, int n_in,
                              void* d_out, int out_size) {
    const int* seed_sr = (const int*)d_in[0];
    const int* seed_tg = (const int*)d_in[1];
    const int* tri_sr  = (const int*)d_in[2];
    const int* tri_tg  = (const int*)d_in[3];
    const int* rows_sr = (const int*)d_in[4];
    const int* cols_sr = (const int*)d_in[5];
    const int* rows_tg = (const int*)d_in[6];
    const int* cols_tg = (const int*)d_in[7];
    const float* att_feats = (const float*)d_in[8];
    const float* val_feats = (const float*)d_in[9];
    const float* ent_sr = (const float*)d_in[10];
    const float* ent_tg = (const float*)d_in[11];
    const float* a_w   = (const float*)d_in[12];
    const float* a_b   = (const float*)d_in[13];
    const float* W_enc = (const float*)d_in[14];
    const float* w1    = (const float*)d_in[15];
    const float* b1    = (const float*)d_in[16];
    const float* w2    = (const float*)d_in[17];
    const float* b2    = (const float*)d_in[18];
    (void)n_in; (void)out_size;

    const int nseed  = in_sizes[0];
    const int ne0    = in_sizes[2] / 3;
    const int ne1    = in_sizes[3] / 3;
    const int E0     = in_sizes[4];
    const int E1     = in_sizes[6];
    const int natt   = in_sizes[8] / DIM;
    const int nval   = in_sizes[9] / 300;
    const int n0     = in_sizes[10] / DIM;
    const int n1     = in_sizes[11] / DIM;
    const int ntot   = n0 + n1;
    const int netot  = ne0 + ne1;
    const int Etot   = E0 + E1;

    static cudaStream_t s_aux = nullptr;
    static cudaEvent_t ev_fork = nullptr, ev_join = nullptr;
    if (!s_aux) {
        cudaStreamCreateWithFlags(&s_aux, cudaStreamNonBlocking);
        cudaEventCreateWithFlags(&ev_fork, cudaEventDisableTiming);
        cudaEventCreateWithFlags(&ev_join, cudaEventDisableTiming);
    }

    float* valW;  cudaGetSymbolAddress((void**)&valW,  g_valW);
    float* F1;    cudaGetSymbolAddress((void**)&F1,    g_F1);
    float* F2;    cudaGetSymbolAddress((void**)&F2,    g_F2);
    int*   cntp;  cudaGetSymbolAddress((void**)&cntp,  g_cnt);
    __nv_bfloat16 *xaH, *xaL, *wetH, *wetL, *w1tH, *w1tL, *w2tH, *w2tL;
    cudaGetSymbolAddress((void**)&xaH, g_xa_h);
    cudaGetSymbolAddress((void**)&xaL, g_xa_l);
    cudaGetSymbolAddress((void**)&wetH, g_wet_h);
    cudaGetSymbolAddress((void**)&wetL, g_wet_l);
    cudaGetSymbolAddress((void**)&w1tH, g_w1t_h);
    cudaGetSymbolAddress((void**)&w1tL, g_w1t_l);
    cudaGetSymbolAddress((void**)&w2tH, g_w2t_h);
    cudaGetSymbolAddress((void**)&w2tL, g_w2t_l);

    float* out = (float*)d_out;
    float* out_seed = out;
    float* out_full = out + (size_t)2 * nseed * DIM;

    // ---- precompute; ordered so the profiled launch (~idx 3-4) is the valW GEMM ----
    tsplit_k<<<ceildiv(256 * KPAD_VAL, 256), 256>>>(
        W_enc + (size_t)DIM * DIM, 300, KPAD_VAL, wetH, wetL);               // 0
    cudaEventRecord(ev_fork, 0);
    cudaStreamWaitEvent(s_aux, ev_fork, 0);
    att_k<<<natt, DIM>>>(att_feats, W_enc, a_w, natt);                       // 1
    tsplit_k<<<ceildiv(256 * 256, 256), 256>>>(w1, 256, 256, w1tH, w1tL);    // 2
    {
        dim3 grid(2, ceildiv(nval, 128));
        mma_gemm_k<0, 0><<<grid, 256, 0, s_aux>>>(val_feats, nullptr, 300, KPAD_VAL,
                                                  wetH, wetL, nval, nullptr, nullptr, valW); // 3 (aux)
    }
    cudaEventRecord(ev_join, s_aux);
    tsplit_k<<<ceildiv(256 * 256, 256), 256>>>(w2, 256, 256, w2tH, w2tL);    // 4
    entdot_all_k<<<ceildiv(ntot * 32, 256), 256>>>(ent_sr, ent_tg, a_w, n0, ntot);  // 5
    zero_int_k<<<ceildiv(ntot, 256), 256>>>(cntp, ntot);
    hist_tri_all_k<<<ceildiv(netot, 256), 256>>>(tri_sr, tri_tg, ne0, netot, n0);
    int nb = ceildiv(ntot, 1024);
    scan_blk_k<<<nb, 1024>>>(ntot);
    scan_mid_k<<<1, 32>>>(nb, ntot);
    scan_add_k<<<ceildiv(ntot, 256), 256>>>(ntot);
    scatter_tri_all_k<<<ceildiv(netot, 256), 256>>>(tri_sr, tri_tg, ne0, netot, n0);
    edge_ptr_all_k<<<ceildiv(Etot, 256), 256>>>(rows_sr, rows_tg, E0, Etot, n0, ntot);

    // ---- join: attr encoder needs valW ----
    cudaStreamWaitEvent(0, ev_join, 0);
    attr_agg_all_k<<<ntot, 64>>>(tri_sr, tri_tg, ne0, a_b, ent_sr, ent_tg, n0);

    // ---- stacked GCN layers ----
    dim3 ggrid(2, ceildiv(ntot, 128));
    gcn_agg_split_all_k<<<ntot, 64>>>(F1, cols_sr, cols_tg, E0, n0, xaH, xaL);
    mma_gemm_k<1, 1><<<ggrid, 256>>>(xaH, xaL, 256, 256, w1tH, w1tL, ntot, b1, F1, F2);
    gcn_agg_split_all_k<<<ntot, 64>>>(F2, cols_sr, cols_tg, E0, n0, xaH, xaL);
    mma_gemm_k<2, 1><<<ggrid, 256>>>(xaH, xaL, 256, 256, w2tH, w2tL, ntot, b2, F2, F1);

    // ---- output ----
    l2norm_all_k<<<ntot, 64>>>(F1, out_full);
    gather_all_k<<<2 * nseed, 64>>>(seed_sr, seed_tg, nseed, n0, out_full, out_seed);
}

// round 9
// speedup vs baseline: 2.7171x; 1.0062x over previous
#include <cuda_runtime.h>
#include <cuda_bf16.h>
#include <math.h>
#include <stdint.h>

#define DIM 256
#define NTOT 100000
#define ETRI 400000
#define NVALMAX 100000
#define NATTMAX 1001
#define KPAD_VAL 320
#define MT_S 40   // smem row stride in bf16 (80B): conflict-free for ldmatrix 8-row phases

// dynamic smem layout (bytes), per buffer: A 256xMT_S bf16, B 128xMT_S bf16 (hi+lo)
#define OFF_AH 0
#define OFF_AL 20480
#define OFF_BH 40960
#define OFF_BL 51200
#define BUFSZ  61440
#define SMEM_TOT (2 * BUFSZ)

// ---------------- scratch ----------------
__device__ float g_valW[NVALMAX * DIM];
__device__ float g_attW[NATTMAX * DIM];
__device__ float g_attdot[NATTMAX];
__device__ float g_entdot[NTOT];
__device__ int   g_cnt[NTOT];
__device__ int   g_ptr[NTOT + 1];
__device__ int   g_eptr[NTOT + 1];
__device__ int   g_fill[NTOT];
__device__ int   g_idx[ETRI];
__device__ int   g_bsum[128];
__device__ int   g_boff[128];
__device__ float g_F1[NTOT * DIM];
__device__ float g_F2[NTOT * DIM];
__device__ __nv_bfloat16 g_xa_h[NTOT * DIM];
__device__ __nv_bfloat16 g_xa_l[NTOT * DIM];
__device__ __nv_bfloat16 g_wet_h[DIM * KPAD_VAL];
__device__ __nv_bfloat16 g_wet_l[DIM * KPAD_VAL];
__device__ __nv_bfloat16 g_w1t_h[DIM * DIM];
__device__ __nv_bfloat16 g_w1t_l[DIM * DIM];
__device__ __nv_bfloat16 g_w2t_h[DIM * DIM];
__device__ __nv_bfloat16 g_w2t_l[DIM * DIM];

// ---------------- mma.sync + ldmatrix wrappers ----------------
__device__ __forceinline__ void mma16816(float* c, const uint32_t* a, const uint32_t* b) {
    asm volatile(
        "mma.sync.aligned.m16n8k16.row.col.f32.bf16.bf16.f32 "
        "{%0,%1,%2,%3}, {%4,%5,%6,%7}, {%8,%9}, {%0,%1,%2,%3};"
        : "+f"(c[0]), "+f"(c[1]), "+f"(c[2]), "+f"(c[3])
        : "r"(a[0]), "r"(a[1]), "r"(a[2]), "r"(a[3]), "r"(b[0]), "r"(b[1]));
}
#define LDMX4(r0, r1, r2, r3, addr) \
    asm volatile("ldmatrix.sync.aligned.m8n8.x4.shared.b16 {%0,%1,%2,%3}, [%4];" \
        : "=r"(r0), "=r"(r1), "=r"(r2), "=r"(r3) : "r"(addr))

// ---------------- HMMA split GEMM, 256x128 CTA tile, 64x64 warp tiles ----------------
// PRE=0: A fp32 converted in-register; PRE=1: A pre-split bf16 hi/lo.
// MODE 0: C = AB ; MODE 1: C = res + relu(AB+bias) ; MODE 2: C = res + AB + bias
template <int MODE, int PRE>
__global__ void __launch_bounds__(256, 1)
mma_gemm_k(const void* __restrict__ Ap, const void* __restrict__ Ap2, int K, int Kpad,
           const __nv_bfloat16* __restrict__ Bh, const __nv_bfloat16* __restrict__ Bl,
           int M,
           const float* __restrict__ bias, const float* __restrict__ res,
           float* __restrict__ C) {
    extern __shared__ char smem_dyn[];
    uint32_t smem_b = (uint32_t)__cvta_generic_to_shared(smem_dyn);
    int tid = threadIdx.x;
    int wid = tid >> 5, lane = tid & 31;
    int wm = wid & 3;      // 4 warp-rows of 64
    int wn = wid >> 2;     // 2 warp-cols of 64
    int row0 = blockIdx.y * 256;
    int col0 = blockIdx.x * 128;

    float acc[4][8][4];
    #pragma unroll
    for (int mt = 0; mt < 4; mt++)
        #pragma unroll
        for (int nt = 0; nt < 8; nt++)
            #pragma unroll
            for (int q = 0; q < 4; q++) acc[mt][nt][q] = 0.f;

    // global-load mapping: A one thread per row (256), B two threads per row (128)
    int a_r = tid;
    int b_r = tid >> 1;
    int seg = (tid & 1) * 16;
    int gr = row0 + a_r;
    bool arow_ok = gr < M;
    const float* Arow = (const float*)Ap + (size_t)(arow_ok ? gr : 0) * K;
    const __nv_bfloat16* AhRow = (const __nv_bfloat16*)Ap + (size_t)(arow_ok ? gr : 0) * Kpad;
    const __nv_bfloat16* AlRow = (const __nv_bfloat16*)Ap2 + (size_t)(arow_ok ? gr : 0) * Kpad;
    const __nv_bfloat16* BhRow = Bh + (size_t)(col0 + b_r) * Kpad;
    const __nv_bfloat16* BlRow = Bl + (size_t)(col0 + b_r) * Kpad;

    float aF[32];
    uint4 ah[4], al[4];
    uint4 bh[2], bl[2];

    auto loadChunk = [&](int k0) {
        if (PRE) {
            #pragma unroll
            for (int j = 0; j < 4; j++) {
                ah[j] = *(const uint4*)(AhRow + k0 + j * 8);
                al[j] = *(const uint4*)(AlRow + k0 + j * 8);
            }
        } else {
            #pragma unroll
            for (int j = 0; j < 8; j++) {
                int gk = k0 + j * 4;
                float4 v = make_float4(0.f, 0.f, 0.f, 0.f);
                if (arow_ok && gk + 3 < K) v = *(const float4*)(Arow + gk);
                else if (arow_ok) {
                    float tmp[4] = {0.f, 0.f, 0.f, 0.f};
                    #pragma unroll
                    for (int u = 0; u < 4; u++) if (gk + u < K) tmp[u] = Arow[gk + u];
                    v = make_float4(tmp[0], tmp[1], tmp[2], tmp[3]);
                }
                aF[j * 4 + 0] = v.x; aF[j * 4 + 1] = v.y;
                aF[j * 4 + 2] = v.z; aF[j * 4 + 3] = v.w;
            }
        }
        bh[0] = *(const uint4*)(BhRow + k0 + seg);
        bh[1] = *(const uint4*)(BhRow + k0 + seg + 8);
        bl[0] = *(const uint4*)(BlRow + k0 + seg);
        bl[1] = *(const uint4*)(BlRow + k0 + seg + 8);
    };
    auto storeChunk = [&](int buf) {
        char* base = smem_dyn + buf * BUFSZ;
        if (PRE) {
            #pragma unroll
            for (int j = 0; j < 4; j++) {
                *(uint4*)(base + OFF_AH + (a_r * MT_S + j * 8) * 2) = ah[j];
                *(uint4*)(base + OFF_AL + (a_r * MT_S + j * 8) * 2) = al[j];
            }
        } else {
            __nv_bfloat16 h[32], l[32];
            #pragma unroll
            for (int j = 0; j < 32; j++) {
                h[j] = __float2bfloat16(aF[j]);
                l[j] = __float2bfloat16(aF[j] - __bfloat162float(h[j]));
            }
            #pragma unroll
            for (int j = 0; j < 4; j++) {
                *(uint4*)(base + OFF_AH + (a_r * MT_S + j * 8) * 2) = ((const uint4*)h)[j];
                *(uint4*)(base + OFF_AL + (a_r * MT_S + j * 8) * 2) = ((const uint4*)l)[j];
            }
        }
        *(uint4*)(base + OFF_BH + (b_r * MT_S + seg) * 2)     = bh[0];
        *(uint4*)(base + OFF_BH + (b_r * MT_S + seg + 8) * 2) = bh[1];
        *(uint4*)(base + OFF_BL + (b_r * MT_S + seg) * 2)     = bl[0];
        *(uint4*)(base + OFF_BL + (b_r * MT_S + seg + 8) * 2) = bl[1];
    };

    // ldmatrix lane-address components
    int a_row = wm * 64 + (lane & 15);                         // + mt*16
    int a_colsel = (lane >> 4) * 8;
    int b_row = wn * 64 + ((lane >> 4) ? 8 : 0) + (lane & 7);  // + p*16
    int b_colsel = ((lane >> 3) & 1) * 8;

    int nch = Kpad / 32;
    loadChunk(0);
    storeChunk(0);
    __syncthreads();
    if (nch > 1) loadChunk(32);

    for (int ci = 0; ci < nch; ci++) {
        uint32_t bufb = smem_b + (ci & 1) * BUFSZ;
        #pragma unroll
        for (int ks = 0; ks < 2; ks++) {
            uint32_t aH[4][4], aL[4][4];
            #pragma unroll
            for (int mt = 0; mt < 4; mt++) {
                uint32_t off = (uint32_t)(((a_row + mt * 16) * MT_S + ks * 16 + a_colsel) * 2);
                LDMX4(aH[mt][0], aH[mt][1], aH[mt][2], aH[mt][3], bufb + OFF_AH + off);
                LDMX4(aL[mt][0], aL[mt][1], aL[mt][2], aL[mt][3], bufb + OFF_AL + off);
            }
            #pragma unroll
            for (int p = 0; p < 4; p++) {
                uint32_t off = (uint32_t)(((b_row + p * 16) * MT_S + ks * 16 + b_colsel) * 2);
                uint32_t h0, h1, h2, h3, l0, l1, l2, l3;
                LDMX4(h0, h1, h2, h3, bufb + OFF_BH + off);
                LDMX4(l0, l1, l2, l3, bufb + OFF_BL + off);
                uint32_t bH0[2] = {h0, h1}, bH1[2] = {h2, h3};
                uint32_t bL0[2] = {l0, l1}, bL1[2] = {l2, l3};
                #pragma unroll
                for (int mt = 0; mt < 4; mt++) {
                    mma16816(acc[mt][2 * p],     aH[mt], bH0);
                    mma16816(acc[mt][2 * p],     aL[mt], bH0);
                    mma16816(acc[mt][2 * p],     aH[mt], bL0);
                    mma16816(acc[mt][2 * p + 1], aH[mt], bH1);
                    mma16816(acc[mt][2 * p + 1], aL[mt], bH1);
                    mma16816(acc[mt][2 * p + 1], aH[mt], bL1);
                }
            }
        }
        if (ci + 1 < nch) {
            storeChunk((ci + 1) & 1);
            __syncthreads();
            if (ci + 2 < nch) loadChunk((ci + 2) * 32);
        }
    }

    #pragma unroll
    for (int mt = 0; mt < 4; mt++) {
        #pragma unroll
        for (int half = 0; half < 2; half++) {
            int r = row0 + wm * 64 + mt * 16 + (lane >> 2) + half * 8;
            if (r >= M) continue;
            #pragma unroll
            for (int nt = 0; nt < 8; nt++) {
                int c = col0 + wn * 64 + nt * 8 + (lane & 3) * 2;
                float2 v;
                v.x = acc[mt][nt][half * 2 + 0];
                v.y = acc[mt][nt][half * 2 + 1];
                if (MODE >= 1) {
                    const float2 bb = *(const float2*)&bias[c];
                    v.x += bb.x; v.y += bb.y;
                    if (MODE == 1) { v.x = fmaxf(v.x, 0.f); v.y = fmaxf(v.y, 0.f); }
                    const float2 rr = *(const float2*)&res[(size_t)r * 256 + c];
                    v.x += rr.x; v.y += rr.y;
                }
                *(float2*)&C[(size_t)r * 256 + c] = v;
            }
        }
    }
}

// ---------------- weight transpose + hi/lo split ----------------
__global__ void tsplit_k(const float* __restrict__ src, int K, int Kpad,
                         __nv_bfloat16* __restrict__ hi, __nv_bfloat16* __restrict__ lo) {
    int idx = blockIdx.x * blockDim.x + threadIdx.x;
    if (idx >= 256 * Kpad) return;
    int k = idx % Kpad;
    int n = idx / Kpad;
    float v = (k < K) ? src[(size_t)k * 256 + n] : 0.f;
    __nv_bfloat16 h = __float2bfloat16(v);
    hi[idx] = h;
    lo[idx] = __float2bfloat16(v - __bfloat162float(h));
}

// ---------------- stacked SIMT pipeline kernels ----------------
__global__ void zero_int_k(int* p, int n) {
    int i = blockIdx.x * blockDim.x + threadIdx.x;
    if (i < n) p[i] = 0;
}
__global__ void att_k(const float* __restrict__ att_feats,
                      const float* __restrict__ W_enc,
                      const float* __restrict__ a_w, int natt) {
    int r = blockIdx.x;
    int d = threadIdx.x;
    __shared__ float sh[DIM];
    __shared__ float sred[8];
    sh[d] = att_feats[(size_t)r * DIM + d];
    __syncthreads();
    float acc = 0.f;
    #pragma unroll 8
    for (int k = 0; k < DIM; k++) acc += sh[k] * W_enc[(size_t)k * DIM + d];
    g_attW[(size_t)r * DIM + d] = acc;
    float v = sh[d] * a_w[DIM + d];
    for (int o = 16; o; o >>= 1) v += __shfl_xor_sync(0xffffffffu, v, o);
    if ((d & 31) == 0) sred[d >> 5] = v;
    __syncthreads();
    if (d == 0) {
        float s = 0.f;
        #pragma unroll
        for (int i = 0; i < 8; i++) s += sred[i];
        g_attdot[r] = s;
    }
}
__global__ void entdot_all_k(const float* __restrict__ ent0, const float* __restrict__ ent1,
                             const float* __restrict__ a_w, int n0, int ntot) {
    int node = (blockIdx.x * blockDim.x + threadIdx.x) >> 5;
    int lane = threadIdx.x & 31;
    if (node >= ntot) return;
    const float* row = (node < n0) ? ent0 + (size_t)node * DIM
                                   : ent1 + (size_t)(node - n0) * DIM;
    float s = 0.f;
    #pragma unroll
    for (int d = lane; d < DIM; d += 32) s += row[d] * a_w[d];
    for (int o = 16; o; o >>= 1) s += __shfl_xor_sync(0xffffffffu, s, o);
    if (lane == 0) g_entdot[node] = s;
}
__global__ void hist_tri_all_k(const int* __restrict__ t0, const int* __restrict__ t1,
                               int ne0, int netot, int n0) {
    int e = blockIdx.x * blockDim.x + threadIdx.x;
    if (e >= netot) return;
    int head = (e < ne0) ? t0[3 * e] : n0 + t1[3 * (e - ne0)];
    atomicAdd(&g_cnt[head], 1);
}
__global__ void scan_blk_k(int n) {
    __shared__ int wsum[32];
    int b = blockIdx.x;
    int i = b * 1024 + threadIdx.x;
    int lane = threadIdx.x & 31, wid = threadIdx.x >> 5;
    int v = (i < n) ? g_cnt[i] : 0;
    int x = v;
    #pragma unroll
    for (int o = 1; o < 32; o <<= 1) {
        int y = __shfl_up_sync(0xffffffffu, x, o);
        if (lane >= o) x += y;
    }
    if (lane == 31) wsum[wid] = x;
    __syncthreads();
    if (wid == 0) {
        int w = wsum[lane];
        int xs = w;
        #pragma unroll
        for (int o = 1; o < 32; o <<= 1) {
            int y = __shfl_up_sync(0xffffffffu, xs, o);
            if (lane >= o) xs += y;
        }
        wsum[lane] = xs - w;
    }
    __syncthreads();
    int excl = wsum[wid] + x - v;
    if (i < n) g_ptr[i] = excl;
    if (threadIdx.x == 1023) g_bsum[b] = excl + v;
}
__global__ void scan_mid_k(int nb, int n) {
    int lane = threadIdx.x;
    int carry = 0;
    for (int base = 0; base < nb; base += 32) {
        int i = base + lane;
        int v = (i < nb) ? g_bsum[i] : 0;
        int x = v;
        #pragma unroll
        for (int o = 1; o < 32; o <<= 1) {
            int y = __shfl_up_sync(0xffffffffu, x, o);
            if (lane >= o) x += y;
        }
        if (i < nb) g_boff[i] = carry + x - v;
        carry += __shfl_sync(0xffffffffu, x, 31);
    }
    if (lane == 0) g_ptr[n] = carry;
}
__global__ void scan_add_k(int n) {
    int i = blockIdx.x * blockDim.x + threadIdx.x;
    if (i < n) {
        int p = g_ptr[i] + g_boff[i >> 10];
        g_ptr[i] = p;
        g_fill[i] = p;
    }
}
__global__ void scatter_tri_all_k(const int* __restrict__ t0, const int* __restrict__ t1,
                                  int ne0, int netot, int n0) {
    int e = blockIdx.x * blockDim.x + threadIdx.x;
    if (e >= netot) return;
    int head = (e < ne0) ? t0[3 * e] : n0 + t1[3 * (e - ne0)];
    int pos = atomicAdd(&g_fill[head], 1);
    g_idx[pos] = e;
}
__global__ void edge_ptr_all_k(const int* __restrict__ r0, const int* __restrict__ r1,
                               int E0, int Etot, int n0, int ntot) {
    int e = blockIdx.x * blockDim.x + threadIdx.x;
    if (e >= Etot) return;
    int r = (e < E0) ? r0[e] : n0 + r1[e - E0];
    if (e == 0) {
        for (int v = 0; v <= r; v++) g_eptr[v] = 0;
    } else {
        int rp = (e - 1 < E0) ? r0[e - 1] : n0 + r1[e - 1 - E0];
        for (int v = rp + 1; v <= r; v++) g_eptr[v] = e;
    }
    if (e == Etot - 1) {
        for (int v = r + 1; v <= ntot; v++) g_eptr[v] = Etot;
    }
}
__global__ void attr_agg_all_k(const int* __restrict__ t0, const int* __restrict__ t1,
                               int ne0,
                               const float* __restrict__ ab_ptr,
                               const float* __restrict__ ent0, const float* __restrict__ ent1,
                               int n0) {
    int v = blockIdx.x;
    int t = threadIdx.x;
    int s = g_ptr[v], e = g_ptr[v + 1];
    int side = v >= n0;
    const int* tri = side ? t1 : t0;
    int tbase = side ? ne0 : 0;
    __shared__ float sred[2];
    __shared__ float s_inv;
    __shared__ float sh_p[64];
    __shared__ int sh_att[64];
    __shared__ int sh_val[64];
    float ab = ab_ptr[0];
    float ed = g_entdot[v];
    float part = 0.f;
    for (int i = s + t; i < e; i += 64) {
        int tt = g_idx[i] - tbase;
        float sc = ed + g_attdot[tri[3 * tt + 2]] + ab;
        sc = sc > 0.f ? sc : 0.2f * sc;
        part += expf(sc);
    }
    for (int o = 16; o; o >>= 1) part += __shfl_xor_sync(0xffffffffu, part, o);
    if ((t & 31) == 0) sred[t >> 5] = part;
    __syncthreads();
    if (t == 0) {
        float rs = sred[0] + sred[1];
        s_inv = (rs > 0.f) ? 1.f / rs : 0.f;
    }
    __syncthreads();
    float inv_rs = s_inv;
    float4 acc = make_float4(0.f, 0.f, 0.f, 0.f);
    for (int base = s; base < e; base += 64) {
        int cnt = min(64, e - base);
        if (t < cnt) {
            int tt = g_idx[base + t] - tbase;
            int att = tri[3 * tt + 2];
            int val = tri[3 * tt + 1];
            sh_att[t] = att;
            sh_val[t] = val;
            float sc = ed + g_attdot[att] + ab;
            sc = sc > 0.f ? sc : 0.2f * sc;
            sh_p[t] = expf(sc) * inv_rs;
        }
        __syncthreads();
        for (int j = 0; j < cnt; j++) {
            float p = sh_p[j];
            const float4 aw = *(const float4*)&g_attW[(size_t)sh_att[j] * DIM + t * 4];
            const float4 vw = *(const float4*)&g_valW[(size_t)sh_val[j] * DIM + t * 4];
            acc.x += p * (aw.x + vw.x);
            acc.y += p * (aw.y + vw.y);
            acc.z += p * (aw.z + vw.z);
            acc.w += p * (aw.w + vw.w);
        }
        __syncthreads();
    }
    const float* ef_row = side ? ent1 + (size_t)(v - n0) * DIM : ent0 + (size_t)v * DIM;
    const float4 ef = *(const float4*)&ef_row[t * 4];
    float4 x = make_float4(acc.x + ef.x, acc.y + ef.y, acc.z + ef.z, acc.w + ef.w);
    x.x = x.x > 0.f ? x.x : expm1f(x.x);
    x.y = x.y > 0.f ? x.y : expm1f(x.y);
    x.z = x.z > 0.f ? x.z : expm1f(x.z);
    x.w = x.w > 0.f ? x.w : expm1f(x.w);
    *(float4*)&g_F1[(size_t)v * DIM + t * 4] = x;
}
__global__ void gcn_agg_split_all_k(const float* __restrict__ feats,
                                    const int* __restrict__ c0, const int* __restrict__ c1,
                                    int E0, int n0,
                                    __nv_bfloat16* __restrict__ hi,
                                    __nv_bfloat16* __restrict__ lo) {
    int v = blockIdx.x;
    int t = threadIdx.x;
    int s = g_eptr[v], e = g_eptr[v + 1];
    __shared__ int sh_c[64];
    float4 acc = make_float4(0.f, 0.f, 0.f, 0.f);
    for (int base = s; base < e; base += 64) {
        int cnt = min(64, e - base);
        if (t < cnt) {
            int i = base + t;
            sh_c[t] = (i < E0) ? c0[i] : n0 + c1[i - E0];
        }
        __syncthreads();
        for (int j = 0; j < cnt; j++) {
            const float4 f = *(const float4*)&feats[(size_t)sh_c[j] * DIM + t * 4];
            acc.x += f.x; acc.y += f.y; acc.z += f.z; acc.w += f.w;
        }
        __syncthreads();
    }
    float inv = (e > s) ? 1.f / (float)(e - s) : 0.f;
    float vals[4] = {acc.x * inv, acc.y * inv, acc.z * inv, acc.w * inv};
    __nv_bfloat16 hv[4], lv[4];
    #pragma unroll
    for (int j = 0; j < 4; j++) {
        hv[j] = __float2bfloat16(vals[j]);
        lv[j] = __float2bfloat16(vals[j] - __bfloat162float(hv[j]));
    }
    *(uint2*)&hi[(size_t)v * DIM + t * 4] = *(uint2*)hv;
    *(uint2*)&lo[(size_t)v * DIM + t * 4] = *(uint2*)lv;
}
__global__ void l2norm_all_k(const float* __restrict__ in, float* __restrict__ out) {
    int v = blockIdx.x;
    int t = threadIdx.x;
    __shared__ float sred[2];
    __shared__ float s_inv;
    const float4 x = *(const float4*)&in[(size_t)v * DIM + t * 4];
    float sq = x.x * x.x + x.y * x.y + x.z * x.z + x.w * x.w;
    for (int o = 16; o; o >>= 1) sq += __shfl_xor_sync(0xffffffffu, sq, o);
    if ((t & 31) == 0) sred[t >> 5] = sq;
    __syncthreads();
    if (t == 0) {
        float nrm = sqrtf(sred[0] + sred[1]);
        s_inv = 1.f / fmaxf(nrm, 1e-12f);
    }
    __syncthreads();
    float inv = s_inv;
    float4 y = make_float4(x.x * inv, x.y * inv, x.z * inv, x.w * inv);
    *(float4*)&out[(size_t)v * DIM + t * 4] = y;
}
__global__ void gather_all_k(const int* __restrict__ s0, const int* __restrict__ s1,
                             int nseed, int n0,
                             const float* __restrict__ src, float* __restrict__ dst) {
    int i = blockIdx.x;
    int t = threadIdx.x;
    int node = (i < nseed) ? s0[i] : n0 + s1[i - nseed];
    *(float4*)&dst[(size_t)i * DIM + t * 4] =
        *(const float4*)&src[(size_t)node * DIM + t * 4];
}

// ---------------- host orchestration ----------------
static inline int ceildiv(int a, int b) { return (a + b - 1) / b; }

extern "C" void kernel_launch(void* const* d_in, const int* in_sizes, int n_in,
                              void* d_out, int out_size) {
    const int* seed_sr = (const int*)d_in[0];
    const int* seed_tg = (const int*)d_in[1];
    const int* tri_sr  = (const int*)d_in[2];
    const int* tri_tg  = (const int*)d_in[3];
    const int* rows_sr = (const int*)d_in[4];
    const int* cols_sr = (const int*)d_in[5];
    const int* rows_tg = (const int*)d_in[6];
    const int* cols_tg = (const int*)d_in[7];
    const float* att_feats = (const float*)d_in[8];
    const float* val_feats = (const float*)d_in[9];
    const float* ent_sr = (const float*)d_in[10];
    const float* ent_tg = (const float*)d_in[11];
    const float* a_w   = (const float*)d_in[12];
    const float* a_b   = (const float*)d_in[13];
    const float* W_enc = (const float*)d_in[14];
    const float* w1    = (const float*)d_in[15];
    const float* b1    = (const float*)d_in[16];
    const float* w2    = (const float*)d_in[17];
    const float* b2    = (const float*)d_in[18];
    (void)n_in; (void)out_size;

    const int nseed  = in_sizes[0];
    const int ne0    = in_sizes[2] / 3;
    const int ne1    = in_sizes[3] / 3;
    const int E0     = in_sizes[4];
    const int E1     = in_sizes[6];
    const int natt   = in_sizes[8] / DIM;
    const int nval   = in_sizes[9] / 300;
    const int n0     = in_sizes[10] / DIM;
    const int n1     = in_sizes[11] / DIM;
    const int ntot   = n0 + n1;
    const int netot  = ne0 + ne1;
    const int Etot   = E0 + E1;

    static cudaStream_t s_aux = nullptr;
    static cudaEvent_t ev_fork = nullptr, ev_join = nullptr;
    if (!s_aux) {
        cudaStreamCreateWithFlags(&s_aux, cudaStreamNonBlocking);
        cudaEventCreateWithFlags(&ev_fork, cudaEventDisableTiming);
        cudaEventCreateWithFlags(&ev_join, cudaEventDisableTiming);
        cudaFuncSetAttribute(mma_gemm_k<0, 0>, cudaFuncAttributeMaxDynamicSharedMemorySize, SMEM_TOT);
        cudaFuncSetAttribute(mma_gemm_k<1, 1>, cudaFuncAttributeMaxDynamicSharedMemorySize, SMEM_TOT);
        cudaFuncSetAttribute(mma_gemm_k<2, 1>, cudaFuncAttributeMaxDynamicSharedMemorySize, SMEM_TOT);
    }

    float* valW;  cudaGetSymbolAddress((void**)&valW,  g_valW);
    float* F1;    cudaGetSymbolAddress((void**)&F1,    g_F1);
    float* F2;    cudaGetSymbolAddress((void**)&F2,    g_F2);
    int*   cntp;  cudaGetSymbolAddress((void**)&cntp,  g_cnt);
    __nv_bfloat16 *xaH, *xaL, *wetH, *wetL, *w1tH, *w1tL, *w2tH, *w2tL;
    cudaGetSymbolAddress((void**)&xaH, g_xa_h);
    cudaGetSymbolAddress((void**)&xaL, g_xa_l);
    cudaGetSymbolAddress((void**)&wetH, g_wet_h);
    cudaGetSymbolAddress((void**)&wetL, g_wet_l);
    cudaGetSymbolAddress((void**)&w1tH, g_w1t_h);
    cudaGetSymbolAddress((void**)&w1tL, g_w1t_l);
    cudaGetSymbolAddress((void**)&w2tH, g_w2t_h);
    cudaGetSymbolAddress((void**)&w2tL, g_w2t_l);

    float* out = (float*)d_out;
    float* out_seed = out;
    float* out_full = out + (size_t)2 * nseed * DIM;

    // ---- precompute; valW GEMM forked to aux stream ----
    tsplit_k<<<ceildiv(256 * KPAD_VAL, 256), 256>>>(
        W_enc + (size_t)DIM * DIM, 300, KPAD_VAL, wetH, wetL);
    cudaEventRecord(ev_fork, 0);
    cudaStreamWaitEvent(s_aux, ev_fork, 0);
    att_k<<<natt, DIM>>>(att_feats, W_enc, a_w, natt);
    tsplit_k<<<ceildiv(256 * 256, 256), 256>>>(w1, 256, 256, w1tH, w1tL);
    {
        dim3 grid(2, ceildiv(nval, 256));
        mma_gemm_k<0, 0><<<grid, 256, SMEM_TOT, s_aux>>>(
            val_feats, nullptr, 300, KPAD_VAL, wetH, wetL, nval, nullptr, nullptr, valW);
    }
    cudaEventRecord(ev_join, s_aux);
    tsplit_k<<<ceildiv(256 * 256, 256), 256>>>(w2, 256, 256, w2tH, w2tL);
    entdot_all_k<<<ceildiv(ntot * 32, 256), 256>>>(ent_sr, ent_tg, a_w, n0, ntot);
    zero_int_k<<<ceildiv(ntot, 256), 256>>>(cntp, ntot);
    hist_tri_all_k<<<ceildiv(netot, 256), 256>>>(tri_sr, tri_tg, ne0, netot, n0);
    int nb = ceildiv(ntot, 1024);
    scan_blk_k<<<nb, 1024>>>(ntot);
    scan_mid_k<<<1, 32>>>(nb, ntot);
    scan_add_k<<<ceildiv(ntot, 256), 256>>>(ntot);
    scatter_tri_all_k<<<ceildiv(netot, 256), 256>>>(tri_sr, tri_tg, ne0, netot, n0);
    edge_ptr_all_k<<<ceildiv(Etot, 256), 256>>>(rows_sr, rows_tg, E0, Etot, n0, ntot);

    // ---- join: attr encoder needs valW ----
    cudaStreamWaitEvent(0, ev_join, 0);
    attr_agg_all_k<<<ntot, 64>>>(tri_sr, tri_tg, ne0, a_b, ent_sr, ent_tg, n0);

    // ---- stacked GCN layers ----
    dim3 ggrid(2, ceildiv(ntot, 256));
    gcn_agg_split_all_k<<<ntot, 64>>>(F1, cols_sr, cols_tg, E0, n0, xaH, xaL);
    mma_gemm_k<1, 1><<<ggrid, 256, SMEM_TOT>>>(xaH, xaL, 256, 256, w1tH, w1tL, ntot, b1, F1, F2);
    gcn_agg_split_all_k<<<ntot, 64>>>(F2, cols_sr, cols_tg, E0, n0, xaH, xaL);
    mma_gemm_k<2, 1><<<ggrid, 256, SMEM_TOT>>>(xaH, xaL, 256, 256, w2tH, w2tL, ntot, b2, F2, F1);

    // ---- output ----
    l2norm_all_k<<<ntot, 64>>>(F1, out_full);
    gather_all_k<<<2 * nseed, 64>>>(seed_sr, seed_tg, nseed, n0, out_full, out_seed);
}